// round 1
// baseline (speedup 1.0000x reference)
#include <cuda_runtime.h>
#include <cstdint>
#include <cstdio>

#define B_  4
#define S_  2048
#define D_  1024
#define H_  16
#define DK_ 64
#define M_  (B_*S_)      // 8192 rows for the big GEMMs
#define N_  1024         // H*DK  and  D

// Scratch (static device allocations are allowed; runtime allocation is not)
__device__ float g_Q[(size_t)B_*H_*S_*DK_];   // [b,h,s,k]
__device__ float g_K[(size_t)B_*H_*S_*DK_];
__device__ float g_V[(size_t)B_*H_*S_*DK_];
__device__ float g_Z[(size_t)B_*S_*H_*DK_];   // [b,s,h*64]  (concat layout)

// ---------------------------------------------------------------------------
// GEMM: C[M,N] = X[M,K] * W + bias, 128x128x16 tiles, 8x8 per thread.
// MODE 0: W is [H,D,DK] (per-head proj weight), output scattered to [b,h,s,k]
// MODE 1: W is row-major [K,N], output row-major [M,N]
// ---------------------------------------------------------------------------
template<int MODE>
__global__ __launch_bounds__(256)
void gemm_kernel(const float* __restrict__ X, const float* __restrict__ W,
                 const float* __restrict__ bias, float* __restrict__ out)
{
    constexpr int BM = 128, BN = 128, BK = 16;
    __shared__ float As[BK][BM];   // A stored transposed: As[k][m]
    __shared__ float Bs[BK][BN];

    const int tid  = threadIdx.x;
    const int tx   = tid & 15;
    const int ty   = tid >> 4;
    const int row0 = blockIdx.y * BM;
    const int col0 = blockIdx.x * BN;
    const int K    = 1024;

    float acc[8][8];
#pragma unroll
    for (int i = 0; i < 8; ++i)
#pragma unroll
        for (int j = 0; j < 8; ++j) acc[i][j] = 0.f;

    const int ar = tid >> 2;            // 0..63  (A row within tile, +64 second half)
    const int ak = (tid & 3) * 4;       // 0..12  (A k-offset, float4)
    const int bk = tid >> 5;            // 0..7   (B k-row, +8 second half)
    const int bn = (tid & 31) * 4;      // 0..124 (B col, float4)

    for (int k0 = 0; k0 < K; k0 += BK) {
#pragma unroll
        for (int h2 = 0; h2 < 2; ++h2) {
            // A tile load (coalesced), store transposed
            int r = ar + h2 * 64;
            float4 a = *(const float4*)(X + (size_t)(row0 + r) * K + k0 + ak);
            As[ak + 0][r] = a.x; As[ak + 1][r] = a.y;
            As[ak + 2][r] = a.z; As[ak + 3][r] = a.w;
            // B tile load
            int kk = bk + h2 * 8;
            const float* wp;
            if (MODE == 0) {
                int c = col0 + bn;                       // global out column = h*64+k
                wp = W + (size_t)(c >> 6) * (D_ * DK_)   // head block
                       + (size_t)(k0 + kk) * DK_ + (c & 63);
            } else {
                wp = W + (size_t)(k0 + kk) * N_ + col0 + bn;
            }
            *(float4*)(&Bs[kk][bn]) = *(const float4*)wp;
        }
        __syncthreads();

#pragma unroll
        for (int kk = 0; kk < BK; ++kk) {
            float4 a0 = *(const float4*)(&As[kk][ty * 4]);
            float4 a1 = *(const float4*)(&As[kk][64 + ty * 4]);
            float4 b0 = *(const float4*)(&Bs[kk][tx * 4]);
            float4 b1 = *(const float4*)(&Bs[kk][64 + tx * 4]);
            float av[8] = {a0.x, a0.y, a0.z, a0.w, a1.x, a1.y, a1.z, a1.w};
            float bv[8] = {b0.x, b0.y, b0.z, b0.w, b1.x, b1.y, b1.z, b1.w};
#pragma unroll
            for (int i = 0; i < 8; ++i)
#pragma unroll
                for (int j = 0; j < 8; ++j)
                    acc[i][j] = fmaf(av[i], bv[j], acc[i][j]);
        }
        __syncthreads();
    }

    // Epilogue: bias + store
#pragma unroll
    for (int ih = 0; ih < 2; ++ih) {
#pragma unroll
        for (int i = 0; i < 4; ++i) {
            int r = row0 + ih * 64 + ty * 4 + i;
#pragma unroll
            for (int jh = 0; jh < 2; ++jh) {
                int c = col0 + jh * 64 + tx * 4;
                float4 v;
                v.x = acc[ih * 4 + i][jh * 4 + 0] + bias[c + 0];
                v.y = acc[ih * 4 + i][jh * 4 + 1] + bias[c + 1];
                v.z = acc[ih * 4 + i][jh * 4 + 2] + bias[c + 2];
                v.w = acc[ih * 4 + i][jh * 4 + 3] + bias[c + 3];
                if (MODE == 0) {
                    int b  = r >> 11;           // r / S
                    int s  = r & 2047;          // r % S
                    int hh = c >> 6;
                    int kc = c & 63;            // float4 stays inside one head
                    *(float4*)(out + (((size_t)(b * H_ + hh) * S_ + s) * DK_) + kc) = v;
                } else {
                    *(float4*)(out + (size_t)r * N_ + c) = v;
                }
            }
        }
    }
}

// ---------------------------------------------------------------------------
// Flash attention per (b,h). 64-row Q tiles, 64-col KV tiles, fp32,
// UNSCALED scores (faithful to reference), online softmax.
// Shared: Q^T, K^T (reused as P), V  = 3 * 16KB = 48KB (static limit exactly).
// ---------------------------------------------------------------------------
__global__ __launch_bounds__(256)
void attn_kernel(const float* __restrict__ Q, const float* __restrict__ K,
                 const float* __restrict__ V, float* __restrict__ Z)
{
    __shared__ float sQt[64][64];   // [d][row]
    __shared__ float sKP[64][64];   // K^T [d][col], then P [row][col]
    __shared__ float sV [64][64];   // [col][v]

    const int tid = threadIdx.x;
    const int tx  = tid & 15;
    const int ty  = tid >> 4;
    const int bh  = blockIdx.y;           // b*H + h
    const int b   = bh >> 4;
    const int h   = bh & 15;
    const int r0  = blockIdx.x * 64;

    const float* Qp = Q + ((size_t)bh * S_ + r0) * DK_;
    const float* Kp = K + (size_t)bh * S_ * DK_;
    const float* Vp = V + (size_t)bh * S_ * DK_;

    // Load Q tile transposed (conflict-free transposed stores)
    {
        int row = tid & 63;
        int d4  = tid >> 6;                  // 0..3
#pragma unroll
        for (int it = 0; it < 4; ++it) {
            int dd = (d4 + 4 * it) * 4;
            float4 q = *(const float4*)(Qp + (size_t)row * DK_ + dd);
            sQt[dd + 0][row] = q.x; sQt[dd + 1][row] = q.y;
            sQt[dd + 2][row] = q.z; sQt[dd + 3][row] = q.w;
        }
    }

    float m[4], l[4], acc[4][4];
#pragma unroll
    for (int i = 0; i < 4; ++i) {
        m[i] = -1e30f; l[i] = 0.f;
#pragma unroll
        for (int j = 0; j < 4; ++j) acc[i][j] = 0.f;
    }

    const int rowA = tid & 63, d4A = tid >> 6;   // K-transpose mapping
    const int d4B  = tid & 15, rowB = tid >> 4;  // V straight mapping

    for (int t = 0; t < S_ / 64; ++t) {
        __syncthreads();   // protects sQt (t=0) and sKP/sV reuse (t>0)
        {
            const float* Kt = Kp + (size_t)t * 64 * DK_;
            const float* Vt = Vp + (size_t)t * 64 * DK_;
#pragma unroll
            for (int it = 0; it < 4; ++it) {
                int dd = (d4A + 4 * it) * 4;
                float4 kv = *(const float4*)(Kt + (size_t)rowA * DK_ + dd);
                sKP[dd + 0][rowA] = kv.x; sKP[dd + 1][rowA] = kv.y;
                sKP[dd + 2][rowA] = kv.z; sKP[dd + 3][rowA] = kv.w;
                int rv = rowB + 16 * it;
                *(float4*)(&sV[rv][d4B * 4]) =
                    *(const float4*)(Vt + (size_t)rv * DK_ + d4B * 4);
            }
        }
        __syncthreads();

        // S tile: s[i][j] = sum_d Q[r0+4ty+i][d] * K[t*64+4tx+j][d]
        float s[4][4];
#pragma unroll
        for (int i = 0; i < 4; ++i)
#pragma unroll
            for (int j = 0; j < 4; ++j) s[i][j] = 0.f;

#pragma unroll
        for (int d = 0; d < 64; ++d) {
            float4 qv = *(const float4*)(&sQt[d][ty * 4]);
            float4 kv = *(const float4*)(&sKP[d][tx * 4]);
            float qa[4] = {qv.x, qv.y, qv.z, qv.w};
            float ka[4] = {kv.x, kv.y, kv.z, kv.w};
#pragma unroll
            for (int i = 0; i < 4; ++i)
#pragma unroll
                for (int j = 0; j < 4; ++j)
                    s[i][j] = fmaf(qa[i], ka[j], s[i][j]);
        }

        // Online softmax update (row stats across the 16 tx lanes)
#pragma unroll
        for (int i = 0; i < 4; ++i) {
            float tm = fmaxf(fmaxf(s[i][0], s[i][1]), fmaxf(s[i][2], s[i][3]));
#pragma unroll
            for (int o = 8; o >= 1; o >>= 1)
                tm = fmaxf(tm, __shfl_xor_sync(0xffffffffu, tm, o));
            float mn    = fmaxf(m[i], tm);
            float scale = __expf(m[i] - mn);
            m[i] = mn;
            float rs = 0.f;
#pragma unroll
            for (int j = 0; j < 4; ++j) {
                s[i][j] = __expf(s[i][j] - mn);
                rs += s[i][j];
            }
#pragma unroll
            for (int o = 8; o >= 1; o >>= 1)
                rs += __shfl_xor_sync(0xffffffffu, rs, o);
            l[i] = l[i] * scale + rs;
#pragma unroll
            for (int j = 0; j < 4; ++j) acc[i][j] *= scale;
        }

        __syncthreads();   // all threads done reading sKP as K^T
        // Write P into sKP as [row][col]
#pragma unroll
        for (int i = 0; i < 4; ++i)
            *(float4*)(&sKP[ty * 4 + i][tx * 4]) =
                make_float4(s[i][0], s[i][1], s[i][2], s[i][3]);
        __syncthreads();

        // acc += P @ V
#pragma unroll
        for (int j = 0; j < 64; ++j) {
            float4 vv = *(const float4*)(&sV[j][tx * 4]);
            float p0 = sKP[ty * 4 + 0][j];
            float p1 = sKP[ty * 4 + 1][j];
            float p2 = sKP[ty * 4 + 2][j];
            float p3 = sKP[ty * 4 + 3][j];
            acc[0][0] = fmaf(p0, vv.x, acc[0][0]); acc[0][1] = fmaf(p0, vv.y, acc[0][1]);
            acc[0][2] = fmaf(p0, vv.z, acc[0][2]); acc[0][3] = fmaf(p0, vv.w, acc[0][3]);
            acc[1][0] = fmaf(p1, vv.x, acc[1][0]); acc[1][1] = fmaf(p1, vv.y, acc[1][1]);
            acc[1][2] = fmaf(p1, vv.z, acc[1][2]); acc[1][3] = fmaf(p1, vv.w, acc[1][3]);
            acc[2][0] = fmaf(p2, vv.x, acc[2][0]); acc[2][1] = fmaf(p2, vv.y, acc[2][1]);
            acc[2][2] = fmaf(p2, vv.z, acc[2][2]); acc[2][3] = fmaf(p2, vv.w, acc[2][3]);
            acc[3][0] = fmaf(p3, vv.x, acc[3][0]); acc[3][1] = fmaf(p3, vv.y, acc[3][1]);
            acc[3][2] = fmaf(p3, vv.z, acc[3][2]); acc[3][3] = fmaf(p3, vv.w, acc[3][3]);
        }
    }

    // Normalize and write to concat layout Z[b][s][h*64 + v]
#pragma unroll
    for (int i = 0; i < 4; ++i) {
        float inv = 1.f / l[i];
        int s_row = r0 + ty * 4 + i;
        float4 o;
        o.x = acc[i][0] * inv; o.y = acc[i][1] * inv;
        o.z = acc[i][2] * inv; o.w = acc[i][3] * inv;
        *(float4*)(Z + ((size_t)(b * S_ + s_row) * N_) + h * DK_ + tx * 4) = o;
    }
}

// ---------------------------------------------------------------------------
extern "C" void kernel_launch(void* const* d_in, const int* in_sizes, int n_in,
                              void* d_out, int out_size)
{
    const float* in_q = (const float*)d_in[0];
    const float* in_k = (const float*)d_in[1];
    const float* in_v = (const float*)d_in[2];
    const float* Wq   = (const float*)d_in[3];
    const float* bq   = (const float*)d_in[4];
    const float* Wk   = (const float*)d_in[5];
    const float* bk   = (const float*)d_in[6];
    const float* Wv   = (const float*)d_in[7];
    const float* bv   = (const float*)d_in[8];
    const float* Wo   = (const float*)d_in[9];
    const float* bo   = (const float*)d_in[10];
    float* out = (float*)d_out;

    float *gq, *gk, *gv, *gz;
    cudaGetSymbolAddress((void**)&gq, g_Q);
    cudaGetSymbolAddress((void**)&gk, g_K);
    cudaGetSymbolAddress((void**)&gv, g_V);
    cudaGetSymbolAddress((void**)&gz, g_Z);

    dim3 tb(256);
    dim3 gg(N_ / 128, M_ / 128);            // (8, 64)

    gemm_kernel<0><<<gg, tb>>>(in_q, Wq, bq, gq);
    gemm_kernel<0><<<gg, tb>>>(in_k, Wk, bk, gk);
    gemm_kernel<0><<<gg, tb>>>(in_v, Wv, bv, gv);

    attn_kernel<<<dim3(S_ / 64, B_ * H_), tb>>>(gq, gk, gv, gz);

    gemm_kernel<1><<<gg, tb>>>(gz, Wo, bo, out);
}

// round 4
// speedup vs baseline: 1.3186x; 1.3186x over previous
#include <cuda_runtime.h>
#include <cuda_bf16.h>
#include <cstdint>

#define B_  4
#define S_  2048
#define D_  1024
#define H_  16
#define DK_ 64
#define M_  (B_*S_)
#define N_  1024

// Scratch
__device__ float g_Q[(size_t)B_*H_*S_*DK_];   // [b,h,s,k]
__device__ float g_K[(size_t)B_*H_*S_*DK_];
__device__ float g_V[(size_t)B_*H_*S_*DK_];
__device__ float g_Z[(size_t)B_*S_*H_*DK_];   // [b,s,h*64]

// ---------------------------------------------------------------------------
// Split a pair of floats into (hi, lo) bf16x2 registers. Low half = x0.
__device__ __forceinline__ void split2(float x0, float x1, unsigned& hi, unsigned& lo) {
    unsigned h;
    asm("cvt.rn.bf16x2.f32 %0, %1, %2;" : "=r"(h) : "f"(x1), "f"(x0));
    __nv_bfloat162 hb = *reinterpret_cast<__nv_bfloat162*>(&h);
    float h0 = __bfloat162float(hb.x);
    float h1 = __bfloat162float(hb.y);
    hi = h;
    asm("cvt.rn.bf16x2.f32 %0, %1, %2;" : "=r"(lo) : "f"(x1 - h1), "f"(x0 - h0));
}

__device__ __forceinline__ void mma16(float* c, const unsigned* a, const unsigned* b) {
    asm volatile("mma.sync.aligned.m16n8k16.row.col.f32.bf16.bf16.f32 "
        "{%0,%1,%2,%3},{%4,%5,%6,%7},{%8,%9},{%0,%1,%2,%3};"
        : "+f"(c[0]), "+f"(c[1]), "+f"(c[2]), "+f"(c[3])
        : "r"(a[0]), "r"(a[1]), "r"(a[2]), "r"(a[3]), "r"(b[0]), "r"(b[1]));
}

// Fragment index helpers (m16n8k16).
// A element (r in 0..15, kpair p' in 0..7): lane=(r&7)*4+(p'&3), reg=(p'>>2)*2+(r>>3)
// B element (n in 0..7,  kpair p' in 0..7): lane=n*4+(p'&3),     reg=p'>>2

// ---------------------------------------------------------------------------
// bf16x3 GEMM: C[M,1024] = X[M,1024]*W + bias. 128x128 tile, BK=32 (2 k16 chunks).
// 8 warps = 2(m) x 4(n), warp tile 64x32.
// MODE 0: W=[H,D,64], out scattered to [b,h,s,k]. MODE 1: W row-major, out row-major.
// ---------------------------------------------------------------------------
template<int MODE>
__global__ __launch_bounds__(256)
void gemm_tc(const float* __restrict__ X, const float* __restrict__ W,
             const float* __restrict__ bias, float* __restrict__ out)
{
    __shared__ unsigned sAh[2048], sAl[2048];   // [ks2][mt8][lane32][reg4]
    __shared__ unsigned sBh[2048], sBl[2048];   // [ks2][nt16][lane32][reg2]

    const int tid  = threadIdx.x;
    const int lane = tid & 31, warp = tid >> 5;
    const int wm   = warp >> 2, wn = warp & 3;
    const int row0 = blockIdx.y * 128, col0 = blockIdx.x * 128;
    const int g    = lane >> 2, t = lane & 3;

    float c[4][4][4];
#pragma unroll
    for (int i = 0; i < 4; ++i)
#pragma unroll
        for (int j = 0; j < 4; ++j)
#pragma unroll
            for (int q = 0; q < 4; ++q) c[i][j][q] = 0.f;

    for (int k0 = 0; k0 < 1024; k0 += 32) {
        // ---- prefetch global tiles into regs ----
        float4 ra[4], rb0[2], rb1[2];
#pragma unroll
        for (int i = 0; i < 4; ++i) {
            int idx = tid + 256 * i;
            int row = idx >> 3, kq = idx & 7;
            ra[i] = *(const float4*)(X + (size_t)(row0 + row) * 1024 + k0 + kq * 4);
        }
#pragma unroll
        for (int i = 0; i < 2; ++i) {
            int idx = tid + 256 * i;
            int kk = idx >> 5, nq = idx & 31;
            if (MODE == 0) {
                int coln = col0 + nq * 4;
                const float* base = W + (size_t)(coln >> 6) * (1024 * 64) + (coln & 63);
                rb0[i] = *(const float4*)(base + (size_t)(k0 + 2 * kk) * 64);
                rb1[i] = *(const float4*)(base + (size_t)(k0 + 2 * kk + 1) * 64);
            } else {
                rb0[i] = *(const float4*)(W + (size_t)(k0 + 2 * kk) * 1024 + col0 + nq * 4);
                rb1[i] = *(const float4*)(W + (size_t)(k0 + 2 * kk + 1) * 1024 + col0 + nq * 4);
            }
        }
        __syncthreads();
        // ---- store A fragments ----
#pragma unroll
        for (int i = 0; i < 4; ++i) {
            int idx = tid + 256 * i;
            int row = idx >> 3, kq = idx & 7;
            int r = row & 15, mt = row >> 4;
#pragma unroll
            for (int pp = 0; pp < 2; ++pp) {
                int p = 2 * kq + pp;
                int ks = p >> 3, p2 = p & 7;
                unsigned hi, lo;
                split2(pp ? ra[i].z : ra[i].x, pp ? ra[i].w : ra[i].y, hi, lo);
                unsigned bidx = ((ks * 8 + mt) * 32 + (r & 7) * 4 + (p2 & 3)) * 4
                              + (p2 >> 2) * 2 + (r >> 3);
                sAh[bidx] = hi; sAl[bidx] = lo;
            }
        }
        // ---- store B fragments ----
#pragma unroll
        for (int i = 0; i < 2; ++i) {
            int idx = tid + 256 * i;
            int kk = idx >> 5, nq = idx & 31;
            int ks = kk >> 3, p2 = kk & 7;
            float v0[4] = {rb0[i].x, rb0[i].y, rb0[i].z, rb0[i].w};
            float v1[4] = {rb1[i].x, rb1[i].y, rb1[i].z, rb1[i].w};
#pragma unroll
            for (int ci = 0; ci < 4; ++ci) {
                int n = nq * 4 + ci;
                unsigned hi, lo;
                split2(v0[ci], v1[ci], hi, lo);
                unsigned bidx = ((ks * 16 + (n >> 3)) * 32 + (n & 7) * 4 + (p2 & 3)) * 2
                              + (p2 >> 2);
                sBh[bidx] = hi; sBl[bidx] = lo;
            }
        }
        __syncthreads();

        // ---- mma: hi*hi + hi*lo + lo*hi ----
#pragma unroll
        for (int ks = 0; ks < 2; ++ks) {
            unsigned afh[4][4], afl[4][4], bfh[4][2], bfl[4][2];
#pragma unroll
            for (int mt = 0; mt < 4; ++mt) {
                unsigned base = ((ks * 8 + wm * 4 + mt) * 32 + lane) * 4;
                uint4 vh = *(const uint4*)&sAh[base];
                uint4 vl = *(const uint4*)&sAl[base];
                afh[mt][0] = vh.x; afh[mt][1] = vh.y; afh[mt][2] = vh.z; afh[mt][3] = vh.w;
                afl[mt][0] = vl.x; afl[mt][1] = vl.y; afl[mt][2] = vl.z; afl[mt][3] = vl.w;
            }
#pragma unroll
            for (int nt = 0; nt < 4; ++nt) {
                unsigned base = ((ks * 16 + wn * 4 + nt) * 32 + lane) * 2;
                uint2 vh = *(const uint2*)&sBh[base];
                uint2 vl = *(const uint2*)&sBl[base];
                bfh[nt][0] = vh.x; bfh[nt][1] = vh.y;
                bfl[nt][0] = vl.x; bfl[nt][1] = vl.y;
            }
#pragma unroll
            for (int mt = 0; mt < 4; ++mt)
#pragma unroll
                for (int nt = 0; nt < 4; ++nt) {
                    mma16(c[mt][nt], afh[mt], bfh[nt]);
                    mma16(c[mt][nt], afh[mt], bfl[nt]);
                    mma16(c[mt][nt], afl[mt], bfh[nt]);
                }
        }
    }

    // ---- epilogue: bias + store ----
#pragma unroll
    for (int mt = 0; mt < 4; ++mt) {
        int rbase = row0 + wm * 64 + mt * 16;
#pragma unroll
        for (int nt = 0; nt < 4; ++nt) {
            int ccol = col0 + wn * 32 + nt * 8 + 2 * t;
            float b0 = bias[ccol], b1 = bias[ccol + 1];
#pragma unroll
            for (int h2 = 0; h2 < 2; ++h2) {
                int r = rbase + g + h2 * 8;
                float2 v = make_float2(c[mt][nt][h2 * 2 + 0] + b0,
                                       c[mt][nt][h2 * 2 + 1] + b1);
                if (MODE == 0) {
                    int b  = r >> 11, s = r & 2047;
                    int hh = ccol >> 6, cc = ccol & 63;
                    *(float2*)(out + (((size_t)(b * H_ + hh) * S_ + s) * 64) + cc) = v;
                } else {
                    *(float2*)(out + (size_t)r * 1024 + ccol) = v;
                }
            }
        }
    }
}

// ---------------------------------------------------------------------------
// bf16x3 flash attention. Q-tile 128 rows (8 warps x 16), KV-tile 64.
// Q hi/lo fragments pinned in registers (loaded directly from global in frag
// positions); K/V hi/lo in fragment-layout smem. P C-frag maps DIRECTLY to
// PV A-frag lanes (k16 pair = adjacent kv columns) -> no P staging at all.
// Unscaled scores (faithful to reference). Online softmax.
// ---------------------------------------------------------------------------
__global__ __launch_bounds__(256)
void attn_tc(const float* __restrict__ Q, const float* __restrict__ K,
             const float* __restrict__ V, float* __restrict__ Z)
{
    __shared__ unsigned sKh[2048], sKl[2048];   // [ks4][nt8][lane32][reg2] (k=d)
    __shared__ unsigned sVh[2048], sVl[2048];   // [ks4][nt8][lane32][reg2] (k=kv)

    const int tid  = threadIdx.x;
    const int lane = tid & 31, warp = tid >> 5;
    const int g    = lane >> 2, t = lane & 3;
    const int bh   = blockIdx.y, b = bh >> 4, h = bh & 15;
    const int q0   = blockIdx.x * 128;

    const float* Qp = Q + ((size_t)bh * S_ + q0) * 64;
    const float* Kp = K + (size_t)bh * S_ * 64;
    const float* Vp = V + (size_t)bh * S_ * 64;

    // ---- Q fragments, loaded straight into frag positions ----
    unsigned qfh[4][4], qfl[4][4];
#pragma unroll
    for (int ks = 0; ks < 4; ++ks)
#pragma unroll
        for (int r2 = 0; r2 < 4; ++r2) {
            int row = warp * 16 + (r2 & 1) * 8 + g;
            int d   = ks * 16 + (t + (r2 >> 1) * 4) * 2;
            float2 qv = *(const float2*)(Qp + (size_t)row * 64 + d);
            split2(qv.x, qv.y, qfh[ks][r2], qfl[ks][r2]);
        }

    float o[8][4];
#pragma unroll
    for (int nt = 0; nt < 8; ++nt)
#pragma unroll
        for (int q = 0; q < 4; ++q) o[nt][q] = 0.f;
    float mrow[2] = {-1e30f, -1e30f};
    float lrow[2] = {0.f, 0.f};

    for (int tkv = 0; tkv < S_ / 64; ++tkv) {
        // ---- prefetch K/V tile ----
        float4 rk[4], rv0[2], rv1[2];
#pragma unroll
        for (int i = 0; i < 4; ++i) {
            int idx = tid + 256 * i;
            int kvr = idx >> 4, kq = idx & 15;
            rk[i] = *(const float4*)(Kp + (size_t)(tkv * 64 + kvr) * 64 + kq * 4);
        }
#pragma unroll
        for (int i = 0; i < 2; ++i) {
            int idx = tid + 256 * i;
            int kk = idx >> 4, dq = idx & 15;
            rv0[i] = *(const float4*)(Vp + (size_t)(tkv * 64 + 2 * kk) * 64 + dq * 4);
            rv1[i] = *(const float4*)(Vp + (size_t)(tkv * 64 + 2 * kk + 1) * 64 + dq * 4);
        }
        __syncthreads();   // prior-tile consumers done
        // ---- store K fragments (B-op of S: n=kv, k=d) ----
#pragma unroll
        for (int i = 0; i < 4; ++i) {
            int idx = tid + 256 * i;
            int kvr = idx >> 4, kq = idx & 15;
#pragma unroll
            for (int pp = 0; pp < 2; ++pp) {
                int p = 2 * kq + pp;
                int ks = p >> 3, p2 = p & 7;
                unsigned hi, lo;
                split2(pp ? rk[i].z : rk[i].x, pp ? rk[i].w : rk[i].y, hi, lo);
                unsigned bidx = ((ks * 8 + (kvr >> 3)) * 32 + (kvr & 7) * 4 + (p2 & 3)) * 2
                              + (p2 >> 2);
                sKh[bidx] = hi; sKl[bidx] = lo;
            }
        }
        // ---- store V fragments (B-op of PV: n=dv, k=kv) ----
#pragma unroll
        for (int i = 0; i < 2; ++i) {
            int idx = tid + 256 * i;
            int kk = idx >> 4, dq = idx & 15;
            int ks = kk >> 3, p2 = kk & 7;
            float v0[4] = {rv0[i].x, rv0[i].y, rv0[i].z, rv0[i].w};
            float v1[4] = {rv1[i].x, rv1[i].y, rv1[i].z, rv1[i].w};
#pragma unroll
            for (int ci = 0; ci < 4; ++ci) {
                int dv = dq * 4 + ci;
                unsigned hi, lo;
                split2(v0[ci], v1[ci], hi, lo);
                unsigned bidx = ((ks * 8 + (dv >> 3)) * 32 + (dv & 7) * 4 + (p2 & 3)) * 2
                              + (p2 >> 2);
                sVh[bidx] = hi; sVl[bidx] = lo;
            }
        }
        __syncthreads();

        // ---- S = Q K^T (16x64 per warp) ----
        float s[8][4];
#pragma unroll
        for (int j = 0; j < 8; ++j)
#pragma unroll
            for (int q = 0; q < 4; ++q) s[j][q] = 0.f;
#pragma unroll
        for (int ks = 0; ks < 4; ++ks)
#pragma unroll
            for (int j = 0; j < 8; ++j) {
                unsigned base = ((ks * 8 + j) * 32 + lane) * 2;
                uint2 vh = *(const uint2*)&sKh[base];
                uint2 vl = *(const uint2*)&sKl[base];
                unsigned bhf[2] = {vh.x, vh.y}, blf[2] = {vl.x, vl.y};
                mma16(s[j], qfh[ks], bhf);
                mma16(s[j], qfh[ks], blf);
                mma16(s[j], qfl[ks], bhf);
            }

        // ---- online softmax (rows g, g+8) ----
#pragma unroll
        for (int h2 = 0; h2 < 2; ++h2) {
            float mx = -1e30f;
#pragma unroll
            for (int j = 0; j < 8; ++j)
                mx = fmaxf(mx, fmaxf(s[j][h2 * 2], s[j][h2 * 2 + 1]));
            mx = fmaxf(mx, __shfl_xor_sync(0xffffffffu, mx, 1));
            mx = fmaxf(mx, __shfl_xor_sync(0xffffffffu, mx, 2));
            float mn   = fmaxf(mrow[h2], mx);
            float corr = __expf(mrow[h2] - mn);
            mrow[h2] = mn;
            float rs = 0.f;
#pragma unroll
            for (int j = 0; j < 8; ++j) {
                float p0 = __expf(s[j][h2 * 2] - mn);
                float p1 = __expf(s[j][h2 * 2 + 1] - mn);
                s[j][h2 * 2] = p0; s[j][h2 * 2 + 1] = p1;
                rs += p0 + p1;
            }
            rs += __shfl_xor_sync(0xffffffffu, rs, 1);
            rs += __shfl_xor_sync(0xffffffffu, rs, 2);
            lrow[h2] = lrow[h2] * corr + rs;
#pragma unroll
            for (int nt = 0; nt < 8; ++nt) {
                o[nt][h2 * 2]     *= corr;
                o[nt][h2 * 2 + 1] *= corr;
            }
        }

        // ---- P: C-frag -> A-frag entirely in registers ----
        // S-mma j gives (row g,  cols j*8+2t, j*8+2t+1) = kvpair j*4+t, and rows g+8.
        // PV chunk ks=j>>1; p' = (j&1)*4+t; regs: (j&1)*2 (+1 for rows g+8).
        unsigned pfh[4][4], pfl[4][4];
#pragma unroll
        for (int j = 0; j < 8; ++j) {
            int ks = j >> 1, i0 = (j & 1) * 2;
            split2(s[j][0], s[j][1], pfh[ks][i0],     pfl[ks][i0]);
            split2(s[j][2], s[j][3], pfh[ks][i0 + 1], pfl[ks][i0 + 1]);
        }

        // ---- O += P V ----
#pragma unroll
        for (int ks = 0; ks < 4; ++ks)
#pragma unroll
            for (int nt = 0; nt < 8; ++nt) {
                unsigned base = ((ks * 8 + nt) * 32 + lane) * 2;
                uint2 vh = *(const uint2*)&sVh[base];
                uint2 vl = *(const uint2*)&sVl[base];
                unsigned bhf[2] = {vh.x, vh.y}, blf[2] = {vl.x, vl.y};
                mma16(o[nt], pfh[ks], bhf);
                mma16(o[nt], pfh[ks], blf);
                mma16(o[nt], pfl[ks], bhf);
            }
    }

    // ---- normalize + store to concat layout Z[b][s][h*64+dv] ----
    float inv0 = 1.f / lrow[0], inv1 = 1.f / lrow[1];
    int qrow = q0 + warp * 16 + g;
#pragma unroll
    for (int nt = 0; nt < 8; ++nt) {
        int col = h * 64 + nt * 8 + 2 * t;
        *(float2*)(Z + ((size_t)(b * S_ + qrow) * 1024) + col) =
            make_float2(o[nt][0] * inv0, o[nt][1] * inv0);
        *(float2*)(Z + ((size_t)(b * S_ + qrow + 8) * 1024) + col) =
            make_float2(o[nt][2] * inv1, o[nt][3] * inv1);
    }
}

// ---------------------------------------------------------------------------
extern "C" void kernel_launch(void* const* d_in, const int* in_sizes, int n_in,
                              void* d_out, int out_size)
{
    const float* in_q = (const float*)d_in[0];
    const float* in_k = (const float*)d_in[1];
    const float* in_v = (const float*)d_in[2];
    const float* Wq   = (const float*)d_in[3];
    const float* bq   = (const float*)d_in[4];
    const float* Wk   = (const float*)d_in[5];
    const float* bk   = (const float*)d_in[6];
    const float* Wv   = (const float*)d_in[7];
    const float* bv   = (const float*)d_in[8];
    const float* Wo   = (const float*)d_in[9];
    const float* bo   = (const float*)d_in[10];
    float* out = (float*)d_out;

    float *gq, *gk, *gv, *gz;
    cudaGetSymbolAddress((void**)&gq, g_Q);
    cudaGetSymbolAddress((void**)&gk, g_K);
    cudaGetSymbolAddress((void**)&gv, g_V);
    cudaGetSymbolAddress((void**)&gz, g_Z);

    dim3 tb(256);
    dim3 gg(8, 64);                       // 128x128 tiles over [8192 x 1024]

    gemm_tc<0><<<gg, tb>>>(in_q, Wq, bq, gq);
    gemm_tc<0><<<gg, tb>>>(in_k, Wk, bk, gk);
    gemm_tc<0><<<gg, tb>>>(in_v, Wv, bv, gv);

    attn_tc<<<dim3(S_ / 128, B_ * H_), tb>>>(gq, gk, gv, gz);

    gemm_tc<1><<<gg, tb>>>(gz, Wo, bo, out);
}

// round 6
// speedup vs baseline: 2.3582x; 1.7884x over previous
#include <cuda_runtime.h>
#include <cuda_bf16.h>
#include <cstdint>

#define B_  4
#define S_  2048
#define D_  1024
#define H_  16
#define M_  (B_*S_)

// ---------------- scratch (static device memory only) ----------------------
__device__ __nv_bfloat16 g_Xh[(size_t)M_*D_]; // A operand (X or Z) hi, [8192][1024]
__device__ __nv_bfloat16 g_Xl[(size_t)M_*D_];
__device__ __nv_bfloat16 g_Wh[(size_t)D_*D_]; // B operand hi, [n][k]
__device__ __nv_bfloat16 g_Wl[(size_t)D_*D_];
__device__ __nv_bfloat16 g_Qh[(size_t)M_*D_]; // [b,h,s,64]
__device__ __nv_bfloat16 g_Ql[(size_t)M_*D_];
__device__ __nv_bfloat16 g_Kh[(size_t)M_*D_];
__device__ __nv_bfloat16 g_Kl[(size_t)M_*D_];
__device__ __nv_bfloat16 g_Vh[(size_t)M_*D_];
__device__ __nv_bfloat16 g_Vl[(size_t)M_*D_];

// ---------------- helpers ----------------------------------------------
__device__ __forceinline__ uint32_t smem_u32(const void* p) {
    uint32_t a;
    asm("{ .reg .u64 t; cvta.to.shared.u64 t, %1; cvt.u32.u64 %0, t; }" : "=r"(a) : "l"(p));
    return a;
}
__device__ __forceinline__ void split2(float x0, float x1, unsigned& hi, unsigned& lo) {
    unsigned h;
    asm("cvt.rn.bf16x2.f32 %0, %1, %2;" : "=r"(h) : "f"(x1), "f"(x0));
    __nv_bfloat162 hb = *reinterpret_cast<__nv_bfloat162*>(&h);
    float h0 = __bfloat162float(hb.x);
    float h1 = __bfloat162float(hb.y);
    hi = h;
    asm("cvt.rn.bf16x2.f32 %0, %1, %2;" : "=r"(lo) : "f"(x1 - h1), "f"(x0 - h0));
}
__device__ __forceinline__ void mma16(float* c, const unsigned* a, const unsigned* b) {
    asm volatile("mma.sync.aligned.m16n8k16.row.col.f32.bf16.bf16.f32 "
        "{%0,%1,%2,%3},{%4,%5,%6,%7},{%8,%9},{%0,%1,%2,%3};"
        : "+f"(c[0]), "+f"(c[1]), "+f"(c[2]), "+f"(c[3])
        : "r"(a[0]), "r"(a[1]), "r"(a[2]), "r"(a[3]), "r"(b[0]), "r"(b[1]));
}
__device__ __forceinline__ void ldsm4(unsigned* r, uint32_t a) {
    asm volatile("ldmatrix.sync.aligned.m8n8.x4.shared.b16 {%0,%1,%2,%3}, [%4];"
        : "=r"(r[0]), "=r"(r[1]), "=r"(r[2]), "=r"(r[3]) : "r"(a));
}
__device__ __forceinline__ void ldsm4t(unsigned* r, uint32_t a) {
    asm volatile("ldmatrix.sync.aligned.m8n8.x4.trans.shared.b16 {%0,%1,%2,%3}, [%4];"
        : "=r"(r[0]), "=r"(r[1]), "=r"(r[2]), "=r"(r[3]) : "r"(a));
}

// ---------------------------------------------------------------------------
// split_x: f32 [8192][1024] -> g_Xh / g_Xl
// ---------------------------------------------------------------------------
__global__ __launch_bounds__(256) void split_x(const float* __restrict__ src) {
    size_t gid = (size_t)blockIdx.x * 256 + threadIdx.x;   // float4 units
    float4 v = *(const float4*)(src + gid * 4);
    unsigned h0, l0, h1, l1;
    split2(v.x, v.y, h0, l0);
    split2(v.z, v.w, h1, l1);
    *(uint2*)(g_Xh + gid * 4) = make_uint2(h0, h1);
    *(uint2*)(g_Xl + gid * 4) = make_uint2(l0, l1);
}

// ---------------------------------------------------------------------------
// split_w: W[g][k][c] -> g_Wh/g_Wl [n=g*Cw+c][k]  (smem-tiled transpose)
// ---------------------------------------------------------------------------
__global__ __launch_bounds__(256) void split_w(const float* __restrict__ W, int Cw) {
    __shared__ float s[64][65];
    const int tid = threadIdx.x;
    const int k0 = blockIdx.x * 64, c0 = blockIdx.y * 64, g = blockIdx.z;
    const float* src = W + ((size_t)g * 1024 + k0) * Cw + c0;
    {
        int lc = tid & 63, kb = tid >> 6;
#pragma unroll
        for (int i = 0; i < 16; ++i) {
            int lk = kb + 4 * i;
            s[lk][lc] = src[(size_t)lk * Cw + lc];
        }
    }
    __syncthreads();
    {
        int k2 = (tid & 31) * 2, cb = tid >> 5;
#pragma unroll
        for (int i = 0; i < 8; ++i) {
            int lc = cb + 8 * i;
            unsigned hi, lo;
            split2(s[k2][lc], s[k2 + 1][lc], hi, lo);
            size_t idx = (size_t)(g * Cw + c0 + lc) * 1024 + k0 + k2;
            *(unsigned*)&g_Wh[idx] = hi;
            *(unsigned*)&g_Wl[idx] = lo;
        }
    }
}

// ---------------------------------------------------------------------------
// bf16x3 GEMM via ldmatrix + mma.sync. 128x128 tile, BK=32, double-buffered.
// 8 warps = 2(m) x 4(n), warp tile 64x32.
// MODE 0: bias + split -> (outh,outl) scattered to [b,h,s,k] bf16 hi/lo.
// MODE 1: bias -> f32 row-major outf.
// smem: 2 stages x {Ah,Al,Bh,Bl}, each 128 rows x 40 bf16 (pad 8) = 10240B.
// ---------------------------------------------------------------------------
#define GARR   10240
#define GSTAGE 40960
#define GSMTOT 81920

template<int MODE>
__global__ __launch_bounds__(256)
void gemm_bf(const float* __restrict__ bias, float* __restrict__ outf,
             __nv_bfloat16* __restrict__ outh, __nv_bfloat16* __restrict__ outl)
{
    extern __shared__ char smem[];
    const uint32_t sb = smem_u32(smem);
    const int tid = threadIdx.x, lane = tid & 31, warp = tid >> 5;
    const int wm = warp >> 2, wn = warp & 3;
    const int row0 = blockIdx.y * 128, col0 = blockIdx.x * 128;
    const int g = lane >> 2, t = lane & 3;
    const int crow = tid >> 2, cch = tid & 3;       // copy: rows crow, crow+64

    float c[4][4][4];
#pragma unroll
    for (int i = 0; i < 4; ++i)
#pragma unroll
        for (int j = 0; j < 4; ++j)
#pragma unroll
            for (int q = 0; q < 4; ++q) c[i][j][q] = 0.f;

    uint4 r[8];
    auto ldgAll = [&](int k0) {
        size_t ao = (size_t)(row0 + crow) * 1024 + k0 + cch * 8;
        size_t bo = (size_t)(col0 + crow) * 1024 + k0 + cch * 8;
        r[0] = *(const uint4*)(g_Xh + ao);
        r[1] = *(const uint4*)(g_Xh + ao + 64 * 1024);
        r[2] = *(const uint4*)(g_Xl + ao);
        r[3] = *(const uint4*)(g_Xl + ao + 64 * 1024);
        r[4] = *(const uint4*)(g_Wh + bo);
        r[5] = *(const uint4*)(g_Wh + bo + 64 * 1024);
        r[6] = *(const uint4*)(g_Wl + bo);
        r[7] = *(const uint4*)(g_Wl + bo + 64 * 1024);
    };
    auto stsAll = [&](int st) {
        char* base = smem + st * GSTAGE + crow * 80 + cch * 16;
        *(uint4*)(base)                       = r[0];
        *(uint4*)(base + 64 * 80)             = r[1];
        *(uint4*)(base + GARR)                = r[2];
        *(uint4*)(base + GARR + 64 * 80)      = r[3];
        *(uint4*)(base + 2 * GARR)            = r[4];
        *(uint4*)(base + 2 * GARR + 64 * 80)  = r[5];
        *(uint4*)(base + 3 * GARR)            = r[6];
        *(uint4*)(base + 3 * GARR + 64 * 80)  = r[7];
    };

    const int a_roff = (lane & 7) + ((lane >> 3) & 1) * 8;   // A: rows, lanes16+ -> k+8
    const int a_koff = (lane >> 4) * 8;
    const int b_roff = (lane & 7) + (lane >> 4) * 8;         // B: lanes16+ -> n+8
    const int b_koff = ((lane >> 3) & 1) * 8;

    auto mmaStage = [&](int st) {
        uint32_t s0 = sb + st * GSTAGE;
#pragma unroll
        for (int ks = 0; ks < 2; ++ks) {
            unsigned ah[4][4], al[4][4], bh[2][4], bl[2][4];
#pragma unroll
            for (int mt = 0; mt < 4; ++mt) {
                uint32_t ad = s0 + (wm * 64 + mt * 16 + a_roff) * 80 + (ks * 16 + a_koff) * 2;
                ldsm4(ah[mt], ad);
                ldsm4(al[mt], ad + GARR);
            }
#pragma unroll
            for (int np = 0; np < 2; ++np) {
                uint32_t bd = s0 + 2 * GARR + (wn * 32 + np * 16 + b_roff) * 80 + (ks * 16 + b_koff) * 2;
                ldsm4(bh[np], bd);
                ldsm4(bl[np], bd + GARR);
            }
#pragma unroll
            for (int mt = 0; mt < 4; ++mt)
#pragma unroll
                for (int nt = 0; nt < 4; ++nt) {
                    int np = nt >> 1, sl = (nt & 1) * 2;
                    unsigned bhf[2] = {bh[np][sl], bh[np][sl + 1]};
                    unsigned blf[2] = {bl[np][sl], bl[np][sl + 1]};
                    mma16(c[mt][nt], ah[mt], bhf);
                    mma16(c[mt][nt], ah[mt], blf);
                    mma16(c[mt][nt], al[mt], bhf);
                }
        }
    };

    ldgAll(0);
    stsAll(0);
    __syncthreads();
    for (int it = 0; it < 32; ++it) {
        if (it < 31) ldgAll((it + 1) * 32);
        mmaStage(it & 1);
        if (it < 31) stsAll((it + 1) & 1);
        __syncthreads();
    }

    // epilogue
#pragma unroll
    for (int mt = 0; mt < 4; ++mt)
#pragma unroll
        for (int nt = 0; nt < 4; ++nt) {
            int col = col0 + wn * 32 + nt * 8 + 2 * t;
            float b0 = bias[col], b1 = bias[col + 1];
#pragma unroll
            for (int h2 = 0; h2 < 2; ++h2) {
                int rr = row0 + wm * 64 + mt * 16 + g + h2 * 8;
                float v0 = c[mt][nt][h2 * 2 + 0] + b0;
                float v1 = c[mt][nt][h2 * 2 + 1] + b1;
                if (MODE == 0) {
                    unsigned hi, lo;
                    split2(v0, v1, hi, lo);
                    int b = rr >> 11, s = rr & 2047, hh = col >> 6;
                    size_t idx = (((size_t)(b * H_ + hh) * S_) + s) * 64 + (col & 63);
                    *(unsigned*)&outh[idx] = hi;
                    *(unsigned*)&outl[idx] = lo;
                } else {
                    *(float2*)(outf + (size_t)rr * 1024 + col) = make_float2(v0, v1);
                }
            }
        }
}

// ---------------------------------------------------------------------------
// bf16x3 flash attention. Q-tile 128 (8 warps x 16), KV-tile 64.
// Inputs pre-split bf16 hi/lo [b,h,s,64]. K/V tiles: raw uint4 copies into
// padded smem (stride 72 bf16), fragments via ldmatrix (K non-trans as B,
// V .trans as B). P: C-frag -> A-frag in registers. Unscaled scores.
// Epilogue writes Z hi/lo splits into g_Xh/g_Xl.
// ---------------------------------------------------------------------------
__global__ __launch_bounds__(256)
void attn_bf()
{
    __shared__ __nv_bfloat16 sKh[64 * 72], sKl[64 * 72];
    __shared__ __nv_bfloat16 sVh[64 * 72], sVl[64 * 72];

    const int tid  = threadIdx.x;
    const int lane = tid & 31, warp = tid >> 5;
    const int g    = lane >> 2, t = lane & 3;
    const int bh   = blockIdx.y, b = bh >> 4, h = bh & 15;
    const int q0   = blockIdx.x * 128;

    const size_t bhOff = (size_t)bh * S_ * 64;
    const __nv_bfloat16* Qph = g_Qh + bhOff + (size_t)q0 * 64;
    const __nv_bfloat16* Qpl = g_Ql + bhOff + (size_t)q0 * 64;

    const uint32_t uKh = smem_u32(sKh), uKl = smem_u32(sKl);
    const uint32_t uVh = smem_u32(sVh), uVl = smem_u32(sVl);

    // Q fragments (direct u32 loads of bf16 pairs)
    unsigned qfh[4][4], qfl[4][4];
#pragma unroll
    for (int ks = 0; ks < 4; ++ks)
#pragma unroll
        for (int r2 = 0; r2 < 4; ++r2) {
            int row = warp * 16 + (r2 & 1) * 8 + g;
            int d   = ks * 16 + (t + (r2 >> 1) * 4) * 2;
            qfh[ks][r2] = *(const unsigned*)(Qph + (size_t)row * 64 + d);
            qfl[ks][r2] = *(const unsigned*)(Qpl + (size_t)row * 64 + d);
        }

    float o[8][4];
#pragma unroll
    for (int nt = 0; nt < 8; ++nt)
#pragma unroll
        for (int q = 0; q < 4; ++q) o[nt][q] = 0.f;
    float mrow[2] = {-1e30f, -1e30f};
    float lrow[2] = {0.f, 0.f};

    const int krow = tid >> 3, kch = tid & 7;   // copy mapping
    const int b_roff = (lane & 7) + (lane >> 4) * 8;        // K (B, non-trans)
    const int b_koff = ((lane >> 3) & 1) * 8;
    const int v_roff = (lane & 7) + ((lane >> 3) & 1) * 8;  // V (B, trans)
    const int v_coff = (lane >> 4) * 8;

    for (int tkv = 0; tkv < S_ / 64; ++tkv) {
        uint4 rk[2], rkl[2], rv[2], rvl[2];
#pragma unroll
        for (int i = 0; i < 2; ++i) {
            size_t src = bhOff + (size_t)(tkv * 64 + krow + 32 * i) * 64 + kch * 8;
            rk[i]  = *(const uint4*)(g_Kh + src);
            rkl[i] = *(const uint4*)(g_Kl + src);
            rv[i]  = *(const uint4*)(g_Vh + src);
            rvl[i] = *(const uint4*)(g_Vl + src);
        }
        __syncthreads();
#pragma unroll
        for (int i = 0; i < 2; ++i) {
            int dst = (krow + 32 * i) * 72 + kch * 8;
            *(uint4*)(sKh + dst) = rk[i];
            *(uint4*)(sKl + dst) = rkl[i];
            *(uint4*)(sVh + dst) = rv[i];
            *(uint4*)(sVl + dst) = rvl[i];
        }
        __syncthreads();

        // ---- S = Q K^T (16x64 per warp) ----
        float s[8][4];
#pragma unroll
        for (int j = 0; j < 8; ++j)
#pragma unroll
            for (int q = 0; q < 4; ++q) s[j][q] = 0.f;
#pragma unroll
        for (int ks = 0; ks < 4; ++ks)
#pragma unroll
            for (int jp = 0; jp < 4; ++jp) {
                uint32_t off = ((jp * 16 + b_roff) * 72 + ks * 16 + b_koff) * 2;
                unsigned kb[4], klo[4];
                ldsm4(kb,  uKh + off);
                ldsm4(klo, uKl + off);
                unsigned bh0[2] = {kb[0], kb[1]},  bl0[2] = {klo[0], klo[1]};
                unsigned bh1[2] = {kb[2], kb[3]},  bl1[2] = {klo[2], klo[3]};
                mma16(s[2 * jp],     qfh[ks], bh0);
                mma16(s[2 * jp],     qfh[ks], bl0);
                mma16(s[2 * jp],     qfl[ks], bh0);
                mma16(s[2 * jp + 1], qfh[ks], bh1);
                mma16(s[2 * jp + 1], qfh[ks], bl1);
                mma16(s[2 * jp + 1], qfl[ks], bh1);
            }

        // ---- online softmax (rows g, g+8) ----
#pragma unroll
        for (int h2 = 0; h2 < 2; ++h2) {
            float mx = -1e30f;
#pragma unroll
            for (int j = 0; j < 8; ++j)
                mx = fmaxf(mx, fmaxf(s[j][h2 * 2], s[j][h2 * 2 + 1]));
            mx = fmaxf(mx, __shfl_xor_sync(0xffffffffu, mx, 1));
            mx = fmaxf(mx, __shfl_xor_sync(0xffffffffu, mx, 2));
            float mn   = fmaxf(mrow[h2], mx);
            float corr = __expf(mrow[h2] - mn);
            mrow[h2] = mn;
            float rs = 0.f;
#pragma unroll
            for (int j = 0; j < 8; ++j) {
                float p0 = __expf(s[j][h2 * 2] - mn);
                float p1 = __expf(s[j][h2 * 2 + 1] - mn);
                s[j][h2 * 2] = p0; s[j][h2 * 2 + 1] = p1;
                rs += p0 + p1;
            }
            rs += __shfl_xor_sync(0xffffffffu, rs, 1);
            rs += __shfl_xor_sync(0xffffffffu, rs, 2);
            lrow[h2] = lrow[h2] * corr + rs;
#pragma unroll
            for (int nt = 0; nt < 8; ++nt) {
                o[nt][h2 * 2]     *= corr;
                o[nt][h2 * 2 + 1] *= corr;
            }
        }

        // ---- P: C-frag -> A-frag in registers ----
        unsigned pfh[4][4], pfl[4][4];
#pragma unroll
        for (int j = 0; j < 8; ++j) {
            int ks = j >> 1, i0 = (j & 1) * 2;
            split2(s[j][0], s[j][1], pfh[ks][i0],     pfl[ks][i0]);
            split2(s[j][2], s[j][3], pfh[ks][i0 + 1], pfl[ks][i0 + 1]);
        }

        // ---- O += P V ----
#pragma unroll
        for (int ks = 0; ks < 4; ++ks)
#pragma unroll
            for (int np = 0; np < 4; ++np) {
                uint32_t off = ((ks * 16 + v_roff) * 72 + np * 16 + v_coff) * 2;
                unsigned vb[4], vlo[4];
                ldsm4t(vb,  uVh + off);
                ldsm4t(vlo, uVl + off);
                unsigned bh0[2] = {vb[0], vb[1]},  bl0[2] = {vlo[0], vlo[1]};
                unsigned bh1[2] = {vb[2], vb[3]},  bl1[2] = {vlo[2], vlo[3]};
                mma16(o[2 * np],     pfh[ks], bh0);
                mma16(o[2 * np],     pfh[ks], bl0);
                mma16(o[2 * np],     pfl[ks], bh0);
                mma16(o[2 * np + 1], pfh[ks], bh1);
                mma16(o[2 * np + 1], pfh[ks], bl1);
                mma16(o[2 * np + 1], pfl[ks], bh1);
            }
    }

    // ---- normalize + write Z hi/lo splits into g_Xh/g_Xl [b*S+s][h*64+dv] ----
    float inv0 = 1.f / lrow[0], inv1 = 1.f / lrow[1];
    int qrow = q0 + warp * 16 + g;
#pragma unroll
    for (int nt = 0; nt < 8; ++nt) {
        int col = h * 64 + nt * 8 + 2 * t;
        unsigned hi, lo;
        size_t i0 = (size_t)(b * S_ + qrow) * 1024 + col;
        split2(o[nt][0] * inv0, o[nt][1] * inv0, hi, lo);
        *(unsigned*)&g_Xh[i0] = hi;
        *(unsigned*)&g_Xl[i0] = lo;
        size_t i1 = (size_t)(b * S_ + qrow + 8) * 1024 + col;
        split2(o[nt][2] * inv1, o[nt][3] * inv1, hi, lo);
        *(unsigned*)&g_Xh[i1] = hi;
        *(unsigned*)&g_Xl[i1] = lo;
    }
}

// ---------------------------------------------------------------------------
extern "C" void kernel_launch(void* const* d_in, const int* in_sizes, int n_in,
                              void* d_out, int out_size)
{
    const float* in_q = (const float*)d_in[0];
    const float* in_k = (const float*)d_in[1];
    const float* in_v = (const float*)d_in[2];
    const float* Wq   = (const float*)d_in[3];
    const float* bq   = (const float*)d_in[4];
    const float* Wk   = (const float*)d_in[5];
    const float* bk   = (const float*)d_in[6];
    const float* Wv   = (const float*)d_in[7];
    const float* bv   = (const float*)d_in[8];
    const float* Wo   = (const float*)d_in[9];
    const float* bo   = (const float*)d_in[10];
    float* out = (float*)d_out;

    __nv_bfloat16 *qh, *ql, *kh, *kl, *vh, *vl;
    cudaGetSymbolAddress((void**)&qh, g_Qh);
    cudaGetSymbolAddress((void**)&ql, g_Ql);
    cudaGetSymbolAddress((void**)&kh, g_Kh);
    cudaGetSymbolAddress((void**)&kl, g_Kl);
    cudaGetSymbolAddress((void**)&vh, g_Vh);
    cudaGetSymbolAddress((void**)&vl, g_Vl);

    cudaFuncSetAttribute(gemm_bf<0>, cudaFuncAttributeMaxDynamicSharedMemorySize, GSMTOT);
    cudaFuncSetAttribute(gemm_bf<1>, cudaFuncAttributeMaxDynamicSharedMemorySize, GSMTOT);

    dim3 tb(256);
    dim3 gg(8, 64);                       // 128x128 tiles over [8192 x 1024]
    dim3 gwP(16, 1, 16);                  // proj weights [16][1024][64]
    dim3 gwO(16, 16, 1);                  // Wo [1024][1024]
    const int SX = (M_ * D_ / 4) / 256;

    split_w<<<gwP, tb>>>(Wq, 64);
    split_x<<<SX, tb>>>(in_q);
    gemm_bf<0><<<gg, tb, GSMTOT>>>(bq, nullptr, qh, ql);

    split_w<<<gwP, tb>>>(Wk, 64);
    split_x<<<SX, tb>>>(in_k);
    gemm_bf<0><<<gg, tb, GSMTOT>>>(bk, nullptr, kh, kl);

    split_w<<<gwP, tb>>>(Wv, 64);
    split_x<<<SX, tb>>>(in_v);
    gemm_bf<0><<<gg, tb, GSMTOT>>>(bv, nullptr, vh, vl);

    attn_bf<<<dim3(S_ / 128, B_ * H_), tb>>>();

    split_w<<<gwO, tb>>>(Wo, 1024);
    gemm_bf<1><<<gg, tb, GSMTOT>>>(bo, out, nullptr, nullptr);
}

// round 7
// speedup vs baseline: 2.4246x; 1.0281x over previous
#include <cuda_runtime.h>
#include <cuda_bf16.h>
#include <cstdint>

#define B_  4
#define S_  2048
#define D_  1024
#define H_  16
#define M_  (B_*S_)

// ---------------- scratch (static device memory only) ----------------------
__device__ __nv_bfloat16 g_Xh[(size_t)M_*D_]; // A operand (X or Z) hi, [8192][1024]
__device__ __nv_bfloat16 g_Xl[(size_t)M_*D_];
__device__ __nv_bfloat16 g_Wh[(size_t)D_*D_]; // B operand hi, [n][k]
__device__ __nv_bfloat16 g_Wl[(size_t)D_*D_];
__device__ __nv_bfloat16 g_Qh[(size_t)M_*D_]; // [b,h,s,64]
__device__ __nv_bfloat16 g_Ql[(size_t)M_*D_];
__device__ __nv_bfloat16 g_Kh[(size_t)M_*D_];
__device__ __nv_bfloat16 g_Kl[(size_t)M_*D_];
__device__ __nv_bfloat16 g_Vh[(size_t)M_*D_];
__device__ __nv_bfloat16 g_Vl[(size_t)M_*D_];

// ---------------- helpers ----------------------------------------------
__device__ __forceinline__ uint32_t smem_u32(const void* p) {
    uint32_t a;
    asm("{ .reg .u64 t; cvta.to.shared.u64 t, %1; cvt.u32.u64 %0, t; }" : "=r"(a) : "l"(p));
    return a;
}
__device__ __forceinline__ void cpa16(uint32_t dst, const void* src) {
    asm volatile("cp.async.cg.shared.global [%0], [%1], 16;" :: "r"(dst), "l"(src));
}
#define CP_COMMIT() asm volatile("cp.async.commit_group;" ::: "memory")
#define CP_WAIT(n)  asm volatile("cp.async.wait_group %0;" :: "n"(n) : "memory")

__device__ __forceinline__ void split2(float x0, float x1, unsigned& hi, unsigned& lo) {
    unsigned h;
    asm("cvt.rn.bf16x2.f32 %0, %1, %2;" : "=r"(h) : "f"(x1), "f"(x0));
    __nv_bfloat162 hb = *reinterpret_cast<__nv_bfloat162*>(&h);
    float h0 = __bfloat162float(hb.x);
    float h1 = __bfloat162float(hb.y);
    hi = h;
    asm("cvt.rn.bf16x2.f32 %0, %1, %2;" : "=r"(lo) : "f"(x1 - h1), "f"(x0 - h0));
}
__device__ __forceinline__ void mma16(float* c, const unsigned* a, const unsigned* b) {
    asm volatile("mma.sync.aligned.m16n8k16.row.col.f32.bf16.bf16.f32 "
        "{%0,%1,%2,%3},{%4,%5,%6,%7},{%8,%9},{%0,%1,%2,%3};"
        : "+f"(c[0]), "+f"(c[1]), "+f"(c[2]), "+f"(c[3])
        : "r"(a[0]), "r"(a[1]), "r"(a[2]), "r"(a[3]), "r"(b[0]), "r"(b[1]));
}
__device__ __forceinline__ void ldsm4(unsigned* r, uint32_t a) {
    asm volatile("ldmatrix.sync.aligned.m8n8.x4.shared.b16 {%0,%1,%2,%3}, [%4];"
        : "=r"(r[0]), "=r"(r[1]), "=r"(r[2]), "=r"(r[3]) : "r"(a));
}
__device__ __forceinline__ void ldsm4t(unsigned* r, uint32_t a) {
    asm volatile("ldmatrix.sync.aligned.m8n8.x4.trans.shared.b16 {%0,%1,%2,%3}, [%4];"
        : "=r"(r[0]), "=r"(r[1]), "=r"(r[2]), "=r"(r[3]) : "r"(a));
}

// ---------------------------------------------------------------------------
// split_x: f32 [8192][1024] -> g_Xh / g_Xl
// ---------------------------------------------------------------------------
__global__ __launch_bounds__(256) void split_x(const float* __restrict__ src) {
    size_t gid = (size_t)blockIdx.x * 256 + threadIdx.x;   // float4 units
    float4 v = *(const float4*)(src + gid * 4);
    unsigned h0, l0, h1, l1;
    split2(v.x, v.y, h0, l0);
    split2(v.z, v.w, h1, l1);
    *(uint2*)(g_Xh + gid * 4) = make_uint2(h0, h1);
    *(uint2*)(g_Xl + gid * 4) = make_uint2(l0, l1);
}

// ---------------------------------------------------------------------------
// split_w: W[g][k][c] -> g_Wh/g_Wl [n=g*Cw+c][k]  (smem-tiled transpose)
// ---------------------------------------------------------------------------
__global__ __launch_bounds__(256) void split_w(const float* __restrict__ W, int Cw) {
    __shared__ float s[64][65];
    const int tid = threadIdx.x;
    const int k0 = blockIdx.x * 64, c0 = blockIdx.y * 64, g = blockIdx.z;
    const float* src = W + ((size_t)g * 1024 + k0) * Cw + c0;
    {
        int lc = tid & 63, kb = tid >> 6;
#pragma unroll
        for (int i = 0; i < 16; ++i) {
            int lk = kb + 4 * i;
            s[lk][lc] = src[(size_t)lk * Cw + lc];
        }
    }
    __syncthreads();
    {
        int k2 = (tid & 31) * 2, cb = tid >> 5;
#pragma unroll
        for (int i = 0; i < 8; ++i) {
            int lc = cb + 8 * i;
            unsigned hi, lo;
            split2(s[k2][lc], s[k2 + 1][lc], hi, lo);
            size_t idx = (size_t)(g * Cw + c0 + lc) * 1024 + k0 + k2;
            *(unsigned*)&g_Wh[idx] = hi;
            *(unsigned*)&g_Wl[idx] = lo;
        }
    }
}

// ---------------------------------------------------------------------------
// bf16x3 GEMM, 3-stage cp.async pipeline. 128x128 tile, BK=32.
// 8 warps = 2(m) x 4(n), warp tile 64x32.
// smem: 3 stages x {Ah,Al,Bh,Bl}, each 128 rows x 40 bf16 (pad 8) = 10240B.
// ---------------------------------------------------------------------------
#define GARR   10240
#define GSTAGE 40960
#define GSMTOT (3*GSTAGE)

template<int MODE>
__global__ __launch_bounds__(256)
void gemm_bf(const float* __restrict__ bias, float* __restrict__ outf,
             __nv_bfloat16* __restrict__ outh, __nv_bfloat16* __restrict__ outl)
{
    extern __shared__ char smem[];
    const uint32_t sb = smem_u32(smem);
    const int tid = threadIdx.x, lane = tid & 31, warp = tid >> 5;
    const int wm = warp >> 2, wn = warp & 3;
    const int row0 = blockIdx.y * 128, col0 = blockIdx.x * 128;
    const int g = lane >> 2, t = lane & 3;
    const int crow = tid >> 2, cch = tid & 3;       // copy: rows crow, crow+64

    float c[4][4][4];
#pragma unroll
    for (int i = 0; i < 4; ++i)
#pragma unroll
        for (int j = 0; j < 4; ++j)
#pragma unroll
            for (int q = 0; q < 4; ++q) c[i][j][q] = 0.f;

    auto issueStage = [&](int it) {
        uint32_t base = sb + (it % 3) * GSTAGE + crow * 80 + cch * 16;
        size_t ao = (size_t)(row0 + crow) * 1024 + it * 32 + cch * 8;
        size_t bo = (size_t)(col0 + crow) * 1024 + it * 32 + cch * 8;
        cpa16(base,                      g_Xh + ao);
        cpa16(base + 64 * 80,            g_Xh + ao + 64 * 1024);
        cpa16(base + GARR,               g_Xl + ao);
        cpa16(base + GARR + 64 * 80,     g_Xl + ao + 64 * 1024);
        cpa16(base + 2 * GARR,           g_Wh + bo);
        cpa16(base + 2 * GARR + 64 * 80, g_Wh + bo + 64 * 1024);
        cpa16(base + 3 * GARR,           g_Wl + bo);
        cpa16(base + 3 * GARR + 64 * 80, g_Wl + bo + 64 * 1024);
        CP_COMMIT();
    };

    const int a_roff = (lane & 7) + ((lane >> 3) & 1) * 8;
    const int a_koff = (lane >> 4) * 8;
    const int b_roff = (lane & 7) + (lane >> 4) * 8;
    const int b_koff = ((lane >> 3) & 1) * 8;

    auto mmaStage = [&](int st) {
        uint32_t s0 = sb + st * GSTAGE;
#pragma unroll
        for (int ks = 0; ks < 2; ++ks) {
            unsigned ah[4][4], al[4][4], bh[2][4], bl[2][4];
#pragma unroll
            for (int mt = 0; mt < 4; ++mt) {
                uint32_t ad = s0 + (wm * 64 + mt * 16 + a_roff) * 80 + (ks * 16 + a_koff) * 2;
                ldsm4(ah[mt], ad);
                ldsm4(al[mt], ad + GARR);
            }
#pragma unroll
            for (int np = 0; np < 2; ++np) {
                uint32_t bd = s0 + 2 * GARR + (wn * 32 + np * 16 + b_roff) * 80 + (ks * 16 + b_koff) * 2;
                ldsm4(bh[np], bd);
                ldsm4(bl[np], bd + GARR);
            }
#pragma unroll
            for (int mt = 0; mt < 4; ++mt)
#pragma unroll
                for (int nt = 0; nt < 4; ++nt) {
                    int np = nt >> 1, sl = (nt & 1) * 2;
                    unsigned bhf[2] = {bh[np][sl], bh[np][sl + 1]};
                    unsigned blf[2] = {bl[np][sl], bl[np][sl + 1]};
                    mma16(c[mt][nt], ah[mt], bhf);
                    mma16(c[mt][nt], ah[mt], blf);
                    mma16(c[mt][nt], al[mt], bhf);
                }
        }
    };

    issueStage(0);
    issueStage(1);
    for (int it = 0; it < 32; ++it) {
        if (it < 31) { CP_WAIT(1); } else { CP_WAIT(0); }
        __syncthreads();
        if (it + 2 < 32) issueStage(it + 2);
        mmaStage(it % 3);
    }

    // epilogue
#pragma unroll
    for (int mt = 0; mt < 4; ++mt)
#pragma unroll
        for (int nt = 0; nt < 4; ++nt) {
            int col = col0 + wn * 32 + nt * 8 + 2 * t;
            float b0 = bias[col], b1 = bias[col + 1];
#pragma unroll
            for (int h2 = 0; h2 < 2; ++h2) {
                int rr = row0 + wm * 64 + mt * 16 + g + h2 * 8;
                float v0 = c[mt][nt][h2 * 2 + 0] + b0;
                float v1 = c[mt][nt][h2 * 2 + 1] + b1;
                if (MODE == 0) {
                    unsigned hi, lo;
                    split2(v0, v1, hi, lo);
                    int b = rr >> 11, s = rr & 2047, hh = col >> 6;
                    size_t idx = (((size_t)(b * H_ + hh) * S_) + s) * 64 + (col & 63);
                    *(unsigned*)&outh[idx] = hi;
                    *(unsigned*)&outl[idx] = lo;
                } else {
                    *(float2*)(outf + (size_t)rr * 1024 + col) = make_float2(v0, v1);
                }
            }
        }
}

// ---------------------------------------------------------------------------
// bf16x3 flash attention, 2-stage cp.async K/V pipeline. Q-tile 128, KV-tile 64.
// smem per stage: {Kh,Kl,Vh,Vl} each 64 rows x 72 bf16 (144B stride) = 9216B.
// ---------------------------------------------------------------------------
#define AARR  9216
#define ASTG  (4*AARR)
#define ASMT  (2*ASTG)

__global__ __launch_bounds__(256)
void attn_bf()
{
    extern __shared__ char smem[];
    const uint32_t sb = smem_u32(smem);

    const int tid  = threadIdx.x;
    const int lane = tid & 31, warp = tid >> 5;
    const int g    = lane >> 2, t = lane & 3;
    const int bh   = blockIdx.y, b = bh >> 4, h = bh & 15;
    const int q0   = blockIdx.x * 128;

    const size_t bhOff = (size_t)bh * S_ * 64;
    const __nv_bfloat16* Qph = g_Qh + bhOff + (size_t)q0 * 64;
    const __nv_bfloat16* Qpl = g_Ql + bhOff + (size_t)q0 * 64;

    // Q fragments
    unsigned qfh[4][4], qfl[4][4];
#pragma unroll
    for (int ks = 0; ks < 4; ++ks)
#pragma unroll
        for (int r2 = 0; r2 < 4; ++r2) {
            int row = warp * 16 + (r2 & 1) * 8 + g;
            int d   = ks * 16 + (t + (r2 >> 1) * 4) * 2;
            qfh[ks][r2] = *(const unsigned*)(Qph + (size_t)row * 64 + d);
            qfl[ks][r2] = *(const unsigned*)(Qpl + (size_t)row * 64 + d);
        }

    float o[8][4];
#pragma unroll
    for (int nt = 0; nt < 8; ++nt)
#pragma unroll
        for (int q = 0; q < 4; ++q) o[nt][q] = 0.f;
    float mrow[2] = {-1e30f, -1e30f};
    float lrow[2] = {0.f, 0.f};

    const int krow = tid >> 3, kch = tid & 7;
    const int b_roff = (lane & 7) + (lane >> 4) * 8;
    const int b_koff = ((lane >> 3) & 1) * 8;
    const int v_roff = (lane & 7) + ((lane >> 3) & 1) * 8;
    const int v_coff = (lane >> 4) * 8;

    auto issueKV = [&](int tkv) {
        uint32_t base = sb + (tkv & 1) * ASTG + krow * 144 + kch * 16;
#pragma unroll
        for (int i = 0; i < 2; ++i) {
            size_t src = bhOff + (size_t)(tkv * 64 + krow + 32 * i) * 64 + kch * 8;
            uint32_t d = base + i * 32 * 144;
            cpa16(d,            g_Kh + src);
            cpa16(d + AARR,     g_Kl + src);
            cpa16(d + 2 * AARR, g_Vh + src);
            cpa16(d + 3 * AARR, g_Vl + src);
        }
        CP_COMMIT();
    };

    issueKV(0);
    for (int tkv = 0; tkv < S_ / 64; ++tkv) {
        if (tkv + 1 < S_ / 64) {
            issueKV(tkv + 1);
            CP_WAIT(1);
        } else {
            CP_WAIT(0);
        }
        __syncthreads();

        uint32_t s0 = sb + (tkv & 1) * ASTG;

        // ---- S = Q K^T (16x64 per warp) ----
        float s[8][4];
#pragma unroll
        for (int j = 0; j < 8; ++j)
#pragma unroll
            for (int q = 0; q < 4; ++q) s[j][q] = 0.f;
#pragma unroll
        for (int ks = 0; ks < 4; ++ks)
#pragma unroll
            for (int jp = 0; jp < 4; ++jp) {
                uint32_t off = s0 + ((jp * 16 + b_roff) * 72 + ks * 16 + b_koff) * 2;
                unsigned kb[4], klo[4];
                ldsm4(kb,  off);
                ldsm4(klo, off + AARR);
                unsigned bh0[2] = {kb[0], kb[1]},  bl0[2] = {klo[0], klo[1]};
                unsigned bh1[2] = {kb[2], kb[3]},  bl1[2] = {klo[2], klo[3]};
                mma16(s[2 * jp],     qfh[ks], bh0);
                mma16(s[2 * jp],     qfh[ks], bl0);
                mma16(s[2 * jp],     qfl[ks], bh0);
                mma16(s[2 * jp + 1], qfh[ks], bh1);
                mma16(s[2 * jp + 1], qfh[ks], bl1);
                mma16(s[2 * jp + 1], qfl[ks], bh1);
            }

        // ---- online softmax (rows g, g+8) ----
#pragma unroll
        for (int h2 = 0; h2 < 2; ++h2) {
            float mx = -1e30f;
#pragma unroll
            for (int j = 0; j < 8; ++j)
                mx = fmaxf(mx, fmaxf(s[j][h2 * 2], s[j][h2 * 2 + 1]));
            mx = fmaxf(mx, __shfl_xor_sync(0xffffffffu, mx, 1));
            mx = fmaxf(mx, __shfl_xor_sync(0xffffffffu, mx, 2));
            float mn   = fmaxf(mrow[h2], mx);
            float corr = __expf(mrow[h2] - mn);
            mrow[h2] = mn;
            float rs = 0.f;
#pragma unroll
            for (int j = 0; j < 8; ++j) {
                float p0 = __expf(s[j][h2 * 2] - mn);
                float p1 = __expf(s[j][h2 * 2 + 1] - mn);
                s[j][h2 * 2] = p0; s[j][h2 * 2 + 1] = p1;
                rs += p0 + p1;
            }
            rs += __shfl_xor_sync(0xffffffffu, rs, 1);
            rs += __shfl_xor_sync(0xffffffffu, rs, 2);
            lrow[h2] = lrow[h2] * corr + rs;
            if (corr != 1.f) {
#pragma unroll
                for (int nt = 0; nt < 8; ++nt) {
                    o[nt][h2 * 2]     *= corr;
                    o[nt][h2 * 2 + 1] *= corr;
                }
            }
        }

        // ---- P: C-frag -> A-frag in registers ----
        unsigned pfh[4][4], pfl[4][4];
#pragma unroll
        for (int j = 0; j < 8; ++j) {
            int ks = j >> 1, i0 = (j & 1) * 2;
            split2(s[j][0], s[j][1], pfh[ks][i0],     pfl[ks][i0]);
            split2(s[j][2], s[j][3], pfh[ks][i0 + 1], pfl[ks][i0 + 1]);
        }

        // ---- O += P V ----
#pragma unroll
        for (int ks = 0; ks < 4; ++ks)
#pragma unroll
            for (int np = 0; np < 4; ++np) {
                uint32_t off = s0 + 2 * AARR + ((ks * 16 + v_roff) * 72 + np * 16 + v_coff) * 2;
                unsigned vb[4], vlo[4];
                ldsm4t(vb,  off);
                ldsm4t(vlo, off + AARR);
                unsigned bh0[2] = {vb[0], vb[1]},  bl0[2] = {vlo[0], vlo[1]};
                unsigned bh1[2] = {vb[2], vb[3]},  bl1[2] = {vlo[2], vlo[3]};
                mma16(o[2 * np],     pfh[ks], bh0);
                mma16(o[2 * np],     pfh[ks], bl0);
                mma16(o[2 * np],     pfl[ks], bh0);
                mma16(o[2 * np + 1], pfh[ks], bh1);
                mma16(o[2 * np + 1], pfh[ks], bl1);
                mma16(o[2 * np + 1], pfl[ks], bh1);
            }
        __syncthreads();
    }

    // ---- normalize + write Z hi/lo splits into g_Xh/g_Xl [b*S+s][h*64+dv] ----
    float inv0 = 1.f / lrow[0], inv1 = 1.f / lrow[1];
    int qrow = q0 + warp * 16 + g;
#pragma unroll
    for (int nt = 0; nt < 8; ++nt) {
        int col = h * 64 + nt * 8 + 2 * t;
        unsigned hi, lo;
        size_t i0 = (size_t)(b * S_ + qrow) * 1024 + col;
        split2(o[nt][0] * inv0, o[nt][1] * inv0, hi, lo);
        *(unsigned*)&g_Xh[i0] = hi;
        *(unsigned*)&g_Xl[i0] = lo;
        size_t i1 = (size_t)(b * S_ + qrow + 8) * 1024 + col;
        split2(o[nt][2] * inv1, o[nt][3] * inv1, hi, lo);
        *(unsigned*)&g_Xh[i1] = hi;
        *(unsigned*)&g_Xl[i1] = lo;
    }
}

// ---------------------------------------------------------------------------
extern "C" void kernel_launch(void* const* d_in, const int* in_sizes, int n_in,
                              void* d_out, int out_size)
{
    const float* in_q = (const float*)d_in[0];
    const float* in_k = (const float*)d_in[1];
    const float* in_v = (const float*)d_in[2];
    const float* Wq   = (const float*)d_in[3];
    const float* bq   = (const float*)d_in[4];
    const float* Wk   = (const float*)d_in[5];
    const float* bk   = (const float*)d_in[6];
    const float* Wv   = (const float*)d_in[7];
    const float* bv   = (const float*)d_in[8];
    const float* Wo   = (const float*)d_in[9];
    const float* bo   = (const float*)d_in[10];
    float* out = (float*)d_out;

    __nv_bfloat16 *qh, *ql, *kh, *kl, *vh, *vl;
    cudaGetSymbolAddress((void**)&qh, g_Qh);
    cudaGetSymbolAddress((void**)&ql, g_Ql);
    cudaGetSymbolAddress((void**)&kh, g_Kh);
    cudaGetSymbolAddress((void**)&kl, g_Kl);
    cudaGetSymbolAddress((void**)&vh, g_Vh);
    cudaGetSymbolAddress((void**)&vl, g_Vl);

    cudaFuncSetAttribute(gemm_bf<0>, cudaFuncAttributeMaxDynamicSharedMemorySize, GSMTOT);
    cudaFuncSetAttribute(gemm_bf<1>, cudaFuncAttributeMaxDynamicSharedMemorySize, GSMTOT);
    cudaFuncSetAttribute(attn_bf,    cudaFuncAttributeMaxDynamicSharedMemorySize, ASMT);

    dim3 tb(256);
    dim3 gg(8, 64);                       // 128x128 tiles over [8192 x 1024]
    dim3 gwP(16, 1, 16);                  // proj weights [16][1024][64]
    dim3 gwO(16, 16, 1);                  // Wo [1024][1024]
    const int SX = (M_ * D_ / 4) / 256;

    split_w<<<gwP, tb>>>(Wq, 64);
    split_x<<<SX, tb>>>(in_q);
    gemm_bf<0><<<gg, tb, GSMTOT>>>(bq, nullptr, qh, ql);

    split_w<<<gwP, tb>>>(Wk, 64);
    split_x<<<SX, tb>>>(in_k);
    gemm_bf<0><<<gg, tb, GSMTOT>>>(bk, nullptr, kh, kl);

    split_w<<<gwP, tb>>>(Wv, 64);
    split_x<<<SX, tb>>>(in_v);
    gemm_bf<0><<<gg, tb, GSMTOT>>>(bv, nullptr, vh, vl);

    attn_bf<<<dim3(S_ / 128, B_ * H_), tb, ASMT>>>();

    split_w<<<gwO, tb>>>(Wo, 1024);
    gemm_bf<1><<<gg, tb, GSMTOT>>>(bo, out, nullptr, nullptr);
}

// round 10
// speedup vs baseline: 2.4359x; 1.0046x over previous
#include <cuda_runtime.h>
#include <cuda_bf16.h>
#include <cstdint>

#define B_  4
#define S_  2048
#define D_  1024
#define H_  16
#define M_  (B_*S_)

// ---------------- scratch (static device memory only) ----------------------
__device__ __nv_bfloat16 g_Xh[(size_t)M_*D_]; // A operand (X or Z) hi, [8192][1024]
__device__ __nv_bfloat16 g_Xl[(size_t)M_*D_];
__device__ __nv_bfloat16 g_Wh[(size_t)D_*D_]; // B operand hi, [n][k]
__device__ __nv_bfloat16 g_Wl[(size_t)D_*D_];
__device__ __nv_bfloat16 g_Qh[(size_t)M_*D_]; // [b,h,s,64]
__device__ __nv_bfloat16 g_Ql[(size_t)M_*D_];
__device__ __nv_bfloat16 g_Kh[(size_t)M_*D_];
__device__ __nv_bfloat16 g_Kl[(size_t)M_*D_];
__device__ __nv_bfloat16 g_Vh[(size_t)M_*D_];
__device__ __nv_bfloat16 g_Vl[(size_t)M_*D_];

// ---------------- helpers ----------------------------------------------
__device__ __forceinline__ uint32_t smem_u32(const void* p) {
    uint32_t a;
    asm("{ .reg .u64 t; cvta.to.shared.u64 t, %1; cvt.u32.u64 %0, t; }" : "=r"(a) : "l"(p));
    return a;
}
__device__ __forceinline__ void cpa16(uint32_t dst, const void* src) {
    asm volatile("cp.async.cg.shared.global [%0], [%1], 16;" :: "r"(dst), "l"(src));
}
#define CP_COMMIT() asm volatile("cp.async.commit_group;" ::: "memory")
#define CP_WAIT(n)  asm volatile("cp.async.wait_group %0;" :: "n"(n) : "memory")

__device__ __forceinline__ void split2(float x0, float x1, unsigned& hi, unsigned& lo) {
    unsigned h;
    asm("cvt.rn.bf16x2.f32 %0, %1, %2;" : "=r"(h) : "f"(x1), "f"(x0));
    __nv_bfloat162 hb = *reinterpret_cast<__nv_bfloat162*>(&h);
    float h0 = __bfloat162float(hb.x);
    float h1 = __bfloat162float(hb.y);
    hi = h;
    asm("cvt.rn.bf16x2.f32 %0, %1, %2;" : "=r"(lo) : "f"(x1 - h1), "f"(x0 - h0));
}
// NOTE: non-volatile — register-only op, data deps keep it correct; lets ptxas schedule.
__device__ __forceinline__ void mma16(float* c, const unsigned* a, const unsigned* b) {
    asm("mma.sync.aligned.m16n8k16.row.col.f32.bf16.bf16.f32 "
        "{%0,%1,%2,%3},{%4,%5,%6,%7},{%8,%9},{%0,%1,%2,%3};"
        : "+f"(c[0]), "+f"(c[1]), "+f"(c[2]), "+f"(c[3])
        : "r"(a[0]), "r"(a[1]), "r"(a[2]), "r"(a[3]), "r"(b[0]), "r"(b[1]));
}
__device__ __forceinline__ void ldsm4(unsigned* r, uint32_t a) {
    asm volatile("ldmatrix.sync.aligned.m8n8.x4.shared.b16 {%0,%1,%2,%3}, [%4];"
        : "=r"(r[0]), "=r"(r[1]), "=r"(r[2]), "=r"(r[3]) : "r"(a));
}
__device__ __forceinline__ void ldsm4t(unsigned* r, uint32_t a) {
    asm volatile("ldmatrix.sync.aligned.m8n8.x4.trans.shared.b16 {%0,%1,%2,%3}, [%4];"
        : "=r"(r[0]), "=r"(r[1]), "=r"(r[2]), "=r"(r[3]) : "r"(a));
}

// ---------------------------------------------------------------------------
// split_x: f32 [8192][1024] -> g_Xh / g_Xl
// ---------------------------------------------------------------------------
__global__ __launch_bounds__(256) void split_x(const float* __restrict__ src) {
    size_t gid = (size_t)blockIdx.x * 256 + threadIdx.x;   // float4 units
    float4 v = *(const float4*)(src + gid * 4);
    unsigned h0, l0, h1, l1;
    split2(v.x, v.y, h0, l0);
    split2(v.z, v.w, h1, l1);
    *(uint2*)(g_Xh + gid * 4) = make_uint2(h0, h1);
    *(uint2*)(g_Xl + gid * 4) = make_uint2(l0, l1);
}

// ---------------------------------------------------------------------------
// split_w: W[g][k][c] -> g_Wh/g_Wl [n=g*Cw+c][k]  (smem-tiled transpose)
// ---------------------------------------------------------------------------
__global__ __launch_bounds__(256) void split_w(const float* __restrict__ W, int Cw) {
    __shared__ float s[64][65];
    const int tid = threadIdx.x;
    const int k0 = blockIdx.x * 64, c0 = blockIdx.y * 64, g = blockIdx.z;
    const float* src = W + ((size_t)g * 1024 + k0) * Cw + c0;
    {
        int lc = tid & 63, kb = tid >> 6;
#pragma unroll
        for (int i = 0; i < 16; ++i) {
            int lk = kb + 4 * i;
            s[lk][lc] = src[(size_t)lk * Cw + lc];
        }
    }
    __syncthreads();
    {
        int k2 = (tid & 31) * 2, cb = tid >> 5;
#pragma unroll
        for (int i = 0; i < 8; ++i) {
            int lc = cb + 8 * i;
            unsigned hi, lo;
            split2(s[k2][lc], s[k2 + 1][lc], hi, lo);
            size_t idx = (size_t)(g * Cw + c0 + lc) * 1024 + k0 + k2;
            *(unsigned*)&g_Wh[idx] = hi;
            *(unsigned*)&g_Wl[idx] = lo;
        }
    }
}

// ---------------------------------------------------------------------------
// bf16x3 GEMM, 3-stage cp.async pipeline. 128x128 tile, BK=32.
// 8 warps = 2(m) x 4(n), warp tile 64x32. Term-major MMA order (RAW spacing 16).
// ---------------------------------------------------------------------------
#define GARR   10240
#define GSTAGE 40960
#define GSMTOT (3*GSTAGE)

template<int MODE>
__global__ __launch_bounds__(256)
void gemm_bf(const float* __restrict__ bias, float* __restrict__ outf,
             __nv_bfloat16* __restrict__ outh, __nv_bfloat16* __restrict__ outl)
{
    extern __shared__ char smem[];
    const uint32_t sb = smem_u32(smem);
    const int tid = threadIdx.x, lane = tid & 31, warp = tid >> 5;
    const int wm = warp >> 2, wn = warp & 3;
    const int row0 = blockIdx.y * 128, col0 = blockIdx.x * 128;
    const int g = lane >> 2, t = lane & 3;
    const int crow = tid >> 2, cch = tid & 3;       // copy: rows crow, crow+64

    float c[4][4][4];
#pragma unroll
    for (int i = 0; i < 4; ++i)
#pragma unroll
        for (int j = 0; j < 4; ++j)
#pragma unroll
            for (int q = 0; q < 4; ++q) c[i][j][q] = 0.f;

    auto issueStage = [&](int it) {
        uint32_t base = sb + (it % 3) * GSTAGE + crow * 80 + cch * 16;
        size_t ao = (size_t)(row0 + crow) * 1024 + it * 32 + cch * 8;
        size_t bo = (size_t)(col0 + crow) * 1024 + it * 32 + cch * 8;
        cpa16(base,                      g_Xh + ao);
        cpa16(base + 64 * 80,            g_Xh + ao + 64 * 1024);
        cpa16(base + GARR,               g_Xl + ao);
        cpa16(base + GARR + 64 * 80,     g_Xl + ao + 64 * 1024);
        cpa16(base + 2 * GARR,           g_Wh + bo);
        cpa16(base + 2 * GARR + 64 * 80, g_Wh + bo + 64 * 1024);
        cpa16(base + 3 * GARR,           g_Wl + bo);
        cpa16(base + 3 * GARR + 64 * 80, g_Wl + bo + 64 * 1024);
        CP_COMMIT();
    };

    const int a_roff = (lane & 7) + ((lane >> 3) & 1) * 8;
    const int a_koff = (lane >> 4) * 8;
    const int b_roff = (lane & 7) + (lane >> 4) * 8;
    const int b_koff = ((lane >> 3) & 1) * 8;

    auto mmaStage = [&](int st) {
        uint32_t s0 = sb + st * GSTAGE;
#pragma unroll
        for (int ks = 0; ks < 2; ++ks) {
            unsigned ah[4][4], al[4][4], bh[2][4], bl[2][4];
#pragma unroll
            for (int mt = 0; mt < 4; ++mt) {
                uint32_t ad = s0 + (wm * 64 + mt * 16 + a_roff) * 80 + (ks * 16 + a_koff) * 2;
                ldsm4(ah[mt], ad);
                ldsm4(al[mt], ad + GARR);
            }
#pragma unroll
            for (int np = 0; np < 2; ++np) {
                uint32_t bd = s0 + 2 * GARR + (wn * 32 + np * 16 + b_roff) * 80 + (ks * 16 + b_koff) * 2;
                ldsm4(bh[np], bd);
                ldsm4(bl[np], bd + GARR);
            }
            // term-major: all hh, then all hl, then all lh (RAW spacing = 16)
#pragma unroll
            for (int mt = 0; mt < 4; ++mt)
#pragma unroll
                for (int nt = 0; nt < 4; ++nt) {
                    int np = nt >> 1, sl = (nt & 1) * 2;
                    mma16(c[mt][nt], ah[mt], &bh[np][sl]);
                }
#pragma unroll
            for (int mt = 0; mt < 4; ++mt)
#pragma unroll
                for (int nt = 0; nt < 4; ++nt) {
                    int np = nt >> 1, sl = (nt & 1) * 2;
                    mma16(c[mt][nt], ah[mt], &bl[np][sl]);
                }
#pragma unroll
            for (int mt = 0; mt < 4; ++mt)
#pragma unroll
                for (int nt = 0; nt < 4; ++nt) {
                    int np = nt >> 1, sl = (nt & 1) * 2;
                    mma16(c[mt][nt], al[mt], &bh[np][sl]);
                }
        }
    };

    issueStage(0);
    issueStage(1);
    for (int it = 0; it < 32; ++it) {
        if (it < 31) { CP_WAIT(1); } else { CP_WAIT(0); }
        __syncthreads();
        if (it + 2 < 32) issueStage(it + 2);
        mmaStage(it % 3);
    }

    // epilogue
#pragma unroll
    for (int mt = 0; mt < 4; ++mt)
#pragma unroll
        for (int nt = 0; nt < 4; ++nt) {
            int col = col0 + wn * 32 + nt * 8 + 2 * t;
            float b0 = bias[col], b1 = bias[col + 1];
#pragma unroll
            for (int h2 = 0; h2 < 2; ++h2) {
                int rr = row0 + wm * 64 + mt * 16 + g + h2 * 8;
                float v0 = c[mt][nt][h2 * 2 + 0] + b0;
                float v1 = c[mt][nt][h2 * 2 + 1] + b1;
                if (MODE == 0) {
                    unsigned hi, lo;
                    split2(v0, v1, hi, lo);
                    int b = rr >> 11, s = rr & 2047, hh = col >> 6;
                    size_t idx = (((size_t)(b * H_ + hh) * S_) + s) * 64 + (col & 63);
                    *(unsigned*)&outh[idx] = hi;
                    *(unsigned*)&outl[idx] = lo;
                } else {
                    *(float2*)(outf + (size_t)rr * 1024 + col) = make_float2(v0, v1);
                }
            }
        }
}

// ---------------------------------------------------------------------------
// bf16x3 flash attention, 2-stage cp.async K/V pipeline. Q-tile 128, KV-tile 64.
// Term-major MMA order (RAW spacing 8) in both S and PV phases.
// ---------------------------------------------------------------------------
#define AARR  9216
#define ASTG  (4*AARR)
#define ASMT  (2*ASTG)

__global__ __launch_bounds__(256)
void attn_bf()
{
    extern __shared__ char smem[];
    const uint32_t sb = smem_u32(smem);

    const int tid  = threadIdx.x;
    const int lane = tid & 31, warp = tid >> 5;
    const int g    = lane >> 2, t = lane & 3;
    const int bh   = blockIdx.y, b = bh >> 4, h = bh & 15;
    const int q0   = blockIdx.x * 128;

    const size_t bhOff = (size_t)bh * S_ * 64;
    const __nv_bfloat16* Qph = g_Qh + bhOff + (size_t)q0 * 64;
    const __nv_bfloat16* Qpl = g_Ql + bhOff + (size_t)q0 * 64;

    // Q fragments
    unsigned qfh[4][4], qfl[4][4];
#pragma unroll
    for (int ks = 0; ks < 4; ++ks)
#pragma unroll
        for (int r2 = 0; r2 < 4; ++r2) {
            int row = warp * 16 + (r2 & 1) * 8 + g;
            int d   = ks * 16 + (t + (r2 >> 1) * 4) * 2;
            qfh[ks][r2] = *(const unsigned*)(Qph + (size_t)row * 64 + d);
            qfl[ks][r2] = *(const unsigned*)(Qpl + (size_t)row * 64 + d);
        }

    float o[8][4];
#pragma unroll
    for (int nt = 0; nt < 8; ++nt)
#pragma unroll
        for (int q = 0; q < 4; ++q) o[nt][q] = 0.f;
    float mrow[2] = {-1e30f, -1e30f};
    float lrow[2] = {0.f, 0.f};

    const int krow = tid >> 3, kch = tid & 7;
    const int b_roff = (lane & 7) + (lane >> 4) * 8;
    const int b_koff = ((lane >> 3) & 1) * 8;
    const int v_roff = (lane & 7) + ((lane >> 3) & 1) * 8;
    const int v_coff = (lane >> 4) * 8;

    auto issueKV = [&](int tkv) {
        uint32_t base = sb + (tkv & 1) * ASTG + krow * 144 + kch * 16;
#pragma unroll
        for (int i = 0; i < 2; ++i) {
            size_t src = bhOff + (size_t)(tkv * 64 + krow + 32 * i) * 64 + kch * 8;
            uint32_t d = base + i * 32 * 144;
            cpa16(d,            g_Kh + src);
            cpa16(d + AARR,     g_Kl + src);
            cpa16(d + 2 * AARR, g_Vh + src);
            cpa16(d + 3 * AARR, g_Vl + src);
        }
        CP_COMMIT();
    };

    issueKV(0);
    for (int tkv = 0; tkv < S_ / 64; ++tkv) {
        if (tkv + 1 < S_ / 64) {
            issueKV(tkv + 1);
            CP_WAIT(1);
        } else {
            CP_WAIT(0);
        }
        __syncthreads();

        uint32_t s0 = sb + (tkv & 1) * ASTG;

        // ---- S = Q K^T (16x64 per warp), term-major per ks ----
        float s[8][4];
#pragma unroll
        for (int j = 0; j < 8; ++j)
#pragma unroll
            for (int q = 0; q < 4; ++q) s[j][q] = 0.f;
#pragma unroll
        for (int ks = 0; ks < 4; ++ks) {
            unsigned kb[4][4], klo[4][4];
#pragma unroll
            for (int jp = 0; jp < 4; ++jp) {
                uint32_t off = s0 + ((jp * 16 + b_roff) * 72 + ks * 16 + b_koff) * 2;
                ldsm4(kb[jp],  off);
                ldsm4(klo[jp], off + AARR);
            }
#pragma unroll
            for (int jp = 0; jp < 4; ++jp) {
                mma16(s[2 * jp],     qfh[ks], &kb[jp][0]);
                mma16(s[2 * jp + 1], qfh[ks], &kb[jp][2]);
            }
#pragma unroll
            for (int jp = 0; jp < 4; ++jp) {
                mma16(s[2 * jp],     qfh[ks], &klo[jp][0]);
                mma16(s[2 * jp + 1], qfh[ks], &klo[jp][2]);
            }
#pragma unroll
            for (int jp = 0; jp < 4; ++jp) {
                mma16(s[2 * jp],     qfl[ks], &kb[jp][0]);
                mma16(s[2 * jp + 1], qfl[ks], &kb[jp][2]);
            }
        }

        // ---- online softmax (rows g, g+8) ----
#pragma unroll
        for (int h2 = 0; h2 < 2; ++h2) {
            float mx = -1e30f;
#pragma unroll
            for (int j = 0; j < 8; ++j)
                mx = fmaxf(mx, fmaxf(s[j][h2 * 2], s[j][h2 * 2 + 1]));
            mx = fmaxf(mx, __shfl_xor_sync(0xffffffffu, mx, 1));
            mx = fmaxf(mx, __shfl_xor_sync(0xffffffffu, mx, 2));
            float mn   = fmaxf(mrow[h2], mx);
            float corr = __expf(mrow[h2] - mn);
            mrow[h2] = mn;
            float rs = 0.f;
#pragma unroll
            for (int j = 0; j < 8; ++j) {
                float p0 = __expf(s[j][h2 * 2] - mn);
                float p1 = __expf(s[j][h2 * 2 + 1] - mn);
                s[j][h2 * 2] = p0; s[j][h2 * 2 + 1] = p1;
                rs += p0 + p1;
            }
            rs += __shfl_xor_sync(0xffffffffu, rs, 1);
            rs += __shfl_xor_sync(0xffffffffu, rs, 2);
            lrow[h2] = lrow[h2] * corr + rs;
            if (corr != 1.f) {
#pragma unroll
                for (int nt = 0; nt < 8; ++nt) {
                    o[nt][h2 * 2]     *= corr;
                    o[nt][h2 * 2 + 1] *= corr;
                }
            }
        }

        // ---- P: C-frag -> A-frag in registers ----
        unsigned pfh[4][4], pfl[4][4];
#pragma unroll
        for (int j = 0; j < 8; ++j) {
            int ks = j >> 1, i0 = (j & 1) * 2;
            split2(s[j][0], s[j][1], pfh[ks][i0],     pfl[ks][i0]);
            split2(s[j][2], s[j][3], pfh[ks][i0 + 1], pfl[ks][i0 + 1]);
        }

        // ---- O += P V, term-major per ks ----
#pragma unroll
        for (int ks = 0; ks < 4; ++ks) {
            unsigned vb[4][4], vlo[4][4];
#pragma unroll
            for (int np = 0; np < 4; ++np) {
                uint32_t off = s0 + 2 * AARR + ((ks * 16 + v_roff) * 72 + np * 16 + v_coff) * 2;
                ldsm4t(vb[np],  off);
                ldsm4t(vlo[np], off + AARR);
            }
#pragma unroll
            for (int np = 0; np < 4; ++np) {
                mma16(o[2 * np],     pfh[ks], &vb[np][0]);
                mma16(o[2 * np + 1], pfh[ks], &vb[np][2]);
            }
#pragma unroll
            for (int np = 0; np < 4; ++np) {
                mma16(o[2 * np],     pfh[ks], &vlo[np][0]);
                mma16(o[2 * np + 1], pfh[ks], &vlo[np][2]);
            }
#pragma unroll
            for (int np = 0; np < 4; ++np) {
                mma16(o[2 * np],     pfl[ks], &vb[np][0]);
                mma16(o[2 * np + 1], pfl[ks], &vb[np][2]);
            }
        }
        __syncthreads();
    }

    // ---- normalize + write Z hi/lo splits into g_Xh/g_Xl [b*S+s][h*64+dv] ----
    float inv0 = 1.f / lrow[0], inv1 = 1.f / lrow[1];
    int qrow = q0 + warp * 16 + g;
#pragma unroll
    for (int nt = 0; nt < 8; ++nt) {
        int col = h * 64 + nt * 8 + 2 * t;
        unsigned hi, lo;
        size_t i0 = (size_t)(b * S_ + qrow) * 1024 + col;
        split2(o[nt][0] * inv0, o[nt][1] * inv0, hi, lo);
        *(unsigned*)&g_Xh[i0] = hi;
        *(unsigned*)&g_Xl[i0] = lo;
        size_t i1 = (size_t)(b * S_ + qrow + 8) * 1024 + col;
        split2(o[nt][2] * inv1, o[nt][3] * inv1, hi, lo);
        *(unsigned*)&g_Xh[i1] = hi;
        *(unsigned*)&g_Xl[i1] = lo;
    }
}

// ---------------------------------------------------------------------------
extern "C" void kernel_launch(void* const* d_in, const int* in_sizes, int n_in,
                              void* d_out, int out_size)
{
    const float* in_q = (const float*)d_in[0];
    const float* in_k = (const float*)d_in[1];
    const float* in_v = (const float*)d_in[2];
    const float* Wq   = (const float*)d_in[3];
    const float* bq   = (const float*)d_in[4];
    const float* Wk   = (const float*)d_in[5];
    const float* bk   = (const float*)d_in[6];
    const float* Wv   = (const float*)d_in[7];
    const float* bv   = (const float*)d_in[8];
    const float* Wo   = (const float*)d_in[9];
    const float* bo   = (const float*)d_in[10];
    float* out = (float*)d_out;

    __nv_bfloat16 *qh, *ql, *kh, *kl, *vh, *vl;
    cudaGetSymbolAddress((void**)&qh, g_Qh);
    cudaGetSymbolAddress((void**)&ql, g_Ql);
    cudaGetSymbolAddress((void**)&kh, g_Kh);
    cudaGetSymbolAddress((void**)&kl, g_Kl);
    cudaGetSymbolAddress((void**)&vh, g_Vh);
    cudaGetSymbolAddress((void**)&vl, g_Vl);

    cudaFuncSetAttribute(gemm_bf<0>, cudaFuncAttributeMaxDynamicSharedMemorySize, GSMTOT);
    cudaFuncSetAttribute(gemm_bf<1>, cudaFuncAttributeMaxDynamicSharedMemorySize, GSMTOT);
    cudaFuncSetAttribute(attn_bf,    cudaFuncAttributeMaxDynamicSharedMemorySize, ASMT);

    dim3 tb(256);
    dim3 gg(8, 64);                       // 128x128 tiles over [8192 x 1024]
    dim3 gwP(16, 1, 16);                  // proj weights [16][1024][64]
    dim3 gwO(16, 16, 1);                  // Wo [1024][1024]
    const int SX = (M_ * D_ / 4) / 256;

    split_w<<<gwP, tb>>>(Wq, 64);
    split_x<<<SX, tb>>>(in_q);
    gemm_bf<0><<<gg, tb, GSMTOT>>>(bq, nullptr, qh, ql);

    split_w<<<gwP, tb>>>(Wk, 64);
    split_x<<<SX, tb>>>(in_k);
    gemm_bf<0><<<gg, tb, GSMTOT>>>(bk, nullptr, kh, kl);

    split_w<<<gwP, tb>>>(Wv, 64);
    split_x<<<SX, tb>>>(in_v);
    gemm_bf<0><<<gg, tb, GSMTOT>>>(bv, nullptr, vh, vl);

    attn_bf<<<dim3(S_ / 128, B_ * H_), tb, ASMT>>>();

    split_w<<<gwO, tb>>>(Wo, 1024);
    gemm_bf<1><<<gg, tb, GSMTOT>>>(bo, out, nullptr, nullptr);
}

// round 12
// speedup vs baseline: 2.9969x; 1.2303x over previous
#include <cuda_runtime.h>
#include <cuda_bf16.h>
#include <cuda_fp16.h>
#include <cstdint>

#define B_  4
#define S_  2048
#define D_  1024
#define H_  16
#define M_  (B_*S_)

// ---------------- scratch (static device memory only) ----------------------
// Raw 16-bit storage; interpreted as bf16 or fp16 per stage.
__device__ __nv_bfloat16 g_Xh[(size_t)M_*D_]; // A operand (X or Z) hi
__device__ __nv_bfloat16 g_Xl[(size_t)M_*D_];
__device__ __nv_bfloat16 g_Wh[(size_t)D_*D_]; // B operand hi, [n][k]
__device__ __nv_bfloat16 g_Wl[(size_t)D_*D_];
__device__ __nv_bfloat16 g_Qh[(size_t)M_*D_]; // [b,h,s,64] bf16
__device__ __nv_bfloat16 g_Ql[(size_t)M_*D_];
__device__ __nv_bfloat16 g_Kh[(size_t)M_*D_]; // bf16
__device__ __nv_bfloat16 g_Kl[(size_t)M_*D_];
__device__ __nv_bfloat16 g_Vh[(size_t)M_*D_]; // fp16 bits (hi/lo split)
__device__ __nv_bfloat16 g_Vl[(size_t)M_*D_];

// ---------------- helpers ----------------------------------------------
__device__ __forceinline__ uint32_t smem_u32(const void* p) {
    uint32_t a;
    asm("{ .reg .u64 t; cvta.to.shared.u64 t, %1; cvt.u32.u64 %0, t; }" : "=r"(a) : "l"(p));
    return a;
}
__device__ __forceinline__ void cpa16(uint32_t dst, const void* src) {
    asm volatile("cp.async.cg.shared.global [%0], [%1], 16;" :: "r"(dst), "l"(src));
}
#define CP_COMMIT() asm volatile("cp.async.commit_group;" ::: "memory")
#define CP_WAIT(n)  asm volatile("cp.async.wait_group %0;" :: "n"(n) : "memory")

// bf16 hi/lo split (low half = x0)
__device__ __forceinline__ void split2(float x0, float x1, unsigned& hi, unsigned& lo) {
    unsigned h;
    asm("cvt.rn.bf16x2.f32 %0, %1, %2;" : "=r"(h) : "f"(x1), "f"(x0));
    __nv_bfloat162 hb = *reinterpret_cast<__nv_bfloat162*>(&h);
    float h0 = __bfloat162float(hb.x);
    float h1 = __bfloat162float(hb.y);
    hi = h;
    asm("cvt.rn.bf16x2.f32 %0, %1, %2;" : "=r"(lo) : "f"(x1 - h1), "f"(x0 - h0));
}
// fp16 hi/lo split (low half = x0)
__device__ __forceinline__ void split2h(float x0, float x1, unsigned& hi, unsigned& lo) {
    __half2 h = __floats2half2_rn(x0, x1);
    float h0 = __low2float(h), h1 = __high2float(h);
    hi = *reinterpret_cast<unsigned*>(&h);
    __half2 l = __floats2half2_rn(x0 - h0, x1 - h1);
    lo = *reinterpret_cast<unsigned*>(&l);
}
__device__ __forceinline__ unsigned pack2h(float x0, float x1) {
    __half2 h = __floats2half2_rn(x0, x1);
    return *reinterpret_cast<unsigned*>(&h);
}
__device__ __forceinline__ void mma16(float* c, const unsigned* a, const unsigned* b) {
    asm("mma.sync.aligned.m16n8k16.row.col.f32.bf16.bf16.f32 "
        "{%0,%1,%2,%3},{%4,%5,%6,%7},{%8,%9},{%0,%1,%2,%3};"
        : "+f"(c[0]), "+f"(c[1]), "+f"(c[2]), "+f"(c[3])
        : "r"(a[0]), "r"(a[1]), "r"(a[2]), "r"(a[3]), "r"(b[0]), "r"(b[1]));
}
__device__ __forceinline__ void mma16f(float* c, const unsigned* a, const unsigned* b) {
    asm("mma.sync.aligned.m16n8k16.row.col.f32.f16.f16.f32 "
        "{%0,%1,%2,%3},{%4,%5,%6,%7},{%8,%9},{%0,%1,%2,%3};"
        : "+f"(c[0]), "+f"(c[1]), "+f"(c[2]), "+f"(c[3])
        : "r"(a[0]), "r"(a[1]), "r"(a[2]), "r"(a[3]), "r"(b[0]), "r"(b[1]));
}
__device__ __forceinline__ void ldsm4(unsigned* r, uint32_t a) {
    asm volatile("ldmatrix.sync.aligned.m8n8.x4.shared.b16 {%0,%1,%2,%3}, [%4];"
        : "=r"(r[0]), "=r"(r[1]), "=r"(r[2]), "=r"(r[3]) : "r"(a));
}
__device__ __forceinline__ void ldsm4t(unsigned* r, uint32_t a) {
    asm volatile("ldmatrix.sync.aligned.m8n8.x4.trans.shared.b16 {%0,%1,%2,%3}, [%4];"
        : "=r"(r[0]), "=r"(r[1]), "=r"(r[2]), "=r"(r[3]) : "r"(a));
}

// ---------------------------------------------------------------------------
// split kernels
// ---------------------------------------------------------------------------
__global__ __launch_bounds__(256) void split_x(const float* __restrict__ src) {
    size_t gid = (size_t)blockIdx.x * 256 + threadIdx.x;
    float4 v = *(const float4*)(src + gid * 4);
    unsigned h0, l0, h1, l1;
    split2(v.x, v.y, h0, l0);
    split2(v.z, v.w, h1, l1);
    *(uint2*)(g_Xh + gid * 4) = make_uint2(h0, h1);
    *(uint2*)(g_Xl + gid * 4) = make_uint2(l0, l1);
}
__global__ __launch_bounds__(256) void split_xh(const float* __restrict__ src) {
    size_t gid = (size_t)blockIdx.x * 256 + threadIdx.x;
    float4 v = *(const float4*)(src + gid * 4);
    unsigned h0, l0, h1, l1;
    split2h(v.x, v.y, h0, l0);
    split2h(v.z, v.w, h1, l1);
    *(uint2*)(g_Xh + gid * 4) = make_uint2(h0, h1);
    *(uint2*)(g_Xl + gid * 4) = make_uint2(l0, l1);
}
// bf16 hi/lo weight transpose: W[g][k][c] -> g_Wh/g_Wl [n=g*Cw+c][k]
__global__ __launch_bounds__(256) void split_w(const float* __restrict__ W, int Cw) {
    __shared__ float s[64][65];
    const int tid = threadIdx.x;
    const int k0 = blockIdx.x * 64, c0 = blockIdx.y * 64, g = blockIdx.z;
    const float* src = W + ((size_t)g * 1024 + k0) * Cw + c0;
    {
        int lc = tid & 63, kb = tid >> 6;
#pragma unroll
        for (int i = 0; i < 16; ++i) {
            int lk = kb + 4 * i;
            s[lk][lc] = src[(size_t)lk * Cw + lc];
        }
    }
    __syncthreads();
    {
        int k2 = (tid & 31) * 2, cb = tid >> 5;
#pragma unroll
        for (int i = 0; i < 8; ++i) {
            int lc = cb + 8 * i;
            unsigned hi, lo;
            split2(s[k2][lc], s[k2 + 1][lc], hi, lo);
            size_t idx = (size_t)(g * Cw + c0 + lc) * 1024 + k0 + k2;
            *(unsigned*)&g_Wh[idx] = hi;
            *(unsigned*)&g_Wl[idx] = lo;
        }
    }
}
// fp16 single weight transpose -> g_Wh only
__global__ __launch_bounds__(256) void split_wh(const float* __restrict__ W, int Cw) {
    __shared__ float s[64][65];
    const int tid = threadIdx.x;
    const int k0 = blockIdx.x * 64, c0 = blockIdx.y * 64, g = blockIdx.z;
    const float* src = W + ((size_t)g * 1024 + k0) * Cw + c0;
    {
        int lc = tid & 63, kb = tid >> 6;
#pragma unroll
        for (int i = 0; i < 16; ++i) {
            int lk = kb + 4 * i;
            s[lk][lc] = src[(size_t)lk * Cw + lc];
        }
    }
    __syncthreads();
    {
        int k2 = (tid & 31) * 2, cb = tid >> 5;
#pragma unroll
        for (int i = 0; i < 8; ++i) {
            int lc = cb + 8 * i;
            size_t idx = (size_t)(g * Cw + c0 + lc) * 1024 + k0 + k2;
            *(unsigned*)&g_Wh[idx] = pack2h(s[k2][lc], s[k2 + 1][lc]);
        }
    }
}

// ---------------------------------------------------------------------------
// bf16x3 GEMM (score path: Q/K projections). 128x128 tile, BK=32, 3-stage.
// ---------------------------------------------------------------------------
#define GARR   10240
#define GSTAGE 40960
#define GSMTOT (3*GSTAGE)

__global__ __launch_bounds__(256)
void gemm_bf(const float* __restrict__ bias,
             __nv_bfloat16* __restrict__ outh, __nv_bfloat16* __restrict__ outl)
{
    extern __shared__ char smem[];
    const uint32_t sb = smem_u32(smem);
    const int tid = threadIdx.x, lane = tid & 31, warp = tid >> 5;
    const int wm = warp >> 2, wn = warp & 3;
    const int row0 = blockIdx.y * 128, col0 = blockIdx.x * 128;
    const int g = lane >> 2, t = lane & 3;
    const int crow = tid >> 2, cch = tid & 3;

    float c[4][4][4];
#pragma unroll
    for (int i = 0; i < 4; ++i)
#pragma unroll
        for (int j = 0; j < 4; ++j)
#pragma unroll
            for (int q = 0; q < 4; ++q) c[i][j][q] = 0.f;

    auto issueStage = [&](int it) {
        uint32_t base = sb + (it % 3) * GSTAGE + crow * 80 + cch * 16;
        size_t ao = (size_t)(row0 + crow) * 1024 + it * 32 + cch * 8;
        size_t bo = (size_t)(col0 + crow) * 1024 + it * 32 + cch * 8;
        cpa16(base,                      g_Xh + ao);
        cpa16(base + 64 * 80,            g_Xh + ao + 64 * 1024);
        cpa16(base + GARR,               g_Xl + ao);
        cpa16(base + GARR + 64 * 80,     g_Xl + ao + 64 * 1024);
        cpa16(base + 2 * GARR,           g_Wh + bo);
        cpa16(base + 2 * GARR + 64 * 80, g_Wh + bo + 64 * 1024);
        cpa16(base + 3 * GARR,           g_Wl + bo);
        cpa16(base + 3 * GARR + 64 * 80, g_Wl + bo + 64 * 1024);
        CP_COMMIT();
    };

    const int a_roff = (lane & 7) + ((lane >> 3) & 1) * 8;
    const int a_koff = (lane >> 4) * 8;
    const int b_roff = (lane & 7) + (lane >> 4) * 8;
    const int b_koff = ((lane >> 3) & 1) * 8;

    auto mmaStage = [&](int st) {
        uint32_t s0 = sb + st * GSTAGE;
#pragma unroll
        for (int ks = 0; ks < 2; ++ks) {
            unsigned ah[4][4], al[4][4], bh[2][4], bl[2][4];
#pragma unroll
            for (int mt = 0; mt < 4; ++mt) {
                uint32_t ad = s0 + (wm * 64 + mt * 16 + a_roff) * 80 + (ks * 16 + a_koff) * 2;
                ldsm4(ah[mt], ad);
                ldsm4(al[mt], ad + GARR);
            }
#pragma unroll
            for (int np = 0; np < 2; ++np) {
                uint32_t bd = s0 + 2 * GARR + (wn * 32 + np * 16 + b_roff) * 80 + (ks * 16 + b_koff) * 2;
                ldsm4(bh[np], bd);
                ldsm4(bl[np], bd + GARR);
            }
#pragma unroll
            for (int mt = 0; mt < 4; ++mt)
#pragma unroll
                for (int nt = 0; nt < 4; ++nt) {
                    int np = nt >> 1, sl = (nt & 1) * 2;
                    mma16(c[mt][nt], ah[mt], &bh[np][sl]);
                }
#pragma unroll
            for (int mt = 0; mt < 4; ++mt)
#pragma unroll
                for (int nt = 0; nt < 4; ++nt) {
                    int np = nt >> 1, sl = (nt & 1) * 2;
                    mma16(c[mt][nt], ah[mt], &bl[np][sl]);
                }
#pragma unroll
            for (int mt = 0; mt < 4; ++mt)
#pragma unroll
                for (int nt = 0; nt < 4; ++nt) {
                    int np = nt >> 1, sl = (nt & 1) * 2;
                    mma16(c[mt][nt], al[mt], &bh[np][sl]);
                }
        }
    };

    issueStage(0);
    issueStage(1);
    for (int it = 0; it < 32; ++it) {
        if (it < 31) { CP_WAIT(1); } else { CP_WAIT(0); }
        __syncthreads();
        if (it + 2 < 32) issueStage(it + 2);
        mmaStage(it % 3);
    }

#pragma unroll
    for (int mt = 0; mt < 4; ++mt)
#pragma unroll
        for (int nt = 0; nt < 4; ++nt) {
            int col = col0 + wn * 32 + nt * 8 + 2 * t;
            float b0 = bias[col], b1 = bias[col + 1];
#pragma unroll
            for (int h2 = 0; h2 < 2; ++h2) {
                int rr = row0 + wm * 64 + mt * 16 + g + h2 * 8;
                float v0 = c[mt][nt][h2 * 2 + 0] + b0;
                float v1 = c[mt][nt][h2 * 2 + 1] + b1;
                unsigned hi, lo;
                split2(v0, v1, hi, lo);
                int b = rr >> 11, s = rr & 2047, hh = col >> 6;
                size_t idx = (((size_t)(b * H_ + hh) * S_) + s) * 64 + (col & 63);
                *(unsigned*)&outh[idx] = hi;
                *(unsigned*)&outl[idx] = lo;
            }
        }
}

// ---------------------------------------------------------------------------
// fp16 2-term GEMM (direct paths: V-proj, out-proj). A = fp16 hi/lo in
// g_Xh/g_Xl, B = fp16 single in g_Wh. 128x128 tile, BK=32, 3-stage.
// MODE 0: bias + fp16-split -> [b,h,s,k] hi/lo. MODE 1: bias -> f32 row-major.
// ---------------------------------------------------------------------------
#define HSTAGE (3*GARR)
#define HSMTOT (3*HSTAGE)

template<int MODE>
__global__ __launch_bounds__(256)
void gemm_hf(const float* __restrict__ bias, float* __restrict__ outf,
             __nv_bfloat16* __restrict__ outh, __nv_bfloat16* __restrict__ outl)
{
    extern __shared__ char smem[];
    const uint32_t sb = smem_u32(smem);
    const int tid = threadIdx.x, lane = tid & 31, warp = tid >> 5;
    const int wm = warp >> 2, wn = warp & 3;
    const int row0 = blockIdx.y * 128, col0 = blockIdx.x * 128;
    const int g = lane >> 2, t = lane & 3;
    const int crow = tid >> 2, cch = tid & 3;

    float c[4][4][4];
#pragma unroll
    for (int i = 0; i < 4; ++i)
#pragma unroll
        for (int j = 0; j < 4; ++j)
#pragma unroll
            for (int q = 0; q < 4; ++q) c[i][j][q] = 0.f;

    auto issueStage = [&](int it) {
        uint32_t base = sb + (it % 3) * HSTAGE + crow * 80 + cch * 16;
        size_t ao = (size_t)(row0 + crow) * 1024 + it * 32 + cch * 8;
        size_t bo = (size_t)(col0 + crow) * 1024 + it * 32 + cch * 8;
        cpa16(base,                      g_Xh + ao);
        cpa16(base + 64 * 80,            g_Xh + ao + 64 * 1024);
        cpa16(base + GARR,               g_Xl + ao);
        cpa16(base + GARR + 64 * 80,     g_Xl + ao + 64 * 1024);
        cpa16(base + 2 * GARR,           g_Wh + bo);
        cpa16(base + 2 * GARR + 64 * 80, g_Wh + bo + 64 * 1024);
        CP_COMMIT();
    };

    const int a_roff = (lane & 7) + ((lane >> 3) & 1) * 8;
    const int a_koff = (lane >> 4) * 8;
    const int b_roff = (lane & 7) + (lane >> 4) * 8;
    const int b_koff = ((lane >> 3) & 1) * 8;

    auto mmaStage = [&](int st) {
        uint32_t s0 = sb + st * HSTAGE;
#pragma unroll
        for (int ks = 0; ks < 2; ++ks) {
            unsigned ah[4][4], al[4][4], bh[2][4];
#pragma unroll
            for (int mt = 0; mt < 4; ++mt) {
                uint32_t ad = s0 + (wm * 64 + mt * 16 + a_roff) * 80 + (ks * 16 + a_koff) * 2;
                ldsm4(ah[mt], ad);
                ldsm4(al[mt], ad + GARR);
            }
#pragma unroll
            for (int np = 0; np < 2; ++np) {
                uint32_t bd = s0 + 2 * GARR + (wn * 32 + np * 16 + b_roff) * 80 + (ks * 16 + b_koff) * 2;
                ldsm4(bh[np], bd);
            }
#pragma unroll
            for (int mt = 0; mt < 4; ++mt)
#pragma unroll
                for (int nt = 0; nt < 4; ++nt) {
                    int np = nt >> 1, sl = (nt & 1) * 2;
                    mma16f(c[mt][nt], ah[mt], &bh[np][sl]);
                }
#pragma unroll
            for (int mt = 0; mt < 4; ++mt)
#pragma unroll
                for (int nt = 0; nt < 4; ++nt) {
                    int np = nt >> 1, sl = (nt & 1) * 2;
                    mma16f(c[mt][nt], al[mt], &bh[np][sl]);
                }
        }
    };

    issueStage(0);
    issueStage(1);
    for (int it = 0; it < 32; ++it) {
        if (it < 31) { CP_WAIT(1); } else { CP_WAIT(0); }
        __syncthreads();
        if (it + 2 < 32) issueStage(it + 2);
        mmaStage(it % 3);
    }

#pragma unroll
    for (int mt = 0; mt < 4; ++mt)
#pragma unroll
        for (int nt = 0; nt < 4; ++nt) {
            int col = col0 + wn * 32 + nt * 8 + 2 * t;
            float b0 = bias[col], b1 = bias[col + 1];
#pragma unroll
            for (int h2 = 0; h2 < 2; ++h2) {
                int rr = row0 + wm * 64 + mt * 16 + g + h2 * 8;
                float v0 = c[mt][nt][h2 * 2 + 0] + b0;
                float v1 = c[mt][nt][h2 * 2 + 1] + b1;
                if (MODE == 0) {
                    unsigned hi, lo;
                    split2h(v0, v1, hi, lo);
                    int b = rr >> 11, s = rr & 2047, hh = col >> 6;
                    size_t idx = (((size_t)(b * H_ + hh) * S_) + s) * 64 + (col & 63);
                    *(unsigned*)&outh[idx] = hi;
                    *(unsigned*)&outl[idx] = lo;
                } else {
                    *(float2*)(outf + (size_t)rr * 1024 + col) = make_float2(v0, v1);
                }
            }
        }
}

// ---------------------------------------------------------------------------
// Flash attention: S = QK^T in bf16x3 (3-term), PV in fp16 2-term
// (P single fp16, V fp16 hi/lo). Q-tile 128, KV-tile 64, 2-stage cp.async.
// Epilogue writes Z as fp16 hi/lo into g_Xh/g_Xl for the out-proj.
// ---------------------------------------------------------------------------
#define AARR  9216
#define ASTG  (4*AARR)
#define ASMT  (2*ASTG)

__global__ __launch_bounds__(256)
void attn_bf()
{
    extern __shared__ char smem[];
    const uint32_t sb = smem_u32(smem);

    const int tid  = threadIdx.x;
    const int lane = tid & 31, warp = tid >> 5;
    const int g    = lane >> 2, t = lane & 3;
    const int bh   = blockIdx.y, b = bh >> 4, h = bh & 15;
    const int q0   = blockIdx.x * 128;

    const size_t bhOff = (size_t)bh * S_ * 64;
    const __nv_bfloat16* Qph = g_Qh + bhOff + (size_t)q0 * 64;
    const __nv_bfloat16* Qpl = g_Ql + bhOff + (size_t)q0 * 64;

    unsigned qfh[4][4], qfl[4][4];
#pragma unroll
    for (int ks = 0; ks < 4; ++ks)
#pragma unroll
        for (int r2 = 0; r2 < 4; ++r2) {
            int row = warp * 16 + (r2 & 1) * 8 + g;
            int d   = ks * 16 + (t + (r2 >> 1) * 4) * 2;
            qfh[ks][r2] = *(const unsigned*)(Qph + (size_t)row * 64 + d);
            qfl[ks][r2] = *(const unsigned*)(Qpl + (size_t)row * 64 + d);
        }

    float o[8][4];
#pragma unroll
    for (int nt = 0; nt < 8; ++nt)
#pragma unroll
        for (int q = 0; q < 4; ++q) o[nt][q] = 0.f;
    float mrow[2] = {-1e30f, -1e30f};
    float lrow[2] = {0.f, 0.f};

    const int krow = tid >> 3, kch = tid & 7;
    const int b_roff = (lane & 7) + (lane >> 4) * 8;
    const int b_koff = ((lane >> 3) & 1) * 8;
    const int v_roff = (lane & 7) + ((lane >> 3) & 1) * 8;
    const int v_coff = (lane >> 4) * 8;

    auto issueKV = [&](int tkv) {
        uint32_t base = sb + (tkv & 1) * ASTG + krow * 144 + kch * 16;
#pragma unroll
        for (int i = 0; i < 2; ++i) {
            size_t src = bhOff + (size_t)(tkv * 64 + krow + 32 * i) * 64 + kch * 8;
            uint32_t d = base + i * 32 * 144;
            cpa16(d,            g_Kh + src);
            cpa16(d + AARR,     g_Kl + src);
            cpa16(d + 2 * AARR, g_Vh + src);
            cpa16(d + 3 * AARR, g_Vl + src);
        }
        CP_COMMIT();
    };

    issueKV(0);
    for (int tkv = 0; tkv < S_ / 64; ++tkv) {
        if (tkv + 1 < S_ / 64) {
            issueKV(tkv + 1);
            CP_WAIT(1);
        } else {
            CP_WAIT(0);
        }
        __syncthreads();

        uint32_t s0 = sb + (tkv & 1) * ASTG;

        // ---- S = Q K^T, bf16x3, term-major ----
        float s[8][4];
#pragma unroll
        for (int j = 0; j < 8; ++j)
#pragma unroll
            for (int q = 0; q < 4; ++q) s[j][q] = 0.f;
#pragma unroll
        for (int ks = 0; ks < 4; ++ks) {
            unsigned kb[4][4], klo[4][4];
#pragma unroll
            for (int jp = 0; jp < 4; ++jp) {
                uint32_t off = s0 + ((jp * 16 + b_roff) * 72 + ks * 16 + b_koff) * 2;
                ldsm4(kb[jp],  off);
                ldsm4(klo[jp], off + AARR);
            }
#pragma unroll
            for (int jp = 0; jp < 4; ++jp) {
                mma16(s[2 * jp],     qfh[ks], &kb[jp][0]);
                mma16(s[2 * jp + 1], qfh[ks], &kb[jp][2]);
            }
#pragma unroll
            for (int jp = 0; jp < 4; ++jp) {
                mma16(s[2 * jp],     qfh[ks], &klo[jp][0]);
                mma16(s[2 * jp + 1], qfh[ks], &klo[jp][2]);
            }
#pragma unroll
            for (int jp = 0; jp < 4; ++jp) {
                mma16(s[2 * jp],     qfl[ks], &kb[jp][0]);
                mma16(s[2 * jp + 1], qfl[ks], &kb[jp][2]);
            }
        }

        // ---- online softmax (rows g, g+8) ----
#pragma unroll
        for (int h2 = 0; h2 < 2; ++h2) {
            float mx = -1e30f;
#pragma unroll
            for (int j = 0; j < 8; ++j)
                mx = fmaxf(mx, fmaxf(s[j][h2 * 2], s[j][h2 * 2 + 1]));
            mx = fmaxf(mx, __shfl_xor_sync(0xffffffffu, mx, 1));
            mx = fmaxf(mx, __shfl_xor_sync(0xffffffffu, mx, 2));
            float mn   = fmaxf(mrow[h2], mx);
            float corr = __expf(mrow[h2] - mn);
            mrow[h2] = mn;
            float rs = 0.f;
#pragma unroll
            for (int j = 0; j < 8; ++j) {
                float p0 = __expf(s[j][h2 * 2] - mn);
                float p1 = __expf(s[j][h2 * 2 + 1] - mn);
                s[j][h2 * 2] = p0; s[j][h2 * 2 + 1] = p1;
                rs += p0 + p1;
            }
            rs += __shfl_xor_sync(0xffffffffu, rs, 1);
            rs += __shfl_xor_sync(0xffffffffu, rs, 2);
            lrow[h2] = lrow[h2] * corr + rs;
            if (corr != 1.f) {
#pragma unroll
                for (int nt = 0; nt < 8; ++nt) {
                    o[nt][h2 * 2]     *= corr;
                    o[nt][h2 * 2 + 1] *= corr;
                }
            }
        }

        // ---- P: C-frag -> A-frag, single fp16 ----
        unsigned pf[4][4];
#pragma unroll
        for (int j = 0; j < 8; ++j) {
            int ks = j >> 1, i0 = (j & 1) * 2;
            pf[ks][i0]     = pack2h(s[j][0], s[j][1]);
            pf[ks][i0 + 1] = pack2h(s[j][2], s[j][3]);
        }

        // ---- O += P V, fp16 2-term (P single, V hi/lo), term-major ----
#pragma unroll
        for (int ks = 0; ks < 4; ++ks) {
            unsigned vb[4][4], vlo[4][4];
#pragma unroll
            for (int np = 0; np < 4; ++np) {
                uint32_t off = s0 + 2 * AARR + ((ks * 16 + v_roff) * 72 + np * 16 + v_coff) * 2;
                ldsm4t(vb[np],  off);
                ldsm4t(vlo[np], off + AARR);
            }
#pragma unroll
            for (int np = 0; np < 4; ++np) {
                mma16f(o[2 * np],     pf[ks], &vb[np][0]);
                mma16f(o[2 * np + 1], pf[ks], &vb[np][2]);
            }
#pragma unroll
            for (int np = 0; np < 4; ++np) {
                mma16f(o[2 * np],     pf[ks], &vlo[np][0]);
                mma16f(o[2 * np + 1], pf[ks], &vlo[np][2]);
            }
        }
        __syncthreads();
    }

    // ---- normalize + write Z fp16 hi/lo into g_Xh/g_Xl [b*S+s][h*64+dv] ----
    float inv0 = 1.f / lrow[0], inv1 = 1.f / lrow[1];
    int qrow = q0 + warp * 16 + g;
#pragma unroll
    for (int nt = 0; nt < 8; ++nt) {
        int col = h * 64 + nt * 8 + 2 * t;
        unsigned hi, lo;
        size_t i0 = (size_t)(b * S_ + qrow) * 1024 + col;
        split2h(o[nt][0] * inv0, o[nt][1] * inv0, hi, lo);
        *(unsigned*)&g_Xh[i0] = hi;
        *(unsigned*)&g_Xl[i0] = lo;
        size_t i1 = (size_t)(b * S_ + qrow + 8) * 1024 + col;
        split2h(o[nt][2] * inv1, o[nt][3] * inv1, hi, lo);
        *(unsigned*)&g_Xh[i1] = hi;
        *(unsigned*)&g_Xl[i1] = lo;
    }
}

// ---------------------------------------------------------------------------
extern "C" void kernel_launch(void* const* d_in, const int* in_sizes, int n_in,
                              void* d_out, int out_size)
{
    const float* in_q = (const float*)d_in[0];
    const float* in_k = (const float*)d_in[1];
    const float* in_v = (const float*)d_in[2];
    const float* Wq   = (const float*)d_in[3];
    const float* bq   = (const float*)d_in[4];
    const float* Wk   = (const float*)d_in[5];
    const float* bk   = (const float*)d_in[6];
    const float* Wv   = (const float*)d_in[7];
    const float* bv   = (const float*)d_in[8];
    const float* Wo   = (const float*)d_in[9];
    const float* bo   = (const float*)d_in[10];
    float* out = (float*)d_out;

    __nv_bfloat16 *qh, *ql, *kh, *kl, *vh, *vl;
    cudaGetSymbolAddress((void**)&qh, g_Qh);
    cudaGetSymbolAddress((void**)&ql, g_Ql);
    cudaGetSymbolAddress((void**)&kh, g_Kh);
    cudaGetSymbolAddress((void**)&kl, g_Kl);
    cudaGetSymbolAddress((void**)&vh, g_Vh);
    cudaGetSymbolAddress((void**)&vl, g_Vl);

    cudaFuncSetAttribute(gemm_bf,    cudaFuncAttributeMaxDynamicSharedMemorySize, GSMTOT);
    cudaFuncSetAttribute(gemm_hf<0>, cudaFuncAttributeMaxDynamicSharedMemorySize, HSMTOT);
    cudaFuncSetAttribute(gemm_hf<1>, cudaFuncAttributeMaxDynamicSharedMemorySize, HSMTOT);
    cudaFuncSetAttribute(attn_bf,    cudaFuncAttributeMaxDynamicSharedMemorySize, ASMT);

    dim3 tb(256);
    dim3 gg(8, 64);                       // 128x128 tiles over [8192 x 1024]
    dim3 gwP(16, 1, 16);                  // proj weights [16][1024][64]
    dim3 gwO(16, 16, 1);                  // Wo [1024][1024]
    const int SX = (M_ * D_ / 4) / 256;

    // Q projection (bf16x3)
    split_w<<<gwP, tb>>>(Wq, 64);
    split_x<<<SX, tb>>>(in_q);
    gemm_bf<<<gg, tb, GSMTOT>>>(bq, qh, ql);

    // K projection (bf16x3)
    split_w<<<gwP, tb>>>(Wk, 64);
    split_x<<<SX, tb>>>(in_k);
    gemm_bf<<<gg, tb, GSMTOT>>>(bk, kh, kl);

    // V projection (fp16 2-term)
    split_wh<<<gwP, tb>>>(Wv, 64);
    split_xh<<<SX, tb>>>(in_v);
    gemm_hf<0><<<gg, tb, HSMTOT>>>(bv, nullptr, vh, vl);

    // attention (S bf16x3, PV fp16 2-term)
    attn_bf<<<dim3(S_ / 128, B_ * H_), tb, ASMT>>>();

    // output projection (fp16 2-term)
    split_wh<<<gwO, tb>>>(Wo, 1024);
    gemm_hf<1><<<gg, tb, HSMTOT>>>(bo, out, nullptr, nullptr);
}

// round 13
// speedup vs baseline: 3.3352x; 1.1129x over previous
#include <cuda_runtime.h>
#include <cuda_bf16.h>
#include <cuda_fp16.h>
#include <cstdint>

#define B_  4
#define S_  2048
#define D_  1024
#define H_  16
#define M_  (B_*S_)

// ---------------- scratch (static device memory only) ----------------------
// Raw 16-bit storage; interpreted as bf16 or fp16 per stage.
__device__ __nv_bfloat16 g_Xh[(size_t)M_*D_]; // A operand (X or Z) hi
__device__ __nv_bfloat16 g_Xl[(size_t)M_*D_];
__device__ __nv_bfloat16 g_Wh[(size_t)D_*D_]; // B operand hi, [n][k]
__device__ __nv_bfloat16 g_Wl[(size_t)D_*D_];
__device__ __nv_bfloat16 g_Qh[(size_t)M_*D_]; // [b,h,s,64] bf16 hi/lo
__device__ __nv_bfloat16 g_Ql[(size_t)M_*D_];
__device__ __nv_bfloat16 g_Kh[(size_t)M_*D_]; // bf16 hi/lo
__device__ __nv_bfloat16 g_Kl[(size_t)M_*D_];
__device__ __nv_bfloat16 g_Vh[(size_t)M_*D_]; // fp16 single

// ---------------- helpers ----------------------------------------------
__device__ __forceinline__ uint32_t smem_u32(const void* p) {
    uint32_t a;
    asm("{ .reg .u64 t; cvta.to.shared.u64 t, %1; cvt.u32.u64 %0, t; }" : "=r"(a) : "l"(p));
    return a;
}
__device__ __forceinline__ void cpa16(uint32_t dst, const void* src) {
    asm volatile("cp.async.cg.shared.global [%0], [%1], 16;" :: "r"(dst), "l"(src));
}
#define CP_COMMIT() asm volatile("cp.async.commit_group;" ::: "memory")
#define CP_WAIT(n)  asm volatile("cp.async.wait_group %0;" :: "n"(n) : "memory")

// bf16 hi/lo split (low half = x0)
__device__ __forceinline__ void split2(float x0, float x1, unsigned& hi, unsigned& lo) {
    unsigned h;
    asm("cvt.rn.bf16x2.f32 %0, %1, %2;" : "=r"(h) : "f"(x1), "f"(x0));
    __nv_bfloat162 hb = *reinterpret_cast<__nv_bfloat162*>(&h);
    float h0 = __bfloat162float(hb.x);
    float h1 = __bfloat162float(hb.y);
    hi = h;
    asm("cvt.rn.bf16x2.f32 %0, %1, %2;" : "=r"(lo) : "f"(x1 - h1), "f"(x0 - h0));
}
__device__ __forceinline__ unsigned pack2h(float x0, float x1) {
    __half2 h = __floats2half2_rn(x0, x1);
    return *reinterpret_cast<unsigned*>(&h);
}
__device__ __forceinline__ void mma16(float* c, const unsigned* a, const unsigned* b) {
    asm("mma.sync.aligned.m16n8k16.row.col.f32.bf16.bf16.f32 "
        "{%0,%1,%2,%3},{%4,%5,%6,%7},{%8,%9},{%0,%1,%2,%3};"
        : "+f"(c[0]), "+f"(c[1]), "+f"(c[2]), "+f"(c[3])
        : "r"(a[0]), "r"(a[1]), "r"(a[2]), "r"(a[3]), "r"(b[0]), "r"(b[1]));
}
__device__ __forceinline__ void mma16f(float* c, const unsigned* a, const unsigned* b) {
    asm("mma.sync.aligned.m16n8k16.row.col.f32.f16.f16.f32 "
        "{%0,%1,%2,%3},{%4,%5,%6,%7},{%8,%9},{%0,%1,%2,%3};"
        : "+f"(c[0]), "+f"(c[1]), "+f"(c[2]), "+f"(c[3])
        : "r"(a[0]), "r"(a[1]), "r"(a[2]), "r"(a[3]), "r"(b[0]), "r"(b[1]));
}
__device__ __forceinline__ void ldsm4(unsigned* r, uint32_t a) {
    asm volatile("ldmatrix.sync.aligned.m8n8.x4.shared.b16 {%0,%1,%2,%3}, [%4];"
        : "=r"(r[0]), "=r"(r[1]), "=r"(r[2]), "=r"(r[3]) : "r"(a));
}
__device__ __forceinline__ void ldsm4t(unsigned* r, uint32_t a) {
    asm volatile("ldmatrix.sync.aligned.m8n8.x4.trans.shared.b16 {%0,%1,%2,%3}, [%4];"
        : "=r"(r[0]), "=r"(r[1]), "=r"(r[2]), "=r"(r[3]) : "r"(a));
}

// ---------------------------------------------------------------------------
// split kernels
// ---------------------------------------------------------------------------
__global__ __launch_bounds__(256) void split_x(const float* __restrict__ src) {
    size_t gid = (size_t)blockIdx.x * 256 + threadIdx.x;
    float4 v = *(const float4*)(src + gid * 4);
    unsigned h0, l0, h1, l1;
    split2(v.x, v.y, h0, l0);
    split2(v.z, v.w, h1, l1);
    *(uint2*)(g_Xh + gid * 4) = make_uint2(h0, h1);
    *(uint2*)(g_Xl + gid * 4) = make_uint2(l0, l1);
}
// single fp16 pack (direct paths)
__global__ __launch_bounds__(256) void split_xh(const float* __restrict__ src) {
    size_t gid = (size_t)blockIdx.x * 256 + threadIdx.x;
    float4 v = *(const float4*)(src + gid * 4);
    *(uint2*)(g_Xh + gid * 4) = make_uint2(pack2h(v.x, v.y), pack2h(v.z, v.w));
}
// bf16 hi/lo weight transpose: W[g][k][c] -> g_Wh/g_Wl [n=g*Cw+c][k]
__global__ __launch_bounds__(256) void split_w(const float* __restrict__ W, int Cw) {
    __shared__ float s[64][65];
    const int tid = threadIdx.x;
    const int k0 = blockIdx.x * 64, c0 = blockIdx.y * 64, g = blockIdx.z;
    const float* src = W + ((size_t)g * 1024 + k0) * Cw + c0;
    {
        int lc = tid & 63, kb = tid >> 6;
#pragma unroll
        for (int i = 0; i < 16; ++i) {
            int lk = kb + 4 * i;
            s[lk][lc] = src[(size_t)lk * Cw + lc];
        }
    }
    __syncthreads();
    {
        int k2 = (tid & 31) * 2, cb = tid >> 5;
#pragma unroll
        for (int i = 0; i < 8; ++i) {
            int lc = cb + 8 * i;
            unsigned hi, lo;
            split2(s[k2][lc], s[k2 + 1][lc], hi, lo);
            size_t idx = (size_t)(g * Cw + c0 + lc) * 1024 + k0 + k2;
            *(unsigned*)&g_Wh[idx] = hi;
            *(unsigned*)&g_Wl[idx] = lo;
        }
    }
}
// fp16 single weight transpose -> g_Wh only
__global__ __launch_bounds__(256) void split_wh(const float* __restrict__ W, int Cw) {
    __shared__ float s[64][65];
    const int tid = threadIdx.x;
    const int k0 = blockIdx.x * 64, c0 = blockIdx.y * 64, g = blockIdx.z;
    const float* src = W + ((size_t)g * 1024 + k0) * Cw + c0;
    {
        int lc = tid & 63, kb = tid >> 6;
#pragma unroll
        for (int i = 0; i < 16; ++i) {
            int lk = kb + 4 * i;
            s[lk][lc] = src[(size_t)lk * Cw + lc];
        }
    }
    __syncthreads();
    {
        int k2 = (tid & 31) * 2, cb = tid >> 5;
#pragma unroll
        for (int i = 0; i < 8; ++i) {
            int lc = cb + 8 * i;
            size_t idx = (size_t)(g * Cw + c0 + lc) * 1024 + k0 + k2;
            *(unsigned*)&g_Wh[idx] = pack2h(s[k2][lc], s[k2 + 1][lc]);
        }
    }
}

// ---------------------------------------------------------------------------
// bf16x3 GEMM (score path: Q/K projections). 128x128 tile, BK=32, 3-stage.
// ---------------------------------------------------------------------------
#define GARR   10240
#define GSTAGE 40960
#define GSMTOT (3*GSTAGE)

__global__ __launch_bounds__(256)
void gemm_bf(const float* __restrict__ bias,
             __nv_bfloat16* __restrict__ outh, __nv_bfloat16* __restrict__ outl)
{
    extern __shared__ char smem[];
    const uint32_t sb = smem_u32(smem);
    const int tid = threadIdx.x, lane = tid & 31, warp = tid >> 5;
    const int wm = warp >> 2, wn = warp & 3;
    const int row0 = blockIdx.y * 128, col0 = blockIdx.x * 128;
    const int g = lane >> 2, t = lane & 3;
    const int crow = tid >> 2, cch = tid & 3;

    float c[4][4][4];
#pragma unroll
    for (int i = 0; i < 4; ++i)
#pragma unroll
        for (int j = 0; j < 4; ++j)
#pragma unroll
            for (int q = 0; q < 4; ++q) c[i][j][q] = 0.f;

    auto issueStage = [&](int it) {
        uint32_t base = sb + (it % 3) * GSTAGE + crow * 80 + cch * 16;
        size_t ao = (size_t)(row0 + crow) * 1024 + it * 32 + cch * 8;
        size_t bo = (size_t)(col0 + crow) * 1024 + it * 32 + cch * 8;
        cpa16(base,                      g_Xh + ao);
        cpa16(base + 64 * 80,            g_Xh + ao + 64 * 1024);
        cpa16(base + GARR,               g_Xl + ao);
        cpa16(base + GARR + 64 * 80,     g_Xl + ao + 64 * 1024);
        cpa16(base + 2 * GARR,           g_Wh + bo);
        cpa16(base + 2 * GARR + 64 * 80, g_Wh + bo + 64 * 1024);
        cpa16(base + 3 * GARR,           g_Wl + bo);
        cpa16(base + 3 * GARR + 64 * 80, g_Wl + bo + 64 * 1024);
        CP_COMMIT();
    };

    const int a_roff = (lane & 7) + ((lane >> 3) & 1) * 8;
    const int a_koff = (lane >> 4) * 8;
    const int b_roff = (lane & 7) + (lane >> 4) * 8;
    const int b_koff = ((lane >> 3) & 1) * 8;

    auto mmaStage = [&](int st) {
        uint32_t s0 = sb + st * GSTAGE;
#pragma unroll
        for (int ks = 0; ks < 2; ++ks) {
            unsigned ah[4][4], al[4][4], bh[2][4], bl[2][4];
#pragma unroll
            for (int mt = 0; mt < 4; ++mt) {
                uint32_t ad = s0 + (wm * 64 + mt * 16 + a_roff) * 80 + (ks * 16 + a_koff) * 2;
                ldsm4(ah[mt], ad);
                ldsm4(al[mt], ad + GARR);
            }
#pragma unroll
            for (int np = 0; np < 2; ++np) {
                uint32_t bd = s0 + 2 * GARR + (wn * 32 + np * 16 + b_roff) * 80 + (ks * 16 + b_koff) * 2;
                ldsm4(bh[np], bd);
                ldsm4(bl[np], bd + GARR);
            }
#pragma unroll
            for (int mt = 0; mt < 4; ++mt)
#pragma unroll
                for (int nt = 0; nt < 4; ++nt) {
                    int np = nt >> 1, sl = (nt & 1) * 2;
                    mma16(c[mt][nt], ah[mt], &bh[np][sl]);
                }
#pragma unroll
            for (int mt = 0; mt < 4; ++mt)
#pragma unroll
                for (int nt = 0; nt < 4; ++nt) {
                    int np = nt >> 1, sl = (nt & 1) * 2;
                    mma16(c[mt][nt], ah[mt], &bl[np][sl]);
                }
#pragma unroll
            for (int mt = 0; mt < 4; ++mt)
#pragma unroll
                for (int nt = 0; nt < 4; ++nt) {
                    int np = nt >> 1, sl = (nt & 1) * 2;
                    mma16(c[mt][nt], al[mt], &bh[np][sl]);
                }
        }
    };

    issueStage(0);
    issueStage(1);
    for (int it = 0; it < 32; ++it) {
        if (it < 31) { CP_WAIT(1); } else { CP_WAIT(0); }
        __syncthreads();
        if (it + 2 < 32) issueStage(it + 2);
        mmaStage(it % 3);
    }

#pragma unroll
    for (int mt = 0; mt < 4; ++mt)
#pragma unroll
        for (int nt = 0; nt < 4; ++nt) {
            int col = col0 + wn * 32 + nt * 8 + 2 * t;
            float b0 = bias[col], b1 = bias[col + 1];
#pragma unroll
            for (int h2 = 0; h2 < 2; ++h2) {
                int rr = row0 + wm * 64 + mt * 16 + g + h2 * 8;
                float v0 = c[mt][nt][h2 * 2 + 0] + b0;
                float v1 = c[mt][nt][h2 * 2 + 1] + b1;
                unsigned hi, lo;
                split2(v0, v1, hi, lo);
                int b = rr >> 11, s = rr & 2047, hh = col >> 6;
                size_t idx = (((size_t)(b * H_ + hh) * S_) + s) * 64 + (col & 63);
                *(unsigned*)&outh[idx] = hi;
                *(unsigned*)&outl[idx] = lo;
            }
        }
}

// ---------------------------------------------------------------------------
// fp16 1-term GEMM (direct paths: V-proj, out-proj). A = fp16 single in g_Xh,
// B = fp16 single in g_Wh. 128x128 tile, BK=32, 3-stage.
// MODE 0: bias + fp16 -> [b,h,s,k] single. MODE 1: bias -> f32 row-major.
// ---------------------------------------------------------------------------
#define HSTAGE (2*GARR)
#define HSMTOT (3*HSTAGE)

template<int MODE>
__global__ __launch_bounds__(256)
void gemm_hf(const float* __restrict__ bias, float* __restrict__ outf,
             __nv_bfloat16* __restrict__ outh)
{
    extern __shared__ char smem[];
    const uint32_t sb = smem_u32(smem);
    const int tid = threadIdx.x, lane = tid & 31, warp = tid >> 5;
    const int wm = warp >> 2, wn = warp & 3;
    const int row0 = blockIdx.y * 128, col0 = blockIdx.x * 128;
    const int g = lane >> 2, t = lane & 3;
    const int crow = tid >> 2, cch = tid & 3;

    float c[4][4][4];
#pragma unroll
    for (int i = 0; i < 4; ++i)
#pragma unroll
        for (int j = 0; j < 4; ++j)
#pragma unroll
            for (int q = 0; q < 4; ++q) c[i][j][q] = 0.f;

    auto issueStage = [&](int it) {
        uint32_t base = sb + (it % 3) * HSTAGE + crow * 80 + cch * 16;
        size_t ao = (size_t)(row0 + crow) * 1024 + it * 32 + cch * 8;
        size_t bo = (size_t)(col0 + crow) * 1024 + it * 32 + cch * 8;
        cpa16(base,                  g_Xh + ao);
        cpa16(base + 64 * 80,        g_Xh + ao + 64 * 1024);
        cpa16(base + GARR,           g_Wh + bo);
        cpa16(base + GARR + 64 * 80, g_Wh + bo + 64 * 1024);
        CP_COMMIT();
    };

    const int a_roff = (lane & 7) + ((lane >> 3) & 1) * 8;
    const int a_koff = (lane >> 4) * 8;
    const int b_roff = (lane & 7) + (lane >> 4) * 8;
    const int b_koff = ((lane >> 3) & 1) * 8;

    auto mmaStage = [&](int st) {
        uint32_t s0 = sb + st * HSTAGE;
#pragma unroll
        for (int ks = 0; ks < 2; ++ks) {
            unsigned ah[4][4], bh[2][4];
#pragma unroll
            for (int mt = 0; mt < 4; ++mt) {
                uint32_t ad = s0 + (wm * 64 + mt * 16 + a_roff) * 80 + (ks * 16 + a_koff) * 2;
                ldsm4(ah[mt], ad);
            }
#pragma unroll
            for (int np = 0; np < 2; ++np) {
                uint32_t bd = s0 + GARR + (wn * 32 + np * 16 + b_roff) * 80 + (ks * 16 + b_koff) * 2;
                ldsm4(bh[np], bd);
            }
#pragma unroll
            for (int mt = 0; mt < 4; ++mt)
#pragma unroll
                for (int nt = 0; nt < 4; ++nt) {
                    int np = nt >> 1, sl = (nt & 1) * 2;
                    mma16f(c[mt][nt], ah[mt], &bh[np][sl]);
                }
        }
    };

    issueStage(0);
    issueStage(1);
    for (int it = 0; it < 32; ++it) {
        if (it < 31) { CP_WAIT(1); } else { CP_WAIT(0); }
        __syncthreads();
        if (it + 2 < 32) issueStage(it + 2);
        mmaStage(it % 3);
    }

#pragma unroll
    for (int mt = 0; mt < 4; ++mt)
#pragma unroll
        for (int nt = 0; nt < 4; ++nt) {
            int col = col0 + wn * 32 + nt * 8 + 2 * t;
            float b0 = bias[col], b1 = bias[col + 1];
#pragma unroll
            for (int h2 = 0; h2 < 2; ++h2) {
                int rr = row0 + wm * 64 + mt * 16 + g + h2 * 8;
                float v0 = c[mt][nt][h2 * 2 + 0] + b0;
                float v1 = c[mt][nt][h2 * 2 + 1] + b1;
                if (MODE == 0) {
                    int b = rr >> 11, s = rr & 2047, hh = col >> 6;
                    size_t idx = (((size_t)(b * H_ + hh) * S_) + s) * 64 + (col & 63);
                    *(unsigned*)&outh[idx] = pack2h(v0, v1);
                } else {
                    *(float2*)(outf + (size_t)rr * 1024 + col) = make_float2(v0, v1);
                }
            }
        }
}

// ---------------------------------------------------------------------------
// Flash attention: S = QK^T in bf16x3, PV in fp16 1-term (P single, V single).
// Q-tile 128, KV-tile 64, 2-stage cp.async {Kh,Kl,Vh}.
// Epilogue writes Z as single fp16 into g_Xh for the out-proj.
// ---------------------------------------------------------------------------
#define AARR  9216
#define ASTG  (3*AARR)
#define ASMT  (2*ASTG)

__global__ __launch_bounds__(256)
void attn_bf()
{
    extern __shared__ char smem[];
    const uint32_t sb = smem_u32(smem);

    const int tid  = threadIdx.x;
    const int lane = tid & 31, warp = tid >> 5;
    const int g    = lane >> 2, t = lane & 3;
    const int bh   = blockIdx.y, b = bh >> 4, h = bh & 15;
    const int q0   = blockIdx.x * 128;

    const size_t bhOff = (size_t)bh * S_ * 64;
    const __nv_bfloat16* Qph = g_Qh + bhOff + (size_t)q0 * 64;
    const __nv_bfloat16* Qpl = g_Ql + bhOff + (size_t)q0 * 64;

    unsigned qfh[4][4], qfl[4][4];
#pragma unroll
    for (int ks = 0; ks < 4; ++ks)
#pragma unroll
        for (int r2 = 0; r2 < 4; ++r2) {
            int row = warp * 16 + (r2 & 1) * 8 + g;
            int d   = ks * 16 + (t + (r2 >> 1) * 4) * 2;
            qfh[ks][r2] = *(const unsigned*)(Qph + (size_t)row * 64 + d);
            qfl[ks][r2] = *(const unsigned*)(Qpl + (size_t)row * 64 + d);
        }

    float o[8][4];
#pragma unroll
    for (int nt = 0; nt < 8; ++nt)
#pragma unroll
        for (int q = 0; q < 4; ++q) o[nt][q] = 0.f;
    float mrow[2] = {-1e30f, -1e30f};
    float lrow[2] = {0.f, 0.f};

    const int krow = tid >> 3, kch = tid & 7;
    const int b_roff = (lane & 7) + (lane >> 4) * 8;
    const int b_koff = ((lane >> 3) & 1) * 8;
    const int v_roff = (lane & 7) + ((lane >> 3) & 1) * 8;
    const int v_coff = (lane >> 4) * 8;

    auto issueKV = [&](int tkv) {
        uint32_t base = sb + (tkv & 1) * ASTG + krow * 144 + kch * 16;
#pragma unroll
        for (int i = 0; i < 2; ++i) {
            size_t src = bhOff + (size_t)(tkv * 64 + krow + 32 * i) * 64 + kch * 8;
            uint32_t d = base + i * 32 * 144;
            cpa16(d,            g_Kh + src);
            cpa16(d + AARR,     g_Kl + src);
            cpa16(d + 2 * AARR, g_Vh + src);
        }
        CP_COMMIT();
    };

    issueKV(0);
    for (int tkv = 0; tkv < S_ / 64; ++tkv) {
        if (tkv + 1 < S_ / 64) {
            issueKV(tkv + 1);
            CP_WAIT(1);
        } else {
            CP_WAIT(0);
        }
        __syncthreads();

        uint32_t s0 = sb + (tkv & 1) * ASTG;

        // ---- S = Q K^T, bf16x3, term-major ----
        float s[8][4];
#pragma unroll
        for (int j = 0; j < 8; ++j)
#pragma unroll
            for (int q = 0; q < 4; ++q) s[j][q] = 0.f;
#pragma unroll
        for (int ks = 0; ks < 4; ++ks) {
            unsigned kb[4][4], klo[4][4];
#pragma unroll
            for (int jp = 0; jp < 4; ++jp) {
                uint32_t off = s0 + ((jp * 16 + b_roff) * 72 + ks * 16 + b_koff) * 2;
                ldsm4(kb[jp],  off);
                ldsm4(klo[jp], off + AARR);
            }
#pragma unroll
            for (int jp = 0; jp < 4; ++jp) {
                mma16(s[2 * jp],     qfh[ks], &kb[jp][0]);
                mma16(s[2 * jp + 1], qfh[ks], &kb[jp][2]);
            }
#pragma unroll
            for (int jp = 0; jp < 4; ++jp) {
                mma16(s[2 * jp],     qfh[ks], &klo[jp][0]);
                mma16(s[2 * jp + 1], qfh[ks], &klo[jp][2]);
            }
#pragma unroll
            for (int jp = 0; jp < 4; ++jp) {
                mma16(s[2 * jp],     qfl[ks], &kb[jp][0]);
                mma16(s[2 * jp + 1], qfl[ks], &kb[jp][2]);
            }
        }

        // ---- online softmax (rows g, g+8) ----
#pragma unroll
        for (int h2 = 0; h2 < 2; ++h2) {
            float mx = -1e30f;
#pragma unroll
            for (int j = 0; j < 8; ++j)
                mx = fmaxf(mx, fmaxf(s[j][h2 * 2], s[j][h2 * 2 + 1]));
            mx = fmaxf(mx, __shfl_xor_sync(0xffffffffu, mx, 1));
            mx = fmaxf(mx, __shfl_xor_sync(0xffffffffu, mx, 2));
            float mn   = fmaxf(mrow[h2], mx);
            float corr = __expf(mrow[h2] - mn);
            mrow[h2] = mn;
            float rs = 0.f;
#pragma unroll
            for (int j = 0; j < 8; ++j) {
                float p0 = __expf(s[j][h2 * 2] - mn);
                float p1 = __expf(s[j][h2 * 2 + 1] - mn);
                s[j][h2 * 2] = p0; s[j][h2 * 2 + 1] = p1;
                rs += p0 + p1;
            }
            rs += __shfl_xor_sync(0xffffffffu, rs, 1);
            rs += __shfl_xor_sync(0xffffffffu, rs, 2);
            lrow[h2] = lrow[h2] * corr + rs;
            if (corr != 1.f) {
#pragma unroll
                for (int nt = 0; nt < 8; ++nt) {
                    o[nt][h2 * 2]     *= corr;
                    o[nt][h2 * 2 + 1] *= corr;
                }
            }
        }

        // ---- P: C-frag -> A-frag, single fp16 ----
        unsigned pf[4][4];
#pragma unroll
        for (int j = 0; j < 8; ++j) {
            int ks = j >> 1, i0 = (j & 1) * 2;
            pf[ks][i0]     = pack2h(s[j][0], s[j][1]);
            pf[ks][i0 + 1] = pack2h(s[j][2], s[j][3]);
        }

        // ---- O += P V, fp16 1-term ----
#pragma unroll
        for (int ks = 0; ks < 4; ++ks) {
            unsigned vb[4][4];
#pragma unroll
            for (int np = 0; np < 4; ++np) {
                uint32_t off = s0 + 2 * AARR + ((ks * 16 + v_roff) * 72 + np * 16 + v_coff) * 2;
                ldsm4t(vb[np], off);
            }
#pragma unroll
            for (int np = 0; np < 4; ++np) {
                mma16f(o[2 * np],     pf[ks], &vb[np][0]);
                mma16f(o[2 * np + 1], pf[ks], &vb[np][2]);
            }
        }
        __syncthreads();
    }

    // ---- normalize + write Z single fp16 into g_Xh [b*S+s][h*64+dv] ----
    float inv0 = 1.f / lrow[0], inv1 = 1.f / lrow[1];
    int qrow = q0 + warp * 16 + g;
#pragma unroll
    for (int nt = 0; nt < 8; ++nt) {
        int col = h * 64 + nt * 8 + 2 * t;
        size_t i0 = (size_t)(b * S_ + qrow) * 1024 + col;
        *(unsigned*)&g_Xh[i0] = pack2h(o[nt][0] * inv0, o[nt][1] * inv0);
        size_t i1 = (size_t)(b * S_ + qrow + 8) * 1024 + col;
        *(unsigned*)&g_Xh[i1] = pack2h(o[nt][2] * inv1, o[nt][3] * inv1);
    }
}

// ---------------------------------------------------------------------------
extern "C" void kernel_launch(void* const* d_in, const int* in_sizes, int n_in,
                              void* d_out, int out_size)
{
    const float* in_q = (const float*)d_in[0];
    const float* in_k = (const float*)d_in[1];
    const float* in_v = (const float*)d_in[2];
    const float* Wq   = (const float*)d_in[3];
    const float* bq   = (const float*)d_in[4];
    const float* Wk   = (const float*)d_in[5];
    const float* bk   = (const float*)d_in[6];
    const float* Wv   = (const float*)d_in[7];
    const float* bv   = (const float*)d_in[8];
    const float* Wo   = (const float*)d_in[9];
    const float* bo   = (const float*)d_in[10];
    float* out = (float*)d_out;

    __nv_bfloat16 *qh, *ql, *kh, *kl, *vh;
    cudaGetSymbolAddress((void**)&qh, g_Qh);
    cudaGetSymbolAddress((void**)&ql, g_Ql);
    cudaGetSymbolAddress((void**)&kh, g_Kh);
    cudaGetSymbolAddress((void**)&kl, g_Kl);
    cudaGetSymbolAddress((void**)&vh, g_Vh);

    cudaFuncSetAttribute(gemm_bf,    cudaFuncAttributeMaxDynamicSharedMemorySize, GSMTOT);
    cudaFuncSetAttribute(gemm_hf<0>, cudaFuncAttributeMaxDynamicSharedMemorySize, HSMTOT);
    cudaFuncSetAttribute(gemm_hf<1>, cudaFuncAttributeMaxDynamicSharedMemorySize, HSMTOT);
    cudaFuncSetAttribute(attn_bf,    cudaFuncAttributeMaxDynamicSharedMemorySize, ASMT);

    dim3 tb(256);
    dim3 gg(8, 64);                       // 128x128 tiles over [8192 x 1024]
    dim3 gwP(16, 1, 16);                  // proj weights [16][1024][64]
    dim3 gwO(16, 16, 1);                  // Wo [1024][1024]
    const int SX = (M_ * D_ / 4) / 256;

    // Q projection (bf16x3)
    split_w<<<gwP, tb>>>(Wq, 64);
    split_x<<<SX, tb>>>(in_q);
    gemm_bf<<<gg, tb, GSMTOT>>>(bq, qh, ql);

    // K projection (bf16x3)
    split_w<<<gwP, tb>>>(Wk, 64);
    split_x<<<SX, tb>>>(in_k);
    gemm_bf<<<gg, tb, GSMTOT>>>(bk, kh, kl);

    // V projection (fp16 1-term)
    split_wh<<<gwP, tb>>>(Wv, 64);
    split_xh<<<SX, tb>>>(in_v);
    gemm_hf<0><<<gg, tb, HSMTOT>>>(bv, nullptr, vh);

    // attention (S bf16x3, PV fp16 1-term)
    attn_bf<<<dim3(S_ / 128, B_ * H_), tb, ASMT>>>();

    // output projection (fp16 1-term)
    split_wh<<<gwO, tb>>>(Wo, 1024);
    gemm_hf<1><<<gg, tb, HSMTOT>>>(bo, out, nullptr);
}

// round 14
// speedup vs baseline: 3.6671x; 1.0995x over previous
#include <cuda_runtime.h>
#include <cuda_bf16.h>
#include <cuda_fp16.h>
#include <cstdint>

#define B_  4
#define S_  2048
#define D_  1024
#define H_  16
#define M_  (B_*S_)

// ---------------- scratch (static device memory only) ----------------------
// Raw 16-bit storage; interpreted as bf16 or fp16 per stage.
__device__ __nv_bfloat16 g_Xh[(size_t)M_*D_]; // A operand (X or Z) hi
__device__ __nv_bfloat16 g_Xl[(size_t)M_*D_];
__device__ __nv_bfloat16 g_Wh[(size_t)D_*D_]; // B operand hi, [n][k]
__device__ __nv_bfloat16 g_Wl[(size_t)D_*D_];
__device__ __nv_bfloat16 g_Qh[(size_t)M_*D_]; // [b,h,s,64] fp16 hi/lo
__device__ __nv_bfloat16 g_Ql[(size_t)M_*D_];
__device__ __nv_bfloat16 g_Kh[(size_t)M_*D_]; // fp16 single
__device__ __nv_bfloat16 g_Vh[(size_t)M_*D_]; // fp16 single

// ---------------- helpers ----------------------------------------------
__device__ __forceinline__ uint32_t smem_u32(const void* p) {
    uint32_t a;
    asm("{ .reg .u64 t; cvta.to.shared.u64 t, %1; cvt.u32.u64 %0, t; }" : "=r"(a) : "l"(p));
    return a;
}
__device__ __forceinline__ void cpa16(uint32_t dst, const void* src) {
    asm volatile("cp.async.cg.shared.global [%0], [%1], 16;" :: "r"(dst), "l"(src));
}
#define CP_COMMIT() asm volatile("cp.async.commit_group;" ::: "memory")
#define CP_WAIT(n)  asm volatile("cp.async.wait_group %0;" :: "n"(n) : "memory")

// bf16 hi/lo split (low half = x0)
__device__ __forceinline__ void split2(float x0, float x1, unsigned& hi, unsigned& lo) {
    unsigned h;
    asm("cvt.rn.bf16x2.f32 %0, %1, %2;" : "=r"(h) : "f"(x1), "f"(x0));
    __nv_bfloat162 hb = *reinterpret_cast<__nv_bfloat162*>(&h);
    float h0 = __bfloat162float(hb.x);
    float h1 = __bfloat162float(hb.y);
    hi = h;
    asm("cvt.rn.bf16x2.f32 %0, %1, %2;" : "=r"(lo) : "f"(x1 - h1), "f"(x0 - h0));
}
// fp16 hi/lo split (low half = x0)
__device__ __forceinline__ void split2h(float x0, float x1, unsigned& hi, unsigned& lo) {
    __half2 h = __floats2half2_rn(x0, x1);
    float h0 = __low2float(h), h1 = __high2float(h);
    hi = *reinterpret_cast<unsigned*>(&h);
    __half2 l = __floats2half2_rn(x0 - h0, x1 - h1);
    lo = *reinterpret_cast<unsigned*>(&l);
}
__device__ __forceinline__ unsigned pack2h(float x0, float x1) {
    __half2 h = __floats2half2_rn(x0, x1);
    return *reinterpret_cast<unsigned*>(&h);
}
__device__ __forceinline__ void mma16(float* c, const unsigned* a, const unsigned* b) {
    asm("mma.sync.aligned.m16n8k16.row.col.f32.bf16.bf16.f32 "
        "{%0,%1,%2,%3},{%4,%5,%6,%7},{%8,%9},{%0,%1,%2,%3};"
        : "+f"(c[0]), "+f"(c[1]), "+f"(c[2]), "+f"(c[3])
        : "r"(a[0]), "r"(a[1]), "r"(a[2]), "r"(a[3]), "r"(b[0]), "r"(b[1]));
}
__device__ __forceinline__ void mma16f(float* c, const unsigned* a, const unsigned* b) {
    asm("mma.sync.aligned.m16n8k16.row.col.f32.f16.f16.f32 "
        "{%0,%1,%2,%3},{%4,%5,%6,%7},{%8,%9},{%0,%1,%2,%3};"
        : "+f"(c[0]), "+f"(c[1]), "+f"(c[2]), "+f"(c[3])
        : "r"(a[0]), "r"(a[1]), "r"(a[2]), "r"(a[3]), "r"(b[0]), "r"(b[1]));
}
__device__ __forceinline__ void ldsm4(unsigned* r, uint32_t a) {
    asm volatile("ldmatrix.sync.aligned.m8n8.x4.shared.b16 {%0,%1,%2,%3}, [%4];"
        : "=r"(r[0]), "=r"(r[1]), "=r"(r[2]), "=r"(r[3]) : "r"(a));
}
__device__ __forceinline__ void ldsm4t(unsigned* r, uint32_t a) {
    asm volatile("ldmatrix.sync.aligned.m8n8.x4.trans.shared.b16 {%0,%1,%2,%3}, [%4];"
        : "=r"(r[0]), "=r"(r[1]), "=r"(r[2]), "=r"(r[3]) : "r"(a));
}

// ---------------------------------------------------------------------------
// split kernels
// ---------------------------------------------------------------------------
__global__ __launch_bounds__(256) void split_x(const float* __restrict__ src) {
    size_t gid = (size_t)blockIdx.x * 256 + threadIdx.x;
    float4 v = *(const float4*)(src + gid * 4);
    unsigned h0, l0, h1, l1;
    split2(v.x, v.y, h0, l0);
    split2(v.z, v.w, h1, l1);
    *(uint2*)(g_Xh + gid * 4) = make_uint2(h0, h1);
    *(uint2*)(g_Xl + gid * 4) = make_uint2(l0, l1);
}
// single fp16 pack (direct paths)
__global__ __launch_bounds__(256) void split_xh(const float* __restrict__ src) {
    size_t gid = (size_t)blockIdx.x * 256 + threadIdx.x;
    float4 v = *(const float4*)(src + gid * 4);
    *(uint2*)(g_Xh + gid * 4) = make_uint2(pack2h(v.x, v.y), pack2h(v.z, v.w));
}
// bf16 hi/lo weight transpose: W[g][k][c] -> g_Wh/g_Wl [n=g*Cw+c][k]
__global__ __launch_bounds__(256) void split_w(const float* __restrict__ W, int Cw) {
    __shared__ float s[64][65];
    const int tid = threadIdx.x;
    const int k0 = blockIdx.x * 64, c0 = blockIdx.y * 64, g = blockIdx.z;
    const float* src = W + ((size_t)g * 1024 + k0) * Cw + c0;
    {
        int lc = tid & 63, kb = tid >> 6;
#pragma unroll
        for (int i = 0; i < 16; ++i) {
            int lk = kb + 4 * i;
            s[lk][lc] = src[(size_t)lk * Cw + lc];
        }
    }
    __syncthreads();
    {
        int k2 = (tid & 31) * 2, cb = tid >> 5;
#pragma unroll
        for (int i = 0; i < 8; ++i) {
            int lc = cb + 8 * i;
            unsigned hi, lo;
            split2(s[k2][lc], s[k2 + 1][lc], hi, lo);
            size_t idx = (size_t)(g * Cw + c0 + lc) * 1024 + k0 + k2;
            *(unsigned*)&g_Wh[idx] = hi;
            *(unsigned*)&g_Wl[idx] = lo;
        }
    }
}
// fp16 single weight transpose -> g_Wh only
__global__ __launch_bounds__(256) void split_wh(const float* __restrict__ W, int Cw) {
    __shared__ float s[64][65];
    const int tid = threadIdx.x;
    const int k0 = blockIdx.x * 64, c0 = blockIdx.y * 64, g = blockIdx.z;
    const float* src = W + ((size_t)g * 1024 + k0) * Cw + c0;
    {
        int lc = tid & 63, kb = tid >> 6;
#pragma unroll
        for (int i = 0; i < 16; ++i) {
            int lk = kb + 4 * i;
            s[lk][lc] = src[(size_t)lk * Cw + lc];
        }
    }
    __syncthreads();
    {
        int k2 = (tid & 31) * 2, cb = tid >> 5;
#pragma unroll
        for (int i = 0; i < 8; ++i) {
            int lc = cb + 8 * i;
            size_t idx = (size_t)(g * Cw + c0 + lc) * 1024 + k0 + k2;
            *(unsigned*)&g_Wh[idx] = pack2h(s[k2][lc], s[k2 + 1][lc]);
        }
    }
}

// ---------------------------------------------------------------------------
// bf16x3 GEMM (score path: Q/K projections). 128x128 tile, BK=32, 3-stage.
// QMODE 0: epilogue splits to fp16 hi/lo (Q). QMODE 1: single fp16 (K).
// ---------------------------------------------------------------------------
#define GARR   10240
#define GSTAGE 40960
#define GSMTOT (3*GSTAGE)

template<int QMODE>
__global__ __launch_bounds__(256)
void gemm_bf(const float* __restrict__ bias,
             __nv_bfloat16* __restrict__ outh, __nv_bfloat16* __restrict__ outl)
{
    extern __shared__ char smem[];
    const uint32_t sb = smem_u32(smem);
    const int tid = threadIdx.x, lane = tid & 31, warp = tid >> 5;
    const int wm = warp >> 2, wn = warp & 3;
    const int row0 = blockIdx.y * 128, col0 = blockIdx.x * 128;
    const int g = lane >> 2, t = lane & 3;
    const int crow = tid >> 2, cch = tid & 3;

    float c[4][4][4];
#pragma unroll
    for (int i = 0; i < 4; ++i)
#pragma unroll
        for (int j = 0; j < 4; ++j)
#pragma unroll
            for (int q = 0; q < 4; ++q) c[i][j][q] = 0.f;

    auto issueStage = [&](int it) {
        uint32_t base = sb + (it % 3) * GSTAGE + crow * 80 + cch * 16;
        size_t ao = (size_t)(row0 + crow) * 1024 + it * 32 + cch * 8;
        size_t bo = (size_t)(col0 + crow) * 1024 + it * 32 + cch * 8;
        cpa16(base,                      g_Xh + ao);
        cpa16(base + 64 * 80,            g_Xh + ao + 64 * 1024);
        cpa16(base + GARR,               g_Xl + ao);
        cpa16(base + GARR + 64 * 80,     g_Xl + ao + 64 * 1024);
        cpa16(base + 2 * GARR,           g_Wh + bo);
        cpa16(base + 2 * GARR + 64 * 80, g_Wh + bo + 64 * 1024);
        cpa16(base + 3 * GARR,           g_Wl + bo);
        cpa16(base + 3 * GARR + 64 * 80, g_Wl + bo + 64 * 1024);
        CP_COMMIT();
    };

    const int a_roff = (lane & 7) + ((lane >> 3) & 1) * 8;
    const int a_koff = (lane >> 4) * 8;
    const int b_roff = (lane & 7) + (lane >> 4) * 8;
    const int b_koff = ((lane >> 3) & 1) * 8;

    auto mmaStage = [&](int st) {
        uint32_t s0 = sb + st * GSTAGE;
#pragma unroll
        for (int ks = 0; ks < 2; ++ks) {
            unsigned ah[4][4], al[4][4], bh[2][4], bl[2][4];
#pragma unroll
            for (int mt = 0; mt < 4; ++mt) {
                uint32_t ad = s0 + (wm * 64 + mt * 16 + a_roff) * 80 + (ks * 16 + a_koff) * 2;
                ldsm4(ah[mt], ad);
                ldsm4(al[mt], ad + GARR);
            }
#pragma unroll
            for (int np = 0; np < 2; ++np) {
                uint32_t bd = s0 + 2 * GARR + (wn * 32 + np * 16 + b_roff) * 80 + (ks * 16 + b_koff) * 2;
                ldsm4(bh[np], bd);
                ldsm4(bl[np], bd + GARR);
            }
#pragma unroll
            for (int mt = 0; mt < 4; ++mt)
#pragma unroll
                for (int nt = 0; nt < 4; ++nt) {
                    int np = nt >> 1, sl = (nt & 1) * 2;
                    mma16(c[mt][nt], ah[mt], &bh[np][sl]);
                }
#pragma unroll
            for (int mt = 0; mt < 4; ++mt)
#pragma unroll
                for (int nt = 0; nt < 4; ++nt) {
                    int np = nt >> 1, sl = (nt & 1) * 2;
                    mma16(c[mt][nt], ah[mt], &bl[np][sl]);
                }
#pragma unroll
            for (int mt = 0; mt < 4; ++mt)
#pragma unroll
                for (int nt = 0; nt < 4; ++nt) {
                    int np = nt >> 1, sl = (nt & 1) * 2;
                    mma16(c[mt][nt], al[mt], &bh[np][sl]);
                }
        }
    };

    issueStage(0);
    issueStage(1);
    for (int it = 0; it < 32; ++it) {
        if (it < 31) { CP_WAIT(1); } else { CP_WAIT(0); }
        __syncthreads();
        if (it + 2 < 32) issueStage(it + 2);
        mmaStage(it % 3);
    }

#pragma unroll
    for (int mt = 0; mt < 4; ++mt)
#pragma unroll
        for (int nt = 0; nt < 4; ++nt) {
            int col = col0 + wn * 32 + nt * 8 + 2 * t;
            float b0 = bias[col], b1 = bias[col + 1];
#pragma unroll
            for (int h2 = 0; h2 < 2; ++h2) {
                int rr = row0 + wm * 64 + mt * 16 + g + h2 * 8;
                float v0 = c[mt][nt][h2 * 2 + 0] + b0;
                float v1 = c[mt][nt][h2 * 2 + 1] + b1;
                int b = rr >> 11, s = rr & 2047, hh = col >> 6;
                size_t idx = (((size_t)(b * H_ + hh) * S_) + s) * 64 + (col & 63);
                if (QMODE == 0) {
                    unsigned hi, lo;
                    split2h(v0, v1, hi, lo);
                    *(unsigned*)&outh[idx] = hi;
                    *(unsigned*)&outl[idx] = lo;
                } else {
                    *(unsigned*)&outh[idx] = pack2h(v0, v1);
                }
            }
        }
}

// ---------------------------------------------------------------------------
// fp16 1-term GEMM (direct paths: V-proj, out-proj). A = fp16 single in g_Xh,
// B = fp16 single in g_Wh. 128x128 tile, BK=32, 3-stage.
// MODE 0: bias + fp16 -> [b,h,s,k] single. MODE 1: bias -> f32 row-major.
// ---------------------------------------------------------------------------
#define HSTAGE (2*GARR)
#define HSMTOT (3*HSTAGE)

template<int MODE>
__global__ __launch_bounds__(256)
void gemm_hf(const float* __restrict__ bias, float* __restrict__ outf,
             __nv_bfloat16* __restrict__ outh)
{
    extern __shared__ char smem[];
    const uint32_t sb = smem_u32(smem);
    const int tid = threadIdx.x, lane = tid & 31, warp = tid >> 5;
    const int wm = warp >> 2, wn = warp & 3;
    const int row0 = blockIdx.y * 128, col0 = blockIdx.x * 128;
    const int g = lane >> 2, t = lane & 3;
    const int crow = tid >> 2, cch = tid & 3;

    float c[4][4][4];
#pragma unroll
    for (int i = 0; i < 4; ++i)
#pragma unroll
        for (int j = 0; j < 4; ++j)
#pragma unroll
            for (int q = 0; q < 4; ++q) c[i][j][q] = 0.f;

    auto issueStage = [&](int it) {
        uint32_t base = sb + (it % 3) * HSTAGE + crow * 80 + cch * 16;
        size_t ao = (size_t)(row0 + crow) * 1024 + it * 32 + cch * 8;
        size_t bo = (size_t)(col0 + crow) * 1024 + it * 32 + cch * 8;
        cpa16(base,                  g_Xh + ao);
        cpa16(base + 64 * 80,        g_Xh + ao + 64 * 1024);
        cpa16(base + GARR,           g_Wh + bo);
        cpa16(base + GARR + 64 * 80, g_Wh + bo + 64 * 1024);
        CP_COMMIT();
    };

    const int a_roff = (lane & 7) + ((lane >> 3) & 1) * 8;
    const int a_koff = (lane >> 4) * 8;
    const int b_roff = (lane & 7) + (lane >> 4) * 8;
    const int b_koff = ((lane >> 3) & 1) * 8;

    auto mmaStage = [&](int st) {
        uint32_t s0 = sb + st * HSTAGE;
#pragma unroll
        for (int ks = 0; ks < 2; ++ks) {
            unsigned ah[4][4], bh[2][4];
#pragma unroll
            for (int mt = 0; mt < 4; ++mt) {
                uint32_t ad = s0 + (wm * 64 + mt * 16 + a_roff) * 80 + (ks * 16 + a_koff) * 2;
                ldsm4(ah[mt], ad);
            }
#pragma unroll
            for (int np = 0; np < 2; ++np) {
                uint32_t bd = s0 + GARR + (wn * 32 + np * 16 + b_roff) * 80 + (ks * 16 + b_koff) * 2;
                ldsm4(bh[np], bd);
            }
#pragma unroll
            for (int mt = 0; mt < 4; ++mt)
#pragma unroll
                for (int nt = 0; nt < 4; ++nt) {
                    int np = nt >> 1, sl = (nt & 1) * 2;
                    mma16f(c[mt][nt], ah[mt], &bh[np][sl]);
                }
        }
    };

    issueStage(0);
    issueStage(1);
    for (int it = 0; it < 32; ++it) {
        if (it < 31) { CP_WAIT(1); } else { CP_WAIT(0); }
        __syncthreads();
        if (it + 2 < 32) issueStage(it + 2);
        mmaStage(it % 3);
    }

#pragma unroll
    for (int mt = 0; mt < 4; ++mt)
#pragma unroll
        for (int nt = 0; nt < 4; ++nt) {
            int col = col0 + wn * 32 + nt * 8 + 2 * t;
            float b0 = bias[col], b1 = bias[col + 1];
#pragma unroll
            for (int h2 = 0; h2 < 2; ++h2) {
                int rr = row0 + wm * 64 + mt * 16 + g + h2 * 8;
                float v0 = c[mt][nt][h2 * 2 + 0] + b0;
                float v1 = c[mt][nt][h2 * 2 + 1] + b1;
                if (MODE == 0) {
                    int b = rr >> 11, s = rr & 2047, hh = col >> 6;
                    size_t idx = (((size_t)(b * H_ + hh) * S_) + s) * 64 + (col & 63);
                    *(unsigned*)&outh[idx] = pack2h(v0, v1);
                } else {
                    *(float2*)(outf + (size_t)rr * 1024 + col) = make_float2(v0, v1);
                }
            }
        }
}

// ---------------------------------------------------------------------------
// Flash attention: S = QK^T fp16 2-term (Q hi/lo fp16, K single fp16),
// PV fp16 1-term. Q-tile 128, KV-tile 64, 2-stage cp.async {Kh,Vh}.
// Epilogue writes Z as single fp16 into g_Xh for the out-proj.
// ---------------------------------------------------------------------------
#define AARR  9216
#define ASTG  (2*AARR)
#define ASMT  (2*ASTG)

__global__ __launch_bounds__(256)
void attn_bf()
{
    extern __shared__ char smem[];
    const uint32_t sb = smem_u32(smem);

    const int tid  = threadIdx.x;
    const int lane = tid & 31, warp = tid >> 5;
    const int g    = lane >> 2, t = lane & 3;
    const int bh   = blockIdx.y, b = bh >> 4, h = bh & 15;
    const int q0   = blockIdx.x * 128;

    const size_t bhOff = (size_t)bh * S_ * 64;
    const __nv_bfloat16* Qph = g_Qh + bhOff + (size_t)q0 * 64;
    const __nv_bfloat16* Qpl = g_Ql + bhOff + (size_t)q0 * 64;

    unsigned qfh[4][4], qfl[4][4];
#pragma unroll
    for (int ks = 0; ks < 4; ++ks)
#pragma unroll
        for (int r2 = 0; r2 < 4; ++r2) {
            int row = warp * 16 + (r2 & 1) * 8 + g;
            int d   = ks * 16 + (t + (r2 >> 1) * 4) * 2;
            qfh[ks][r2] = *(const unsigned*)(Qph + (size_t)row * 64 + d);
            qfl[ks][r2] = *(const unsigned*)(Qpl + (size_t)row * 64 + d);
        }

    float o[8][4];
#pragma unroll
    for (int nt = 0; nt < 8; ++nt)
#pragma unroll
        for (int q = 0; q < 4; ++q) o[nt][q] = 0.f;
    float mrow[2] = {-1e30f, -1e30f};
    float lrow[2] = {0.f, 0.f};

    const int krow = tid >> 3, kch = tid & 7;
    const int b_roff = (lane & 7) + (lane >> 4) * 8;
    const int b_koff = ((lane >> 3) & 1) * 8;
    const int v_roff = (lane & 7) + ((lane >> 3) & 1) * 8;
    const int v_coff = (lane >> 4) * 8;

    auto issueKV = [&](int tkv) {
        uint32_t base = sb + (tkv & 1) * ASTG + krow * 144 + kch * 16;
#pragma unroll
        for (int i = 0; i < 2; ++i) {
            size_t src = bhOff + (size_t)(tkv * 64 + krow + 32 * i) * 64 + kch * 8;
            uint32_t d = base + i * 32 * 144;
            cpa16(d,        g_Kh + src);
            cpa16(d + AARR, g_Vh + src);
        }
        CP_COMMIT();
    };

    issueKV(0);
    for (int tkv = 0; tkv < S_ / 64; ++tkv) {
        if (tkv + 1 < S_ / 64) {
            issueKV(tkv + 1);
            CP_WAIT(1);
        } else {
            CP_WAIT(0);
        }
        __syncthreads();

        uint32_t s0 = sb + (tkv & 1) * ASTG;

        // ---- S = Q K^T, fp16 2-term, term-major ----
        float s[8][4];
#pragma unroll
        for (int j = 0; j < 8; ++j)
#pragma unroll
            for (int q = 0; q < 4; ++q) s[j][q] = 0.f;
#pragma unroll
        for (int ks = 0; ks < 4; ++ks) {
            unsigned kb[4][4];
#pragma unroll
            for (int jp = 0; jp < 4; ++jp) {
                uint32_t off = s0 + ((jp * 16 + b_roff) * 72 + ks * 16 + b_koff) * 2;
                ldsm4(kb[jp], off);
            }
#pragma unroll
            for (int jp = 0; jp < 4; ++jp) {
                mma16f(s[2 * jp],     qfh[ks], &kb[jp][0]);
                mma16f(s[2 * jp + 1], qfh[ks], &kb[jp][2]);
            }
#pragma unroll
            for (int jp = 0; jp < 4; ++jp) {
                mma16f(s[2 * jp],     qfl[ks], &kb[jp][0]);
                mma16f(s[2 * jp + 1], qfl[ks], &kb[jp][2]);
            }
        }

        // ---- online softmax (rows g, g+8) ----
#pragma unroll
        for (int h2 = 0; h2 < 2; ++h2) {
            float mx = -1e30f;
#pragma unroll
            for (int j = 0; j < 8; ++j)
                mx = fmaxf(mx, fmaxf(s[j][h2 * 2], s[j][h2 * 2 + 1]));
            mx = fmaxf(mx, __shfl_xor_sync(0xffffffffu, mx, 1));
            mx = fmaxf(mx, __shfl_xor_sync(0xffffffffu, mx, 2));
            float mn   = fmaxf(mrow[h2], mx);
            float corr = __expf(mrow[h2] - mn);
            mrow[h2] = mn;
            float rs = 0.f;
#pragma unroll
            for (int j = 0; j < 8; ++j) {
                float p0 = __expf(s[j][h2 * 2] - mn);
                float p1 = __expf(s[j][h2 * 2 + 1] - mn);
                s[j][h2 * 2] = p0; s[j][h2 * 2 + 1] = p1;
                rs += p0 + p1;
            }
            rs += __shfl_xor_sync(0xffffffffu, rs, 1);
            rs += __shfl_xor_sync(0xffffffffu, rs, 2);
            lrow[h2] = lrow[h2] * corr + rs;
            if (corr != 1.f) {
#pragma unroll
                for (int nt = 0; nt < 8; ++nt) {
                    o[nt][h2 * 2]     *= corr;
                    o[nt][h2 * 2 + 1] *= corr;
                }
            }
        }

        // ---- P: C-frag -> A-frag, single fp16 ----
        unsigned pf[4][4];
#pragma unroll
        for (int j = 0; j < 8; ++j) {
            int ks = j >> 1, i0 = (j & 1) * 2;
            pf[ks][i0]     = pack2h(s[j][0], s[j][1]);
            pf[ks][i0 + 1] = pack2h(s[j][2], s[j][3]);
        }

        // ---- O += P V, fp16 1-term ----
#pragma unroll
        for (int ks = 0; ks < 4; ++ks) {
            unsigned vb[4][4];
#pragma unroll
            for (int np = 0; np < 4; ++np) {
                uint32_t off = s0 + AARR + ((ks * 16 + v_roff) * 72 + np * 16 + v_coff) * 2;
                ldsm4t(vb[np], off);
            }
#pragma unroll
            for (int np = 0; np < 4; ++np) {
                mma16f(o[2 * np],     pf[ks], &vb[np][0]);
                mma16f(o[2 * np + 1], pf[ks], &vb[np][2]);
            }
        }
        __syncthreads();
    }

    // ---- normalize + write Z single fp16 into g_Xh [b*S+s][h*64+dv] ----
    float inv0 = 1.f / lrow[0], inv1 = 1.f / lrow[1];
    int qrow = q0 + warp * 16 + g;
#pragma unroll
    for (int nt = 0; nt < 8; ++nt) {
        int col = h * 64 + nt * 8 + 2 * t;
        size_t i0 = (size_t)(b * S_ + qrow) * 1024 + col;
        *(unsigned*)&g_Xh[i0] = pack2h(o[nt][0] * inv0, o[nt][1] * inv0);
        size_t i1 = (size_t)(b * S_ + qrow + 8) * 1024 + col;
        *(unsigned*)&g_Xh[i1] = pack2h(o[nt][2] * inv1, o[nt][3] * inv1);
    }
}

// ---------------------------------------------------------------------------
extern "C" void kernel_launch(void* const* d_in, const int* in_sizes, int n_in,
                              void* d_out, int out_size)
{
    const float* in_q = (const float*)d_in[0];
    const float* in_k = (const float*)d_in[1];
    const float* in_v = (const float*)d_in[2];
    const float* Wq   = (const float*)d_in[3];
    const float* bq   = (const float*)d_in[4];
    const float* Wk   = (const float*)d_in[5];
    const float* bk   = (const float*)d_in[6];
    const float* Wv   = (const float*)d_in[7];
    const float* bv   = (const float*)d_in[8];
    const float* Wo   = (const float*)d_in[9];
    const float* bo   = (const float*)d_in[10];
    float* out = (float*)d_out;

    __nv_bfloat16 *qh, *ql, *kh, *vh;
    cudaGetSymbolAddress((void**)&qh, g_Qh);
    cudaGetSymbolAddress((void**)&ql, g_Ql);
    cudaGetSymbolAddress((void**)&kh, g_Kh);
    cudaGetSymbolAddress((void**)&vh, g_Vh);

    cudaFuncSetAttribute(gemm_bf<0>, cudaFuncAttributeMaxDynamicSharedMemorySize, GSMTOT);
    cudaFuncSetAttribute(gemm_bf<1>, cudaFuncAttributeMaxDynamicSharedMemorySize, GSMTOT);
    cudaFuncSetAttribute(gemm_hf<0>, cudaFuncAttributeMaxDynamicSharedMemorySize, HSMTOT);
    cudaFuncSetAttribute(gemm_hf<1>, cudaFuncAttributeMaxDynamicSharedMemorySize, HSMTOT);
    cudaFuncSetAttribute(attn_bf,    cudaFuncAttributeMaxDynamicSharedMemorySize, ASMT);

    dim3 tb(256);
    dim3 gg(8, 64);                       // 128x128 tiles over [8192 x 1024]
    dim3 gwP(16, 1, 16);                  // proj weights [16][1024][64]
    dim3 gwO(16, 16, 1);                  // Wo [1024][1024]
    const int SX = (M_ * D_ / 4) / 256;

    // Q projection (bf16x3, epilogue -> fp16 hi/lo)
    split_w<<<gwP, tb>>>(Wq, 64);
    split_x<<<SX, tb>>>(in_q);
    gemm_bf<0><<<gg, tb, GSMTOT>>>(bq, qh, ql);

    // K projection (bf16x3, epilogue -> fp16 single)
    split_w<<<gwP, tb>>>(Wk, 64);
    split_x<<<SX, tb>>>(in_k);
    gemm_bf<1><<<gg, tb, GSMTOT>>>(bk, kh, nullptr);

    // V projection (fp16 1-term)
    split_wh<<<gwP, tb>>>(Wv, 64);
    split_xh<<<SX, tb>>>(in_v);
    gemm_hf<0><<<gg, tb, HSMTOT>>>(bv, nullptr, vh);

    // attention (S fp16 2-term, PV fp16 1-term)
    attn_bf<<<dim3(S_ / 128, B_ * H_), tb, ASMT>>>();

    // output projection (fp16 1-term)
    split_wh<<<gwO, tb>>>(Wo, 1024);
    gemm_hf<1><<<gg, tb, HSMTOT>>>(bo, out, nullptr);
}

// round 17
// speedup vs baseline: 3.8996x; 1.0634x over previous
#include <cuda_runtime.h>
#include <cuda_bf16.h>
#include <cuda_fp16.h>
#include <cstdint>

#define B_  4
#define S_  2048
#define D_  1024
#define H_  16
#define M_  (B_*S_)

// ---------------- scratch (static device memory only) ----------------------
__device__ __nv_bfloat16 g_Xh[(size_t)M_*D_]; // A operand hi (X_q / X_v / Z)
__device__ __nv_bfloat16 g_Xl[(size_t)M_*D_];
__device__ __nv_bfloat16 g_Yh[(size_t)M_*D_]; // A operand hi (X_k)
__device__ __nv_bfloat16 g_Yl[(size_t)M_*D_];
__device__ __nv_bfloat16 g_Wh[(size_t)D_*D_]; // B operand hi [n][k] (Wq / Wv / Wo)
__device__ __nv_bfloat16 g_Wl[(size_t)D_*D_];
__device__ __nv_bfloat16 g_W2h[(size_t)D_*D_]; // Wk
__device__ __nv_bfloat16 g_W2l[(size_t)D_*D_];
__device__ __nv_bfloat16 g_Qh[(size_t)M_*D_]; // [b,h,s,64] fp16 hi/lo
__device__ __nv_bfloat16 g_Ql[(size_t)M_*D_];
__device__ __nv_bfloat16 g_Kh[(size_t)M_*D_]; // fp16 single
__device__ __nv_bfloat16 g_Vh[(size_t)M_*D_]; // fp16 single

// ---------------- helpers ----------------------------------------------
__device__ __forceinline__ uint32_t smem_u32(const void* p) {
    uint32_t a;
    asm("{ .reg .u64 t; cvta.to.shared.u64 t, %1; cvt.u32.u64 %0, t; }" : "=r"(a) : "l"(p));
    return a;
}
__device__ __forceinline__ void cpa16(uint32_t dst, const void* src) {
    asm volatile("cp.async.cg.shared.global [%0], [%1], 16;" :: "r"(dst), "l"(src));
}
#define CP_COMMIT() asm volatile("cp.async.commit_group;" ::: "memory")
#define CP_WAIT(n)  asm volatile("cp.async.wait_group %0;" :: "n"(n) : "memory")

__device__ __forceinline__ void split2(float x0, float x1, unsigned& hi, unsigned& lo) {
    unsigned h;
    asm("cvt.rn.bf16x2.f32 %0, %1, %2;" : "=r"(h) : "f"(x1), "f"(x0));
    __nv_bfloat162 hb = *reinterpret_cast<__nv_bfloat162*>(&h);
    float h0 = __bfloat162float(hb.x);
    float h1 = __bfloat162float(hb.y);
    hi = h;
    asm("cvt.rn.bf16x2.f32 %0, %1, %2;" : "=r"(lo) : "f"(x1 - h1), "f"(x0 - h0));
}
__device__ __forceinline__ void split2h(float x0, float x1, unsigned& hi, unsigned& lo) {
    __half2 h = __floats2half2_rn(x0, x1);
    float h0 = __low2float(h), h1 = __high2float(h);
    hi = *reinterpret_cast<unsigned*>(&h);
    __half2 l = __floats2half2_rn(x0 - h0, x1 - h1);
    lo = *reinterpret_cast<unsigned*>(&l);
}
__device__ __forceinline__ unsigned pack2h(float x0, float x1) {
    __half2 h = __floats2half2_rn(x0, x1);
    return *reinterpret_cast<unsigned*>(&h);
}
__device__ __forceinline__ void mma16(float* c, const unsigned* a, const unsigned* b) {
    asm("mma.sync.aligned.m16n8k16.row.col.f32.bf16.bf16.f32 "
        "{%0,%1,%2,%3},{%4,%5,%6,%7},{%8,%9},{%0,%1,%2,%3};"
        : "+f"(c[0]), "+f"(c[1]), "+f"(c[2]), "+f"(c[3])
        : "r"(a[0]), "r"(a[1]), "r"(a[2]), "r"(a[3]), "r"(b[0]), "r"(b[1]));
}
__device__ __forceinline__ void mma16f(float* c, const unsigned* a, const unsigned* b) {
    asm("mma.sync.aligned.m16n8k16.row.col.f32.f16.f16.f32 "
        "{%0,%1,%2,%3},{%4,%5,%6,%7},{%8,%9},{%0,%1,%2,%3};"
        : "+f"(c[0]), "+f"(c[1]), "+f"(c[2]), "+f"(c[3])
        : "r"(a[0]), "r"(a[1]), "r"(a[2]), "r"(a[3]), "r"(b[0]), "r"(b[1]));
}
__device__ __forceinline__ void ldsm4(unsigned* r, uint32_t a) {
    asm volatile("ldmatrix.sync.aligned.m8n8.x4.shared.b16 {%0,%1,%2,%3}, [%4];"
        : "=r"(r[0]), "=r"(r[1]), "=r"(r[2]), "=r"(r[3]) : "r"(a));
}
__device__ __forceinline__ void ldsm4t(unsigned* r, uint32_t a) {
    asm volatile("ldmatrix.sync.aligned.m8n8.x4.trans.shared.b16 {%0,%1,%2,%3}, [%4];"
        : "=r"(r[0]), "=r"(r[1]), "=r"(r[2]), "=r"(r[3]) : "r"(a));
}

// ---------------------------------------------------------------------------
// split kernels
// ---------------------------------------------------------------------------
__global__ __launch_bounds__(256)
void split_x(const float* __restrict__ src,
             __nv_bfloat16* __restrict__ dh, __nv_bfloat16* __restrict__ dl) {
    size_t gid = (size_t)blockIdx.x * 256 + threadIdx.x;
    float4 v = *(const float4*)(src + gid * 4);
    unsigned h0, l0, h1, l1;
    split2(v.x, v.y, h0, l0);
    split2(v.z, v.w, h1, l1);
    *(uint2*)(dh + gid * 4) = make_uint2(h0, h1);
    *(uint2*)(dl + gid * 4) = make_uint2(l0, l1);
}
__global__ __launch_bounds__(256) void split_xh(const float* __restrict__ src) {
    size_t gid = (size_t)blockIdx.x * 256 + threadIdx.x;
    float4 v = *(const float4*)(src + gid * 4);
    *(uint2*)(g_Xh + gid * 4) = make_uint2(pack2h(v.x, v.y), pack2h(v.z, v.w));
}
__global__ __launch_bounds__(256)
void split_w(const float* __restrict__ W, int Cw,
             __nv_bfloat16* __restrict__ dh, __nv_bfloat16* __restrict__ dl) {
    __shared__ float s[64][65];
    const int tid = threadIdx.x;
    const int k0 = blockIdx.x * 64, c0 = blockIdx.y * 64, g = blockIdx.z;
    const float* src = W + ((size_t)g * 1024 + k0) * Cw + c0;
    {
        int lc = tid & 63, kb = tid >> 6;
#pragma unroll
        for (int i = 0; i < 16; ++i) {
            int lk = kb + 4 * i;
            s[lk][lc] = src[(size_t)lk * Cw + lc];
        }
    }
    __syncthreads();
    {
        int k2 = (tid & 31) * 2, cb = tid >> 5;
#pragma unroll
        for (int i = 0; i < 8; ++i) {
            int lc = cb + 8 * i;
            unsigned hi, lo;
            split2(s[k2][lc], s[k2 + 1][lc], hi, lo);
            size_t idx = (size_t)(g * Cw + c0 + lc) * 1024 + k0 + k2;
            *(unsigned*)&dh[idx] = hi;
            *(unsigned*)&dl[idx] = lo;
        }
    }
}
__global__ __launch_bounds__(256) void split_wh(const float* __restrict__ W, int Cw) {
    __shared__ float s[64][65];
    const int tid = threadIdx.x;
    const int k0 = blockIdx.x * 64, c0 = blockIdx.y * 64, g = blockIdx.z;
    const float* src = W + ((size_t)g * 1024 + k0) * Cw + c0;
    {
        int lc = tid & 63, kb = tid >> 6;
#pragma unroll
        for (int i = 0; i < 16; ++i) {
            int lk = kb + 4 * i;
            s[lk][lc] = src[(size_t)lk * Cw + lc];
        }
    }
    __syncthreads();
    {
        int k2 = (tid & 31) * 2, cb = tid >> 5;
#pragma unroll
        for (int i = 0; i < 8; ++i) {
            int lc = cb + 8 * i;
            size_t idx = (size_t)(g * Cw + c0 + lc) * 1024 + k0 + k2;
            *(unsigned*)&g_Wh[idx] = pack2h(s[k2][lc], s[k2 + 1][lc]);
        }
    }
}

// ---------------------------------------------------------------------------
// bf16x3 GEMM, Q+K projections merged (blockIdx.z: 0=Q, 1=K).
// 128x128 tile, BK=32, 3-stage, 512 threads (16 warps, warp tile 64x16).
// ---------------------------------------------------------------------------
#define GARR   10240
#define GSTAGE 40960
#define GSMTOT (3*GSTAGE)

__global__ __launch_bounds__(512)
void gemm_qk(const float* __restrict__ bq, const float* __restrict__ bk)
{
    extern __shared__ char smem[];
    const uint32_t sb = smem_u32(smem);
    const int tid = threadIdx.x, lane = tid & 31, warp = tid >> 5;
    const int wm = warp >> 3, wn = warp & 7;
    const int row0 = blockIdx.y * 128, col0 = blockIdx.x * 128;
    const int z = blockIdx.z;
    const int g = lane >> 2, t = lane & 3;
    const int r = tid >> 2, c16 = (tid & 3) * 16, c8 = (tid & 3) * 8;

    const __nv_bfloat16* Ah = z ? g_Yh  : g_Xh;
    const __nv_bfloat16* Al = z ? g_Yl  : g_Xl;
    const __nv_bfloat16* Bh = z ? g_W2h : g_Wh;
    const __nv_bfloat16* Bl = z ? g_W2l : g_Wl;
    const float* bias = z ? bk : bq;

    float c[4][2][4];
#pragma unroll
    for (int i = 0; i < 4; ++i)
#pragma unroll
        for (int j = 0; j < 2; ++j)
#pragma unroll
            for (int q = 0; q < 4; ++q) c[i][j][q] = 0.f;

    auto issueStage = [&](int it) {
        uint32_t base = sb + (it % 3) * GSTAGE + r * 80 + c16;
        size_t ao = (size_t)(row0 + r) * 1024 + it * 32 + c8;
        size_t bo = (size_t)(col0 + r) * 1024 + it * 32 + c8;
        cpa16(base,            Ah + ao);
        cpa16(base + GARR,     Al + ao);
        cpa16(base + 2 * GARR, Bh + bo);
        cpa16(base + 3 * GARR, Bl + bo);
        CP_COMMIT();
    };

    const int a_roff = (lane & 7) + ((lane >> 3) & 1) * 8;
    const int a_koff = (lane >> 4) * 8;
    const int b_roff = (lane & 7) + (lane >> 4) * 8;
    const int b_koff = ((lane >> 3) & 1) * 8;

    auto mmaStage = [&](int st) {
        uint32_t s0 = sb + st * GSTAGE;
#pragma unroll
        for (int ks = 0; ks < 2; ++ks) {
            unsigned ah[4][4], al[4][4], bh[4], bl[4];
#pragma unroll
            for (int mt = 0; mt < 4; ++mt) {
                uint32_t ad = s0 + (wm * 64 + mt * 16 + a_roff) * 80 + (ks * 16 + a_koff) * 2;
                ldsm4(ah[mt], ad);
                ldsm4(al[mt], ad + GARR);
            }
            uint32_t bd = s0 + 2 * GARR + (wn * 16 + b_roff) * 80 + (ks * 16 + b_koff) * 2;
            ldsm4(bh, bd);
            ldsm4(bl, bd + GARR);
            // term-major (per-accumulator order: hh, hl, lh — same as R13)
#pragma unroll
            for (int mt = 0; mt < 4; ++mt)
#pragma unroll
                for (int nt = 0; nt < 2; ++nt)
                    mma16(c[mt][nt], ah[mt], &bh[nt * 2]);
#pragma unroll
            for (int mt = 0; mt < 4; ++mt)
#pragma unroll
                for (int nt = 0; nt < 2; ++nt)
                    mma16(c[mt][nt], ah[mt], &bl[nt * 2]);
#pragma unroll
            for (int mt = 0; mt < 4; ++mt)
#pragma unroll
                for (int nt = 0; nt < 2; ++nt)
                    mma16(c[mt][nt], al[mt], &bh[nt * 2]);
        }
    };

    issueStage(0);
    issueStage(1);
    for (int it = 0; it < 32; ++it) {
        if (it < 31) { CP_WAIT(1); } else { CP_WAIT(0); }
        __syncthreads();
        if (it + 2 < 32) issueStage(it + 2);
        mmaStage(it % 3);
    }

#pragma unroll
    for (int mt = 0; mt < 4; ++mt)
#pragma unroll
        for (int nt = 0; nt < 2; ++nt) {
            int col = col0 + wn * 16 + nt * 8 + 2 * t;
            float b0 = bias[col], b1 = bias[col + 1];
#pragma unroll
            for (int h2 = 0; h2 < 2; ++h2) {
                int rr = row0 + wm * 64 + mt * 16 + g + h2 * 8;
                float v0 = c[mt][nt][h2 * 2 + 0] + b0;
                float v1 = c[mt][nt][h2 * 2 + 1] + b1;
                int b = rr >> 11, s = rr & 2047, hh = col >> 6;
                size_t idx = (((size_t)(b * H_ + hh) * S_) + s) * 64 + (col & 63);
                if (z == 0) {
                    unsigned hi, lo;
                    split2h(v0, v1, hi, lo);
                    *(unsigned*)&g_Qh[idx] = hi;
                    *(unsigned*)&g_Ql[idx] = lo;
                } else {
                    *(unsigned*)&g_Kh[idx] = pack2h(v0, v1);
                }
            }
        }
}

// ---------------------------------------------------------------------------
// fp16 1-term GEMM (V-proj, out-proj). 512 threads, warp tile 64x16.
// ---------------------------------------------------------------------------
#define HSTAGE (2*GARR)
#define HSMTOT (3*HSTAGE)

template<int MODE>
__global__ __launch_bounds__(512)
void gemm_hf(const float* __restrict__ bias, float* __restrict__ outf,
             __nv_bfloat16* __restrict__ outh)
{
    extern __shared__ char smem[];
    const uint32_t sb = smem_u32(smem);
    const int tid = threadIdx.x, lane = tid & 31, warp = tid >> 5;
    const int wm = warp >> 3, wn = warp & 7;
    const int row0 = blockIdx.y * 128, col0 = blockIdx.x * 128;
    const int g = lane >> 2, t = lane & 3;
    const int r = tid >> 2, c16 = (tid & 3) * 16, c8 = (tid & 3) * 8;

    float c[4][2][4];
#pragma unroll
    for (int i = 0; i < 4; ++i)
#pragma unroll
        for (int j = 0; j < 2; ++j)
#pragma unroll
            for (int q = 0; q < 4; ++q) c[i][j][q] = 0.f;

    auto issueStage = [&](int it) {
        uint32_t base = sb + (it % 3) * HSTAGE + r * 80 + c16;
        size_t ao = (size_t)(row0 + r) * 1024 + it * 32 + c8;
        size_t bo = (size_t)(col0 + r) * 1024 + it * 32 + c8;
        cpa16(base,        g_Xh + ao);
        cpa16(base + GARR, g_Wh + bo);
        CP_COMMIT();
    };

    const int a_roff = (lane & 7) + ((lane >> 3) & 1) * 8;
    const int a_koff = (lane >> 4) * 8;
    const int b_roff = (lane & 7) + (lane >> 4) * 8;
    const int b_koff = ((lane >> 3) & 1) * 8;

    auto mmaStage = [&](int st) {
        uint32_t s0 = sb + st * HSTAGE;
#pragma unroll
        for (int ks = 0; ks < 2; ++ks) {
            unsigned ah[4][4], bh[4];
#pragma unroll
            for (int mt = 0; mt < 4; ++mt) {
                uint32_t ad = s0 + (wm * 64 + mt * 16 + a_roff) * 80 + (ks * 16 + a_koff) * 2;
                ldsm4(ah[mt], ad);
            }
            uint32_t bd = s0 + GARR + (wn * 16 + b_roff) * 80 + (ks * 16 + b_koff) * 2;
            ldsm4(bh, bd);
#pragma unroll
            for (int mt = 0; mt < 4; ++mt)
#pragma unroll
                for (int nt = 0; nt < 2; ++nt)
                    mma16f(c[mt][nt], ah[mt], &bh[nt * 2]);
        }
    };

    issueStage(0);
    issueStage(1);
    for (int it = 0; it < 32; ++it) {
        if (it < 31) { CP_WAIT(1); } else { CP_WAIT(0); }
        __syncthreads();
        if (it + 2 < 32) issueStage(it + 2);
        mmaStage(it % 3);
    }

#pragma unroll
    for (int mt = 0; mt < 4; ++mt)
#pragma unroll
        for (int nt = 0; nt < 2; ++nt) {
            int col = col0 + wn * 16 + nt * 8 + 2 * t;
            float b0 = bias[col], b1 = bias[col + 1];
#pragma unroll
            for (int h2 = 0; h2 < 2; ++h2) {
                int rr = row0 + wm * 64 + mt * 16 + g + h2 * 8;
                float v0 = c[mt][nt][h2 * 2 + 0] + b0;
                float v1 = c[mt][nt][h2 * 2 + 1] + b1;
                if (MODE == 0) {
                    int b = rr >> 11, s = rr & 2047, hh = col >> 6;
                    size_t idx = (((size_t)(b * H_ + hh) * S_) + s) * 64 + (col & 63);
                    *(unsigned*)&outh[idx] = pack2h(v0, v1);
                } else {
                    *(float2*)(outf + (size_t)rr * 1024 + col) = make_float2(v0, v1);
                }
            }
        }
}

// ---------------------------------------------------------------------------
// Flash attention: 512 threads, Q-tile 256 (16 warps x 16 rows), KV-tile 64.
// S = QK^T fp16 2-term, PV fp16 1-term. 2-stage cp.async {Kh,Vh}.
// Per-accumulator MMA order identical to R13.
// ---------------------------------------------------------------------------
#define AARR  9216
#define ASTG  (2*AARR)
#define ASMT  (2*ASTG)

__global__ __launch_bounds__(512)
void attn_bf()
{
    extern __shared__ char smem[];
    const uint32_t sb = smem_u32(smem);

    const int tid  = threadIdx.x;
    const int lane = tid & 31, warp = tid >> 5;
    const int g    = lane >> 2, t = lane & 3;
    const int bh   = blockIdx.y, b = bh >> 4, h = bh & 15;
    const int q0   = blockIdx.x * 256;

    const size_t bhOff = (size_t)bh * S_ * 64;
    const __nv_bfloat16* Qph = g_Qh + bhOff + (size_t)q0 * 64;
    const __nv_bfloat16* Qpl = g_Ql + bhOff + (size_t)q0 * 64;

    unsigned qfh[4][4], qfl[4][4];
#pragma unroll
    for (int ks = 0; ks < 4; ++ks)
#pragma unroll
        for (int r2 = 0; r2 < 4; ++r2) {
            int row = warp * 16 + (r2 & 1) * 8 + g;
            int d   = ks * 16 + (t + (r2 >> 1) * 4) * 2;
            qfh[ks][r2] = *(const unsigned*)(Qph + (size_t)row * 64 + d);
            qfl[ks][r2] = *(const unsigned*)(Qpl + (size_t)row * 64 + d);
        }

    float o[8][4];
#pragma unroll
    for (int nt = 0; nt < 8; ++nt)
#pragma unroll
        for (int q = 0; q < 4; ++q) o[nt][q] = 0.f;
    float mrow[2] = {-1e30f, -1e30f};
    float lrow[2] = {0.f, 0.f};

    const int krow = tid >> 3, kch = tid & 7;
    const int b_roff = (lane & 7) + (lane >> 4) * 8;
    const int b_koff = ((lane >> 3) & 1) * 8;
    const int v_roff = (lane & 7) + ((lane >> 3) & 1) * 8;
    const int v_coff = (lane >> 4) * 8;

    auto issueKV = [&](int tkv) {
        uint32_t base = sb + (tkv & 1) * ASTG + krow * 144 + kch * 16;
        size_t src = bhOff + (size_t)(tkv * 64 + krow) * 64 + kch * 8;
        cpa16(base,        g_Kh + src);
        cpa16(base + AARR, g_Vh + src);
        CP_COMMIT();
    };

    issueKV(0);
    for (int tkv = 0; tkv < S_ / 64; ++tkv) {
        if (tkv + 1 < S_ / 64) {
            issueKV(tkv + 1);
            CP_WAIT(1);
        } else {
            CP_WAIT(0);
        }
        __syncthreads();

        uint32_t s0 = sb + (tkv & 1) * ASTG;

        // ---- S = Q K^T, fp16 2-term (per-jp loads; per-acc order = R13) ----
        float s[8][4];
#pragma unroll
        for (int j = 0; j < 8; ++j)
#pragma unroll
            for (int q = 0; q < 4; ++q) s[j][q] = 0.f;
#pragma unroll
        for (int ks = 0; ks < 4; ++ks) {
#pragma unroll
            for (int jp = 0; jp < 4; ++jp) {
                unsigned kb[4];
                uint32_t off = s0 + ((jp * 16 + b_roff) * 72 + ks * 16 + b_koff) * 2;
                ldsm4(kb, off);
                mma16f(s[2 * jp],     qfh[ks], &kb[0]);
                mma16f(s[2 * jp + 1], qfh[ks], &kb[2]);
                mma16f(s[2 * jp],     qfl[ks], &kb[0]);
                mma16f(s[2 * jp + 1], qfl[ks], &kb[2]);
            }
        }

        // ---- online softmax (rows g, g+8) ----
#pragma unroll
        for (int h2 = 0; h2 < 2; ++h2) {
            float mx = -1e30f;
#pragma unroll
            for (int j = 0; j < 8; ++j)
                mx = fmaxf(mx, fmaxf(s[j][h2 * 2], s[j][h2 * 2 + 1]));
            mx = fmaxf(mx, __shfl_xor_sync(0xffffffffu, mx, 1));
            mx = fmaxf(mx, __shfl_xor_sync(0xffffffffu, mx, 2));
            float mn   = fmaxf(mrow[h2], mx);
            float corr = __expf(mrow[h2] - mn);
            mrow[h2] = mn;
            float rs = 0.f;
#pragma unroll
            for (int j = 0; j < 8; ++j) {
                float p0 = __expf(s[j][h2 * 2] - mn);
                float p1 = __expf(s[j][h2 * 2 + 1] - mn);
                s[j][h2 * 2] = p0; s[j][h2 * 2 + 1] = p1;
                rs += p0 + p1;
            }
            rs += __shfl_xor_sync(0xffffffffu, rs, 1);
            rs += __shfl_xor_sync(0xffffffffu, rs, 2);
            lrow[h2] = lrow[h2] * corr + rs;
            if (corr != 1.f) {
#pragma unroll
                for (int nt = 0; nt < 8; ++nt) {
                    o[nt][h2 * 2]     *= corr;
                    o[nt][h2 * 2 + 1] *= corr;
                }
            }
        }

        // ---- P: C-frag -> A-frag, single fp16 ----
        unsigned pf[4][4];
#pragma unroll
        for (int j = 0; j < 8; ++j) {
            int ks = j >> 1, i0 = (j & 1) * 2;
            pf[ks][i0]     = pack2h(s[j][0], s[j][1]);
            pf[ks][i0 + 1] = pack2h(s[j][2], s[j][3]);
        }

        // ---- O += P V, fp16 1-term (per-np loads; per-acc order = R13) ----
#pragma unroll
        for (int ks = 0; ks < 4; ++ks) {
#pragma unroll
            for (int np = 0; np < 4; ++np) {
                unsigned vb[4];
                uint32_t off = s0 + AARR + ((ks * 16 + v_roff) * 72 + np * 16 + v_coff) * 2;
                ldsm4t(vb, off);
                mma16f(o[2 * np],     pf[ks], &vb[0]);
                mma16f(o[2 * np + 1], pf[ks], &vb[2]);
            }
        }
        __syncthreads();
    }

    // ---- normalize + write Z single fp16 into g_Xh [b*S+s][h*64+dv] ----
    float inv0 = 1.f / lrow[0], inv1 = 1.f / lrow[1];
    int qrow = q0 + warp * 16 + g;
#pragma unroll
    for (int nt = 0; nt < 8; ++nt) {
        int col = h * 64 + nt * 8 + 2 * t;
        size_t i0 = (size_t)(b * S_ + qrow) * 1024 + col;
        *(unsigned*)&g_Xh[i0] = pack2h(o[nt][0] * inv0, o[nt][1] * inv0);
        size_t i1 = (size_t)(b * S_ + qrow + 8) * 1024 + col;
        *(unsigned*)&g_Xh[i1] = pack2h(o[nt][2] * inv1, o[nt][3] * inv1);
    }
}

// ---------------------------------------------------------------------------
extern "C" void kernel_launch(void* const* d_in, const int* in_sizes, int n_in,
                              void* d_out, int out_size)
{
    const float* in_q = (const float*)d_in[0];
    const float* in_k = (const float*)d_in[1];
    const float* in_v = (const float*)d_in[2];
    const float* Wq   = (const float*)d_in[3];
    const float* bq   = (const float*)d_in[4];
    const float* Wk   = (const float*)d_in[5];
    const float* bk   = (const float*)d_in[6];
    const float* Wv   = (const float*)d_in[7];
    const float* bv   = (const float*)d_in[8];
    const float* Wo   = (const float*)d_in[9];
    const float* bo   = (const float*)d_in[10];
    float* out = (float*)d_out;

    __nv_bfloat16 *xh, *xl, *yh, *yl, *wh, *wl, *w2h, *w2l, *vh;
    cudaGetSymbolAddress((void**)&xh,  g_Xh);
    cudaGetSymbolAddress((void**)&xl,  g_Xl);
    cudaGetSymbolAddress((void**)&yh,  g_Yh);
    cudaGetSymbolAddress((void**)&yl,  g_Yl);
    cudaGetSymbolAddress((void**)&wh,  g_Wh);
    cudaGetSymbolAddress((void**)&wl,  g_Wl);
    cudaGetSymbolAddress((void**)&w2h, g_W2h);
    cudaGetSymbolAddress((void**)&w2l, g_W2l);
    cudaGetSymbolAddress((void**)&vh,  g_Vh);

    cudaFuncSetAttribute(gemm_qk,    cudaFuncAttributeMaxDynamicSharedMemorySize, GSMTOT);
    cudaFuncSetAttribute(gemm_hf<0>, cudaFuncAttributeMaxDynamicSharedMemorySize, HSMTOT);
    cudaFuncSetAttribute(gemm_hf<1>, cudaFuncAttributeMaxDynamicSharedMemorySize, HSMTOT);
    cudaFuncSetAttribute(attn_bf,    cudaFuncAttributeMaxDynamicSharedMemorySize, ASMT);

    dim3 tb256(256), tb512(512);
    dim3 ggqk(8, 64, 2);                  // merged Q+K projections
    dim3 gg(8, 64);
    dim3 gwP(16, 1, 16);                  // proj weights [16][1024][64]
    dim3 gwO(16, 16, 1);                  // Wo [1024][1024]
    const int SX = (M_ * D_ / 4) / 256;

    // splits for Q and K projections
    split_w<<<gwP, tb256>>>(Wq, 64, wh, wl);
    split_w<<<gwP, tb256>>>(Wk, 64, w2h, w2l);
    split_x<<<SX, tb256>>>(in_q, xh, xl);
    split_x<<<SX, tb256>>>(in_k, yh, yl);

    // Q+K projections (bf16x3), one launch
    gemm_qk<<<ggqk, tb512, GSMTOT>>>(bq, bk);

    // V projection (fp16 1-term)
    split_wh<<<gwP, tb256>>>(Wv, 64);
    split_xh<<<SX, tb256>>>(in_v);
    gemm_hf<0><<<gg, tb512, HSMTOT>>>(bv, nullptr, vh);

    // attention (S fp16 2-term, PV fp16 1-term)
    attn_bf<<<dim3(S_ / 256, B_ * H_), tb512, ASMT>>>();

    // output projection (fp16 1-term)
    split_wh<<<gwO, tb256>>>(Wo, 1024);
    gemm_hf<1><<<gg, tb512, HSMTOT>>>(bo, out, nullptr);
}